// round 7
// baseline (speedup 1.0000x reference)
#include <cuda_runtime.h>
#include <cuda_bf16.h>
#include <math.h>
#include <stdint.h>

// ---------------------------------------------------------------------------
// ToyMoE: conv stack (5x conv3x3+relu+maxpool2) -> top-2 gating (eval)
//         -> sparse top-2 expert MLPs -> softmax -> gated combine + aux loss
// conv2-5 & experts: bf16 mma.sync, 3-term split (Ahi*Whi + Alo*Whi + Ahi*Wlo).
// Conv: 256-thread CTAs, 128x64 tiles, K-chunk 64, 2-stage pipe, 2 CTAs/SM.
// ---------------------------------------------------------------------------

#define BATCH 256
#define DFEAT 2048
#define HID 4096
#define OUTD 1024
#define NEXP 16
#define NPAIR (BATCH * 2)

typedef unsigned short u16;

template <int X> struct LG { static constexpr int v = 1 + LG<X / 2>::v; };
template <> struct LG<1> { static constexpr int v = 0; };

// ------------------------- scratch (device globals) ------------------------
__device__ u16   g_hiA[(size_t)256 * 1024 * 128];  // hi acts (L1/L3 out)
__device__ u16   g_loA[(size_t)256 * 1024 * 128];  // lo acts
__device__ u16   g_hiB[(size_t)256 * 256 * 256];   // hi acts (L2/L4 out)
__device__ u16   g_loB[(size_t)256 * 256 * 256];
__device__ u16   g_whi[4423680];                   // conv weights hi
__device__ u16   g_wlo[4423680];                   // conv weights lo
__device__ float g_pool[BATCH * DFEAT];            // feats fp32 (gating)
__device__ u16   g_feathi[BATCH * DFEAT];
__device__ u16   g_featlo[BATCH * DFEAT];
__device__ u16   g_hhi[(size_t)NPAIR * HID];
__device__ u16   g_hlo[(size_t)NPAIR * HID];
__device__ float g_logits[BATCH * NEXP];
__device__ float g_gates[BATCH * NEXP];
__device__ int   g_pairE[NPAIR];
__device__ float g_pairG[NPAIR];
__device__ int   g_perm[NPAIR];
__device__ int   g_cnt[NEXP];
__device__ int   g_off[NEXP];
__device__ float g_o[(size_t)NPAIR * OUTD];

// ------------------------------ PTX helpers --------------------------------
__device__ __forceinline__ uint32_t smem_u32(const void* p) {
    uint32_t a;
    asm("{ .reg .u64 t; cvta.to.shared.u64 t, %1; cvt.u32.u64 %0, t; }"
        : "=r"(a) : "l"(p));
    return a;
}

#define SWZ128(x) ((x) ^ (((x) >> 3) & 0x70))
#define SWZ64(x)  ((x) ^ (((x) >> 3) & 0x30))

__device__ __forceinline__ void cp16(uint32_t dst, const void* src, int sz) {
    asm volatile("cp.async.cg.shared.global [%0], [%1], 16, %2;"
                 :: "r"(dst), "l"(src), "r"(sz) : "memory");
}
#define CP_COMMIT() asm volatile("cp.async.commit_group;" ::: "memory")
#define CP_WAIT(n)  asm volatile("cp.async.wait_group %0;" :: "n"(n) : "memory")

__device__ __forceinline__ void ldsm4(uint32_t& r0, uint32_t& r1,
                                      uint32_t& r2, uint32_t& r3, uint32_t a) {
    asm volatile("ldmatrix.sync.aligned.m8n8.x4.shared.b16 {%0,%1,%2,%3}, [%4];"
                 : "=r"(r0), "=r"(r1), "=r"(r2), "=r"(r3) : "r"(a));
}
__device__ __forceinline__ void mma16816(float* d, const uint32_t* a,
                                         const uint32_t* b) {
    asm volatile(
        "mma.sync.aligned.m16n8k16.row.col.f32.bf16.bf16.f32 "
        "{%0,%1,%2,%3}, {%4,%5,%6,%7}, {%8,%9}, {%0,%1,%2,%3};"
        : "+f"(d[0]), "+f"(d[1]), "+f"(d[2]), "+f"(d[3])
        : "r"(a[0]), "r"(a[1]), "r"(a[2]), "r"(a[3]), "r"(b[0]), "r"(b[1]));
}
__device__ __forceinline__ void split2(float v, u16* hi, u16* lo) {
    __nv_bfloat16 h = __float2bfloat16_rn(v);
    __nv_bfloat16 l = __float2bfloat16_rn(v - __bfloat162float(h));
    *hi = __bfloat16_as_ushort(h);
    *lo = __bfloat16_as_ushort(l);
}

// --------------------- bf16 mma.sync conv3x3 (SAME, relu, fused pool) ------
// CTA tile 128x64, K-chunk 64 channels (one tap). Stage 48KB (SW128):
//   Ahi 16K @0, Alo 16K @16384, Whi 8K @32768, Wlo 8K @40960.
// 2-stage pipeline, 1 sync/chunk, 2 CTAs/SM.
#define STG 49152
#define CONV_DSM (2 * STG)

template <int CI, int H, int W, int CO, bool FEATS>
__global__ void __launch_bounds__(256, 2) conv_mma_kernel(
    const u16* __restrict__ inhi, const u16* __restrict__ inlo,
    const u16* __restrict__ whi, const u16* __restrict__ wlo,
    const float* __restrict__ bias,
    u16* __restrict__ outhi, u16* __restrict__ outlo, float* __restrict__ outf)
{
    constexpr int HW = H * W;
    constexpr int LHW = LG<HW>::v;
    constexpr int LW = LG<W>::v;
    constexpr int CPT = CI / 64;
    constexpr int NCH = 9 * CPT;
    constexpr int WROW = 9 * CI;

    extern __shared__ __align__(1024) char dsm[];
    const uint32_t sb = smem_u32(dsm);
    const int t = threadIdx.x;
    const int lane = t & 31;
    const int wid = t >> 5;
    const int wm = wid & 3, wn = wid >> 2;     // 4x2 warp grid, 32x32 tiles
    const int m0 = blockIdx.x * 128, n0 = blockIdx.y * 64;

    // A fill: row rA = t>>1 (0..127), half kh = t&1 (64B each)
    const int rA = t >> 1, kh = t & 1;
    const int mA = m0 + rA;
    const int bI = mA >> LHW;
    const int posA = mA & (HW - 1);
    const int yy = posA >> LW, xx = posA & (W - 1);
    // W fill: row nW = t>>2 (0..63), quarter q = t&3 (32B each)
    const int nW = t >> 2, q = t & 3;
    const size_t wro = (size_t)(n0 + nW) * WROW;

    auto fill = [&](int st, int c) {
        const uint32_t stg = sb + (uint32_t)st * STG;
        const int tap = c / CPT;
        const int cib = (c % CPT) * 64;
        const int dy = tap / 3 - 1, dx = tap % 3 - 1;
        const int iy = yy + dy, ix = xx + dx;
        const bool ok = (iy >= 0 && iy < H && ix >= 0 && ix < W);
        const size_t ai =
            (((size_t)bI * H + (ok ? iy : 0)) * W + (ok ? ix : 0)) * CI + cib + kh * 32;
#pragma unroll
        for (int j = 0; j < 4; j++) {
            const uint32_t d = SWZ128((uint32_t)(rA * 128 + kh * 64 + j * 16));
            cp16(stg + d, inhi + ai + j * 8, ok ? 16 : 0);
            cp16(stg + 16384 + d, inlo + ai + j * 8, ok ? 16 : 0);
        }
        const size_t wi = wro + tap * CI + cib + q * 16;
#pragma unroll
        for (int j = 0; j < 2; j++) {
            const uint32_t d = SWZ128((uint32_t)(nW * 128 + q * 32 + j * 16));
            cp16(stg + 32768 + d, whi + wi + j * 8, 16);
            cp16(stg + 40960 + d, wlo + wi + j * 8, 16);
        }
    };

    float acc[2][4][4];
#pragma unroll
    for (int a = 0; a < 2; a++)
#pragma unroll
        for (int b = 0; b < 4; b++)
#pragma unroll
            for (int cj = 0; cj < 4; cj++) acc[a][b][cj] = 0.f;

    fill(0, 0);
    CP_COMMIT();

    int st = 0;
    for (int c = 0; c < NCH; c++) {
        CP_WAIT(0);          // stage c landed (fill c+1 not yet issued)
        __syncthreads();     // all warps done with mma(c-1) -> safe to refill
        if (c + 1 < NCH) {
            fill(st ^ 1, c + 1);
            CP_COMMIT();
        }
        const uint32_t stg = sb + (uint32_t)st * STG;
#pragma unroll
        for (int ks = 0; ks < 4; ks++) {
            const int c0 = ks * 32;
            uint32_t ah[2][4], al[2][4], bh[8], bl[8];
#pragma unroll
            for (int mt = 0; mt < 2; mt++) {
                const int row = wm * 32 + mt * 16 + (lane & 15);
                const uint32_t o =
                    SWZ128((uint32_t)(row * 128 + c0 + (lane >> 4) * 16));
                ldsm4(ah[mt][0], ah[mt][1], ah[mt][2], ah[mt][3], stg + o);
                ldsm4(al[mt][0], al[mt][1], al[mt][2], al[mt][3], stg + 16384 + o);
            }
#pragma unroll
            for (int p = 0; p < 2; p++) {
                const int row = wn * 32 + p * 16 + (lane & 7) + (lane >> 4) * 8;
                const uint32_t o =
                    SWZ128((uint32_t)(row * 128 + c0 + ((lane >> 3) & 1) * 16));
                ldsm4(bh[p * 4], bh[p * 4 + 1], bh[p * 4 + 2], bh[p * 4 + 3],
                      stg + 32768 + o);
                ldsm4(bl[p * 4], bl[p * 4 + 1], bl[p * 4 + 2], bl[p * 4 + 3],
                      stg + 40960 + o);
            }
#pragma unroll
            for (int mt = 0; mt < 2; mt++)
#pragma unroll
                for (int nt = 0; nt < 4; nt++) {
                    mma16816(acc[mt][nt], ah[mt], &bh[nt * 2]);
                    mma16816(acc[mt][nt], al[mt], &bh[nt * 2]);
                    mma16816(acc[mt][nt], ah[mt], &bl[nt * 2]);
                }
        }
        st ^= 1;
    }
    __syncthreads();

    // ---- epilogue: bias+relu -> SMEM [128][68] -> 2x2 pool -> hi/lo planes --
    float* S = (float*)dsm;
#pragma unroll
    for (int mt = 0; mt < 2; mt++)
#pragma unroll
        for (int half = 0; half < 2; half++) {
            const int rr = wm * 32 + mt * 16 + (lane >> 2) + half * 8;
#pragma unroll
            for (int nt = 0; nt < 4; nt++)
#pragma unroll
                for (int j = 0; j < 2; j++) {
                    const int ncl = wn * 32 + nt * 8 + (lane & 3) * 2 + j;
                    float v = acc[mt][nt][half * 2 + j] + bias[n0 + ncl];
                    S[rr * 68 + ncl] = v > 0.f ? v : 0.f;
                }
        }
    __syncthreads();

    constexpr int Wo = W / 2;
    constexpr int HWo = HW / 4;
    for (int idx = t; idx < 32 * 64; idx += 256) {
        const int pp = idx >> 6;     // 0..31 pooled positions in tile
        const int cl = idx & 63;
        const int lpy = pp / Wo;
        const int lpx = pp % Wo;
        const int lm = lpy * 2 * W + lpx * 2;
        const int mm = m0 + lm;
        const int b = mm >> LHW;
        const int rem = mm & (HW - 1);
        const int y = rem >> LW, x = rem & (W - 1);
        const float* p = S + lm * 68 + cl;
        float v = fmaxf(fmaxf(p[0], p[68]), fmaxf(p[W * 68], p[(W + 1) * 68]));
        const int posn = (y >> 1) * Wo + (x >> 1);
        u16 hb, lb;
        split2(v, &hb, &lb);
        if (FEATS) {
            const int d = (n0 + cl) * HWo + posn;
            outf[(size_t)b * DFEAT + d] = v;
            outhi[(size_t)b * DFEAT + d] = hb;
            outlo[(size_t)b * DFEAT + d] = lb;
        } else {
            const size_t oi = ((size_t)b * HWo + posn) * CO + (n0 + cl);
            outhi[oi] = hb;
            outlo[oi] = lb;
        }
    }
}

// ---- weight pack: OIHW -> [co][tap*CI+ci] hi u16 / lo u16 -----------------
__global__ void wpack_kernel(const float* __restrict__ w,
                             u16* __restrict__ ohi, u16* __restrict__ olo,
                             int CO, int CI)
{
    const int i = blockIdx.x * 256 + threadIdx.x;
    if (i >= CO * CI * 9) return;
    const int tap = i % 9;
    const int ci = (i / 9) % CI;
    const int co = i / (9 * CI);
    u16 hb, lb;
    split2(w[i], &hb, &lb);
    const size_t o = (size_t)co * CI * 9 + (size_t)tap * CI + ci;
    ohi[o] = hb;
    olo[o] = lb;
}

// -------------- grouped expert GEMM, bf16 mma (fc1 / fc2) ------------------
#define ESTG 36864
#define EXP_DSM (3 * ESTG + 128)

template <int KDIM, int NDIM, bool RELU, bool GATHER, bool PACKOUT>
__global__ void __launch_bounds__(256, 2) expert_mma_kernel(
    const u16* __restrict__ Ahi, const u16* __restrict__ Alo,
    const float* __restrict__ Wt, const float* __restrict__ bias,
    u16* __restrict__ ohp, u16* __restrict__ olp, float* __restrict__ of)
{
    constexpr int NCH = KDIM / 32;
    const int e = blockIdx.y;
    const int cnt = g_cnt[e];
    const int off = g_off[e];
    const int rbase = blockIdx.z * 32;
    if (rbase >= cnt) return;
    const int n0 = blockIdx.x * 128;

    extern __shared__ __align__(1024) char dsm[];
    const uint32_t sb = smem_u32(dsm);
    const int t = threadIdx.x;
    const int lane = t & 31;
    const int wn = t >> 5;

    int* srcRow = (int*)(dsm + 3 * ESTG);
    if (t < 32) {
        int rr = rbase + t, sr = -1;
        if (rr < cnt) sr = GATHER ? (g_perm[off + rr] >> 1) : (off + rr);
        srcRow[t] = sr;
    }
    __syncthreads();

    const float* wbase = Wt + (size_t)e * KDIM * NDIM + n0;

    auto fill = [&](int st, int c) {
        const uint32_t stg = sb + (uint32_t)st * ESTG;
        const int kb = c * 32;
        if (t < 128) {
            const int rr = t >> 2, sg = t & 3;
            const int sr = srcRow[rr];
            const size_t ai = (sr < 0) ? 0 : ((size_t)sr * KDIM + kb + sg * 8);
            const uint32_t d = SWZ64((uint32_t)(rr * 64 + sg * 16));
            cp16(stg + d, Ahi + ai, sr < 0 ? 0 : 16);
            cp16(stg + 2048 + d, Alo + ai, sr < 0 ? 0 : 16);
        }
#pragma unroll
        for (int i = 0; i < 4; i++) {
            const int task = t + i * 256;
            const int k = task >> 5, sgw = task & 31;
            cp16(stg + 4096 + (uint32_t)(k * 512 + sgw * 16),
                 wbase + (size_t)(kb + k) * NDIM + sgw * 4, 16);
        }
    };

    float acc[2][2][4];
#pragma unroll
    for (int a = 0; a < 2; a++)
#pragma unroll
        for (int b = 0; b < 2; b++)
#pragma unroll
            for (int cj = 0; cj < 4; cj++) acc[a][b][cj] = 0.f;

    fill(0, 0);
    CP_COMMIT();
    fill(1, 1);
    CP_COMMIT();

    int st = 0;
    for (int c = 0; c < NCH; c++) {
        if (c + 1 < NCH) { CP_WAIT(1); } else { CP_WAIT(0); }
        __syncthreads();
        if (c + 2 < NCH) {
            fill(st >= 1 ? st - 1 : st + 2, c + 2);
            CP_COMMIT();
        }
        char* stgc = dsm + (size_t)st * ESTG;
        // ---- convert W fp32 tile -> Whi / Wlo (SW64, n-major) ----
        {
            const int k = t >> 3, ng = t & 7;
#pragma unroll
            for (int j = 0; j < 4; j++) {
                const float4 w =
                    *(const float4*)(stgc + 4096 + k * 512 + ng * 64 + j * 16);
                const float vv[4] = {w.x, w.y, w.z, w.w};
#pragma unroll
                for (int jj = 0; jj < 4; jj++) {
                    const int n = ng * 16 + j * 4 + jj;
                    u16 hb, lb;
                    split2(vv[jj], &hb, &lb);
                    const uint32_t o = SWZ64((uint32_t)(n * 64 + 2 * k));
                    *(u16*)(stgc + 20480 + o) = hb;
                    *(u16*)(stgc + 28672 + o) = lb;
                }
            }
        }
        __syncthreads();

        const uint32_t stg = sb + (uint32_t)st * ESTG;
#pragma unroll
        for (int ks = 0; ks < 2; ks++) {
            const int c0 = ks * 32;
            uint32_t ah[2][4], al[2][4], bh[4], bl[4];
#pragma unroll
            for (int mt = 0; mt < 2; mt++) {
                const int row = mt * 16 + (lane & 15);
                const uint32_t o = SWZ64((uint32_t)(row * 64 + c0 + (lane >> 4) * 16));
                ldsm4(ah[mt][0], ah[mt][1], ah[mt][2], ah[mt][3], stg + o);
                ldsm4(al[mt][0], al[mt][1], al[mt][2], al[mt][3], stg + 2048 + o);
            }
            {
                const int row = wn * 16 + (lane & 7) + (lane >> 4) * 8;
                const uint32_t o =
                    SWZ64((uint32_t)(row * 64 + c0 + ((lane >> 3) & 1) * 16));
                ldsm4(bh[0], bh[1], bh[2], bh[3], stg + 20480 + o);
                ldsm4(bl[0], bl[1], bl[2], bl[3], stg + 28672 + o);
            }
#pragma unroll
            for (int mt = 0; mt < 2; mt++)
#pragma unroll
                for (int nt = 0; nt < 2; nt++) {
                    mma16816(acc[mt][nt], ah[mt], &bh[nt * 2]);
                    mma16816(acc[mt][nt], al[mt], &bh[nt * 2]);
                    mma16816(acc[mt][nt], ah[mt], &bl[nt * 2]);
                }
        }
        st = (st + 1 == 3) ? 0 : st + 1;
    }

    // ---- epilogue ----
#pragma unroll
    for (int mt = 0; mt < 2; mt++)
#pragma unroll
        for (int half = 0; half < 2; half++) {
            const int rr = rbase + mt * 16 + (lane >> 2) + half * 8;
            if (rr >= cnt) continue;
            const int gr = off + rr;
#pragma unroll
            for (int nt = 0; nt < 2; nt++)
#pragma unroll
                for (int j = 0; j < 2; j++) {
                    const int n = n0 + wn * 16 + nt * 8 + (lane & 3) * 2 + j;
                    float v = acc[mt][nt][half * 2 + j] + bias[(size_t)e * NDIM + n];
                    if (RELU) v = v > 0.f ? v : 0.f;
                    if (PACKOUT) {
                        u16 hb, lb;
                        split2(v, &hb, &lb);
                        ohp[(size_t)gr * NDIM + n] = hb;
                        olp[(size_t)gr * NDIM + n] = lb;
                    } else {
                        of[(size_t)gr * NDIM + n] = v;
                    }
                }
        }
}

// ---------- conv1: fp32 SIMT (CI=3) with fused pool+split epilogue ---------
#define CONV1_DSM 68608

__global__ __launch_bounds__(256, 1) void conv1_kernel(
    const float* __restrict__ in, const float* __restrict__ wt,
    const float* __restrict__ bias, u16* __restrict__ outhi,
    u16* __restrict__ outlo)
{
    constexpr int CI = 3, H = 64, W = 64;
    constexpr int BK = 27;
    constexpr int HW = H * W;

    extern __shared__ __align__(1024) char dsm[];
    float (*As)[132] = (float(*)[132])dsm;
    float (*Bs)[132] = (float(*)[132])(dsm + 14784);

    const int t = threadIdx.x;
    const int m0 = blockIdx.x * 128;
    const int tx = t & 15;
    const int ty = t >> 4;

    float acc[8][8];
#pragma unroll
    for (int i = 0; i < 8; i++)
#pragma unroll
        for (int j = 0; j < 8; j++) acc[i][j] = 0.f;

#pragma unroll
    for (int j = 0; j < 14; j++) {
        int e = j * 256 + t;
        if (e >= 27 * 128) break;
        int k = e >> 7;
        int p = e & 127;
        int ci = k / 9;
        int rc = k % 9;
        int s = m0 + p;
        int b = s / HW;
        int rr = s % HW;
        int y = rr / W, x = rr % W;
        int iy = y + rc / 3 - 1;
        int ix = x + rc % 3 - 1;
        float v = 0.f;
        if (iy >= 0 && iy < H && ix >= 0 && ix < W)
            v = in[((size_t)(b * CI + ci) * H + iy) * W + ix];
        As[k][p] = v;
    }
    if (t < 128) {
        const float* wp = wt + (size_t)t * 27;
#pragma unroll
        for (int k = 0; k < 27; k++) Bs[k][t] = wp[k];
    }
    __syncthreads();

#pragma unroll
    for (int kk = 0; kk < BK; kk++) {
        float a[8], bv[8];
        *(float4*)&a[0] = *(const float4*)&As[kk][tx * 8];
        *(float4*)&a[4] = *(const float4*)&As[kk][tx * 8 + 4];
        *(float4*)&bv[0] = *(const float4*)&Bs[kk][ty * 8];
        *(float4*)&bv[4] = *(const float4*)&Bs[kk][ty * 8 + 4];
#pragma unroll
        for (int i = 0; i < 8; i++)
#pragma unroll
            for (int j = 0; j < 8; j++) acc[i][j] += a[i] * bv[j];
    }
    __syncthreads();

    float* S = (float*)dsm;
#pragma unroll
    for (int i = 0; i < 8; i++) {
        const int r = tx * 8 + i;
#pragma unroll
        for (int j = 0; j < 8; j++) {
            const int cl = ty * 8 + j;
            float v = acc[i][j] + bias[cl];
            S[r * 132 + cl] = v > 0.f ? v : 0.f;
        }
    }
    __syncthreads();

    for (int idx = t; idx < 32 * 128; idx += 256) {
        const int pp = idx >> 7;
        const int cl = idx & 127;
        const int lm = pp * 2;
        const int m = m0 + lm;
        const int b = m >> 12;
        const int rem = m & 4095;
        const int y = rem >> 6, x = rem & 63;
        const float* p = S + lm * 132 + cl;
        float v = fmaxf(fmaxf(p[0], p[132]), fmaxf(p[64 * 132], p[65 * 132]));
        u16 hb, lb;
        split2(v, &hb, &lb);
        const size_t oi = ((size_t)b * 1024 + (y >> 1) * 32 + (x >> 1)) * 128 + cl;
        outhi[oi] = hb;
        outlo[oi] = lb;
    }
}

// ----------------------------- gate logits ---------------------------------
__global__ void gate_logits_kernel(const float* __restrict__ feats,
                                   const float* __restrict__ wg)
{
    int t = blockIdx.x * blockDim.x + threadIdx.x;
    if (t >= BATCH * NEXP) return;
    int b = t >> 4, e = t & 15;
    const float* f = feats + (size_t)b * DFEAT;
    float s = 0.f;
    for (int d = 0; d < DFEAT; d++) s += f[d] * wg[d * NEXP + e];
    g_logits[t] = s;
}

// ------------------- top-2 + gate softmax + perm (fused) -------------------
__global__ void topk_perm_kernel()
{
    __shared__ int scnt[NEXP], soff[NEXP], scur[NEXP];
    const int t = threadIdx.x;  // 512
    if (t < BATCH) {
        const int b = t;
        float l[NEXP];
#pragma unroll
        for (int e = 0; e < NEXP; e++) l[e] = g_logits[b * NEXP + e];
        float b1v = -INFINITY, b2v = -INFINITY;
        int b1i = 0, b2i = 0;
#pragma unroll
        for (int e = 0; e < NEXP; e++) {
            float v = l[e];
            if (v > b1v) { b2v = b1v; b2i = b1i; b1v = v; b1i = e; }
            else if (v > b2v) { b2v = v; b2i = e; }
        }
        float e2 = expf(b2v - b1v);
        float denom = 1.f + e2;
        float gate1 = 1.f / denom;
        float gate2 = e2 / denom;
#pragma unroll
        for (int e = 0; e < NEXP; e++) g_gates[b * NEXP + e] = 0.f;
        g_gates[b * NEXP + b1i] = gate1;
        g_gates[b * NEXP + b2i] = gate2;
        g_pairE[2 * b] = b1i;     g_pairG[2 * b] = gate1;
        g_pairE[2 * b + 1] = b2i; g_pairG[2 * b + 1] = gate2;
    }
    if (t < NEXP) { scnt[t] = 0; scur[t] = 0; }
    __syncthreads();
    const int e = g_pairE[t];
    atomicAdd(&scnt[e], 1);
    __syncthreads();
    if (t == 0) {
        int o = 0;
        for (int i = 0; i < NEXP; i++) { soff[i] = o; o += scnt[i]; }
    }
    __syncthreads();
    const int slot = soff[e] + atomicAdd(&scur[e], 1);
    g_perm[slot] = t;
    if (t < NEXP) { g_cnt[t] = scnt[t]; g_off[t] = soff[t]; }
}

// -------------------------- zero output buffer -----------------------------
__global__ void zero_kernel(float* __restrict__ p, int n)
{
    int i = blockIdx.x * blockDim.x + threadIdx.x;
    if (i < n) p[i] = 0.f;
}

// ------------------- softmax over experts' logits + combine ----------------
__global__ void softmax_combine_kernel(float* __restrict__ y)
{
    const int gr = blockIdx.x;
    const int t = threadIdx.x;
    const int pair = g_perm[gr];
    const int token = pair >> 1;
    const float gate = g_pairG[pair];
    const float* row = g_o + (size_t)gr * OUTD;

    __shared__ float red[256];
    float m = -INFINITY;
    for (int j = t; j < OUTD; j += 256) m = fmaxf(m, row[j]);
    red[t] = m;
    __syncthreads();
    for (int s = 128; s > 0; s >>= 1) {
        if (t < s) red[t] = fmaxf(red[t], red[t + s]);
        __syncthreads();
    }
    const float M = red[0];
    __syncthreads();

    float s = 0.f;
    for (int j = t; j < OUTD; j += 256) s += expf(row[j] - M);
    red[t] = s;
    __syncthreads();
    for (int st = 128; st > 0; st >>= 1) {
        if (t < st) red[t] += red[t + st];
        __syncthreads();
    }
    const float scale = gate / red[0];

    for (int j = t; j < OUTD; j += 256)
        atomicAdd(&y[(size_t)token * OUTD + j], expf(row[j] - M) * scale);
}

// ------------------------------- aux loss ----------------------------------
__global__ void aux_kernel(float* __restrict__ out, int out_size)
{
    __shared__ float imp[NEXP], loadv[NEXP];
    int t = threadIdx.x;
    if (t < NEXP) {
        float s = 0.f, L = 0.f;
        for (int b = 0; b < BATCH; b++) {
            float gv = g_gates[b * NEXP + t];
            s += gv;
            if (gv > 0.f) L += 1.f;
        }
        imp[t] = s;
        loadv[t] = L;
    }
    __syncthreads();
    if (t == 0 && out_size > BATCH * OUTD) {
        float mi = 0.f, ml = 0.f;
        for (int e = 0; e < NEXP; e++) { mi += imp[e]; ml += loadv[e]; }
        mi /= NEXP; ml /= NEXP;
        float vi = 0.f, vl = 0.f;
        for (int e = 0; e < NEXP; e++) {
            float di = imp[e] - mi, dl = loadv[e] - ml;
            vi += di * di; vl += dl * dl;
        }
        vi /= NEXP; vl /= NEXP;
        out[BATCH * OUTD] =
            0.01f * (vi / (mi * mi + 1e-10f) + vl / (ml * ml + 1e-10f));
    }
}

// ------------------------------- launcher ----------------------------------
extern "C" void kernel_launch(void* const* d_in, const int* in_sizes, int n_in,
                              void* d_out, int out_size)
{
    (void)in_sizes; (void)n_in;
    const float* x   = (const float*)d_in[0];
    const float* cw1 = (const float*)d_in[1];
    const float* cb1 = (const float*)d_in[2];
    const float* cw2 = (const float*)d_in[3];
    const float* cb2 = (const float*)d_in[4];
    const float* cw3 = (const float*)d_in[5];
    const float* cb3 = (const float*)d_in[6];
    const float* cw4 = (const float*)d_in[7];
    const float* cb4 = (const float*)d_in[8];
    const float* cw5 = (const float*)d_in[9];
    const float* cb5 = (const float*)d_in[10];
    const float* w1  = (const float*)d_in[11];
    const float* b1  = (const float*)d_in[12];
    const float* w2  = (const float*)d_in[13];
    const float* b2  = (const float*)d_in[14];
    const float* wg  = (const float*)d_in[15];
    float* y = (float*)d_out;

    float *pool_s, *o_s;
    u16 *hiA, *loA, *hiB, *loB, *whi, *wlo, *feathi, *featlo, *hhi, *hlo;
    cudaGetSymbolAddress((void**)&pool_s, g_pool);
    cudaGetSymbolAddress((void**)&o_s, g_o);
    cudaGetSymbolAddress((void**)&hiA, g_hiA);
    cudaGetSymbolAddress((void**)&loA, g_loA);
    cudaGetSymbolAddress((void**)&hiB, g_hiB);
    cudaGetSymbolAddress((void**)&loB, g_loB);
    cudaGetSymbolAddress((void**)&whi, g_whi);
    cudaGetSymbolAddress((void**)&wlo, g_wlo);
    cudaGetSymbolAddress((void**)&feathi, g_feathi);
    cudaGetSymbolAddress((void**)&featlo, g_featlo);
    cudaGetSymbolAddress((void**)&hhi, g_hhi);
    cudaGetSymbolAddress((void**)&hlo, g_hlo);

    cudaFuncSetAttribute(conv1_kernel,
                         cudaFuncAttributeMaxDynamicSharedMemorySize, CONV1_DSM);
    cudaFuncSetAttribute(conv_mma_kernel<128, 32, 32, 256, false>,
                         cudaFuncAttributeMaxDynamicSharedMemorySize, CONV_DSM);
    cudaFuncSetAttribute(conv_mma_kernel<256, 16, 16, 256, false>,
                         cudaFuncAttributeMaxDynamicSharedMemorySize, CONV_DSM);
    cudaFuncSetAttribute(conv_mma_kernel<256, 8, 8, 512, false>,
                         cudaFuncAttributeMaxDynamicSharedMemorySize, CONV_DSM);
    cudaFuncSetAttribute(conv_mma_kernel<512, 4, 4, 512, true>,
                         cudaFuncAttributeMaxDynamicSharedMemorySize, CONV_DSM);
    cudaFuncSetAttribute(expert_mma_kernel<DFEAT, HID, true, true, true>,
                         cudaFuncAttributeMaxDynamicSharedMemorySize, EXP_DSM);
    cudaFuncSetAttribute(expert_mma_kernel<HID, OUTD, false, false, false>,
                         cudaFuncAttributeMaxDynamicSharedMemorySize, EXP_DSM);

    // weight offsets within g_whi/g_wlo (elements)
    const size_t OFF2 = 0, OFF3 = 294912, OFF4 = 884736, OFF5 = 2064384;

    // ---- all conv weight packs upfront ----
    wpack_kernel<<<(256 * 128 * 9 + 255) / 256, 256>>>(cw2, whi + OFF2, wlo + OFF2, 256, 128);
    wpack_kernel<<<(256 * 256 * 9 + 255) / 256, 256>>>(cw3, whi + OFF3, wlo + OFF3, 256, 256);
    wpack_kernel<<<(512 * 256 * 9 + 255) / 256, 256>>>(cw4, whi + OFF4, wlo + OFF4, 512, 256);
    wpack_kernel<<<(512 * 512 * 9 + 255) / 256, 256>>>(cw5, whi + OFF5, wlo + OFF5, 512, 512);

    // ---- conv stack ----
    conv1_kernel<<<8192, 256, CONV1_DSM>>>(x, cw1, cb1, hiA, loA);
    conv_mma_kernel<128, 32, 32, 256, false><<<dim3(2048, 4), 256, CONV_DSM>>>(
        hiA, loA, whi + OFF2, wlo + OFF2, cb2, hiB, loB, nullptr);
    conv_mma_kernel<256, 16, 16, 256, false><<<dim3(512, 4), 256, CONV_DSM>>>(
        hiB, loB, whi + OFF3, wlo + OFF3, cb3, hiA, loA, nullptr);
    conv_mma_kernel<256, 8, 8, 512, false><<<dim3(128, 8), 256, CONV_DSM>>>(
        hiA, loA, whi + OFF4, wlo + OFF4, cb4, hiB, loB, nullptr);
    conv_mma_kernel<512, 4, 4, 512, true><<<dim3(32, 8), 256, CONV_DSM>>>(
        hiB, loB, whi + OFF5, wlo + OFF5, cb5, feathi, featlo, pool_s);

    // ---- gating ----
    gate_logits_kernel<<<NEXP, 256>>>(pool_s, wg);
    topk_perm_kernel<<<1, 512>>>();

    // ---- sparse expert MLPs (bf16 mma) ----
    expert_mma_kernel<DFEAT, HID, true, true, true>
        <<<dim3(HID / 128, NEXP, 8), 256, EXP_DSM>>>(feathi, featlo, w1, b1,
                                                     hhi, hlo, nullptr);
    expert_mma_kernel<HID, OUTD, false, false, false>
        <<<dim3(OUTD / 128, NEXP, 8), 256, EXP_DSM>>>(hhi, hlo, w2, b2,
                                                      nullptr, nullptr, o_s);

    // ---- combine + aux ----
    zero_kernel<<<(out_size + 255) / 256, 256>>>(y, out_size);
    softmax_combine_kernel<<<NPAIR, 256>>>(y);
    aux_kernel<<<1, 256>>>(y, out_size);
}

// round 8
// speedup vs baseline: 1.4220x; 1.4220x over previous
#include <cuda_runtime.h>
#include <cuda_fp16.h>
#include <math.h>
#include <stdint.h>

// ---------------------------------------------------------------------------
// ToyMoE: conv stack (5x conv3x3+relu+maxpool2) -> top-2 gating (eval)
//         -> sparse top-2 expert MLPs -> softmax -> gated combine + aux loss
// conv2-5 & experts: fp16 mma.sync, 2-term split (Ahi*Whi + Alo*Whi),
// per-product err ~2^-12 (fp16 residual split). Fused pool/split epilogues.
// Conv: 512-thread CTAs, 128x128 tiles, 32-k chunks, 3-stage cp.async pipe.
// ---------------------------------------------------------------------------

#define BATCH 256
#define DFEAT 2048
#define HID 4096
#define OUTD 1024
#define NEXP 16
#define NPAIR (BATCH * 2)

typedef unsigned short u16;

template <int X> struct LG { static constexpr int v = 1 + LG<X / 2>::v; };
template <> struct LG<1> { static constexpr int v = 0; };

// ------------------------- scratch (device globals) ------------------------
__device__ u16   g_hiA[(size_t)256 * 1024 * 128];  // hi acts (L1/L3 out)
__device__ u16   g_loA[(size_t)256 * 1024 * 128];  // lo acts
__device__ u16   g_hiB[(size_t)256 * 256 * 256];   // hi acts (L2/L4 out)
__device__ u16   g_loB[(size_t)256 * 256 * 256];
__device__ u16   g_whi[4423680];                   // conv weights hi (fp16)
__device__ float g_pool[BATCH * DFEAT];            // feats fp32 (gating)
__device__ u16   g_feathi[BATCH * DFEAT];
__device__ u16   g_featlo[BATCH * DFEAT];
__device__ u16   g_hhi[(size_t)NPAIR * HID];
__device__ u16   g_hlo[(size_t)NPAIR * HID];
__device__ float g_logits[BATCH * NEXP];
__device__ float g_gates[BATCH * NEXP];
__device__ int   g_pairE[NPAIR];
__device__ float g_pairG[NPAIR];
__device__ int   g_perm[NPAIR];
__device__ int   g_cnt[NEXP];
__device__ int   g_off[NEXP];
__device__ float g_o[(size_t)NPAIR * OUTD];

// ------------------------------ PTX helpers --------------------------------
__device__ __forceinline__ uint32_t smem_u32(const void* p) {
    uint32_t a;
    asm("{ .reg .u64 t; cvta.to.shared.u64 t, %1; cvt.u32.u64 %0, t; }"
        : "=r"(a) : "l"(p));
    return a;
}

#define SWZ64(x) ((x) ^ (((x) >> 3) & 0x30))

__device__ __forceinline__ void cp16(uint32_t dst, const void* src, int sz) {
    asm volatile("cp.async.cg.shared.global [%0], [%1], 16, %2;"
                 :: "r"(dst), "l"(src), "r"(sz) : "memory");
}
#define CP_COMMIT() asm volatile("cp.async.commit_group;" ::: "memory")
#define CP_WAIT(n)  asm volatile("cp.async.wait_group %0;" :: "n"(n) : "memory")

__device__ __forceinline__ void ldsm4(uint32_t& r0, uint32_t& r1,
                                      uint32_t& r2, uint32_t& r3, uint32_t a) {
    asm volatile("ldmatrix.sync.aligned.m8n8.x4.shared.b16 {%0,%1,%2,%3}, [%4];"
                 : "=r"(r0), "=r"(r1), "=r"(r2), "=r"(r3) : "r"(a));
}
__device__ __forceinline__ void mma16816(float* d, const uint32_t* a,
                                         const uint32_t* b) {
    asm volatile(
        "mma.sync.aligned.m16n8k16.row.col.f32.f16.f16.f32 "
        "{%0,%1,%2,%3}, {%4,%5,%6,%7}, {%8,%9}, {%0,%1,%2,%3};"
        : "+f"(d[0]), "+f"(d[1]), "+f"(d[2]), "+f"(d[3])
        : "r"(a[0]), "r"(a[1]), "r"(a[2]), "r"(a[3]), "r"(b[0]), "r"(b[1]));
}
// fp16 residual split: v = hi + lo, |lo| <= ulp(hi)/2 ~ v*2^-11
__device__ __forceinline__ void split2(float v, u16* hi, u16* lo) {
    __half h = __float2half_rn(v);
    __half l = __float2half_rn(v - __half2float(h));
    *hi = __half_as_ushort(h);
    *lo = __half_as_ushort(l);
}

// --------------------- fp16 mma.sync conv3x3 (SAME, relu, fused pool) ------
// 2 passes per 32-channel tap chunk: Ahi*Whi + Alo*Whi (W quantized to fp16
// hi only; dropped A*Wlo term ~2^-12 relative).
// Stage 24KB = Ahi(8K) Alo(8K) Whi(8K), all SW64. 3 stages, 1 sync/chunk.
#define STG 24576
#define CONV_DSM (3 * STG)

template <int CI, int H, int W, int CO, bool FEATS>
__global__ void __launch_bounds__(512, 1) conv_mma_kernel(
    const u16* __restrict__ inhi, const u16* __restrict__ inlo,
    const u16* __restrict__ whi, const float* __restrict__ bias,
    u16* __restrict__ outhi, u16* __restrict__ outlo, float* __restrict__ outf)
{
    constexpr int HW = H * W;
    constexpr int LHW = LG<HW>::v;
    constexpr int LW = LG<W>::v;
    constexpr int CPT = CI / 32;
    constexpr int NCH = 9 * CPT;
    constexpr int WROW = 9 * CI;

    extern __shared__ __align__(1024) char dsm[];
    const uint32_t sb = smem_u32(dsm);
    const int t = threadIdx.x;
    const int lane = t & 31;
    const int wid = t >> 5;
    const int wm = wid & 3, wn = wid >> 2;     // 4x4 warp grid, 32x32 tiles
    const int m0 = blockIdx.x * 128, n0 = blockIdx.y * 128;

    // fill metadata: one 64B row per thread (r = t>>2, seg = t&3)
    const int r = t >> 2, sg = t & 3;
    const int m = m0 + r;
    const int bI = m >> LHW;
    const int pos = m & (HW - 1);
    const int yy = pos >> LW, xx = pos & (W - 1);
    const size_t wro = (size_t)(n0 + r) * WROW + sg * 8;
    const uint32_t dstA = SWZ64((uint32_t)(r * 64 + sg * 16));

    auto fill = [&](int st, int c) {
        const uint32_t stg = sb + (uint32_t)st * STG;
        const int tap = c / CPT;
        const int cib = (c % CPT) * 32;
        const int dy = tap / 3 - 1, dx = tap % 3 - 1;
        const int iy = yy + dy, ix = xx + dx;
        const bool ok = (iy >= 0 && iy < H && ix >= 0 && ix < W);
        const size_t ai =
            (((size_t)bI * H + (ok ? iy : 0)) * W + (ok ? ix : 0)) * CI + cib + sg * 8;
        cp16(stg + dstA, inhi + ai, ok ? 16 : 0);
        cp16(stg + 8192 + dstA, inlo + ai, ok ? 16 : 0);
        cp16(stg + 16384 + dstA, whi + wro + tap * CI + cib, 16);
    };

    float acc[2][4][4];
#pragma unroll
    for (int a = 0; a < 2; a++)
#pragma unroll
        for (int b = 0; b < 4; b++)
#pragma unroll
            for (int cj = 0; cj < 4; cj++) acc[a][b][cj] = 0.f;

    fill(0, 0);
    CP_COMMIT();
    fill(1, 1);
    CP_COMMIT();

    int st = 0;
    for (int c = 0; c < NCH; c++) {
        if (c + 1 < NCH) { CP_WAIT(1); } else { CP_WAIT(0); }
        __syncthreads();
        if (c + 2 < NCH) {
            fill(st >= 1 ? st - 1 : st + 2, c + 2);
            CP_COMMIT();
        }
        const uint32_t stg = sb + (uint32_t)st * STG;
#pragma unroll
        for (int ks = 0; ks < 2; ks++) {
            const int c0 = ks * 32;
            uint32_t ah[2][4], al[2][4], bh[8];
#pragma unroll
            for (int mt = 0; mt < 2; mt++) {
                const int row = wm * 32 + mt * 16 + (lane & 15);
                const uint32_t off = SWZ64((uint32_t)(row * 64 + c0 + (lane >> 4) * 16));
                ldsm4(ah[mt][0], ah[mt][1], ah[mt][2], ah[mt][3], stg + off);
                ldsm4(al[mt][0], al[mt][1], al[mt][2], al[mt][3], stg + 8192 + off);
            }
#pragma unroll
            for (int p = 0; p < 2; p++) {
                const int row = wn * 32 + p * 16 + (lane & 7) + (lane >> 4) * 8;
                const uint32_t off =
                    SWZ64((uint32_t)(row * 64 + c0 + ((lane >> 3) & 1) * 16));
                ldsm4(bh[p * 4], bh[p * 4 + 1], bh[p * 4 + 2], bh[p * 4 + 3],
                      stg + 16384 + off);
            }
#pragma unroll
            for (int mt = 0; mt < 2; mt++)
#pragma unroll
                for (int nt = 0; nt < 4; nt++) {
                    mma16816(acc[mt][nt], ah[mt], &bh[nt * 2]);
                    mma16816(acc[mt][nt], al[mt], &bh[nt * 2]);
                }
        }
        st = (st + 1 == 3) ? 0 : st + 1;
    }
    __syncthreads();

    // ---- epilogue: bias+relu -> SMEM tile -> 2x2 pool -> hi/lo planes ----
    float* S = (float*)dsm;  // [128][132]
#pragma unroll
    for (int mt = 0; mt < 2; mt++)
#pragma unroll
        for (int half = 0; half < 2; half++) {
            const int rr = wm * 32 + mt * 16 + (lane >> 2) + half * 8;
#pragma unroll
            for (int nt = 0; nt < 4; nt++)
#pragma unroll
                for (int j = 0; j < 2; j++) {
                    const int ncl = wn * 32 + nt * 8 + (lane & 3) * 2 + j;
                    float v = acc[mt][nt][half * 2 + j] + bias[n0 + ncl];
                    S[rr * 132 + ncl] = v > 0.f ? v : 0.f;
                }
        }
    __syncthreads();

    constexpr int Wo = W / 2;
    constexpr int HWo = HW / 4;
    for (int idx = t; idx < 32 * 128; idx += 512) {
        const int pp = idx >> 7;
        const int cl = idx & 127;
        const int lpy = pp / Wo;
        const int lpx = pp % Wo;
        const int lm = lpy * 2 * W + lpx * 2;
        const int mm = m0 + lm;
        const int b = mm >> LHW;
        const int rem = mm & (HW - 1);
        const int y = rem >> LW, x = rem & (W - 1);
        const float* p = S + lm * 132 + cl;
        float v = fmaxf(fmaxf(p[0], p[132]), fmaxf(p[W * 132], p[(W + 1) * 132]));
        const int posn = (y >> 1) * Wo + (x >> 1);
        u16 hb, lb;
        split2(v, &hb, &lb);
        if (FEATS) {
            const int d = (n0 + cl) * HWo + posn;
            outf[(size_t)b * DFEAT + d] = v;
            outhi[(size_t)b * DFEAT + d] = hb;
            outlo[(size_t)b * DFEAT + d] = lb;
        } else {
            const size_t oi = ((size_t)b * HWo + posn) * CO + (n0 + cl);
            outhi[oi] = hb;
            outlo[oi] = lb;
        }
    }
}

// ---- weight pack: OIHW -> [co][tap*CI+ci] fp16 hi -------------------------
__global__ void wpack_kernel(const float* __restrict__ w,
                             u16* __restrict__ ohi, int CO, int CI)
{
    const int i = blockIdx.x * 256 + threadIdx.x;
    if (i >= CO * CI * 9) return;
    const int tap = i % 9;
    const int ci = (i / 9) % CI;
    const int co = i / (9 * CI);
    ohi[(size_t)co * CI * 9 + (size_t)tap * CI + ci] =
        __half_as_ushort(__float2half_rn(w[i]));
}

// -------------- grouped expert GEMM, fp16 mma (fc1 / fc2) ------------------
// M-tile 32 x N-tile 128, chunk = 32 k. W fp32 converted in-kernel to fp16.
// Stage 28KB: Ahi 2K @0, Alo 2K @2048, Wf32 16K @4096, Whi 8K @20480.
#define ESTG 28672
#define EXP_DSM (3 * ESTG + 128)

template <int KDIM, int NDIM, bool RELU, bool GATHER, bool PACKOUT>
__global__ void __launch_bounds__(256, 2) expert_mma_kernel(
    const u16* __restrict__ Ahi, const u16* __restrict__ Alo,
    const float* __restrict__ Wt, const float* __restrict__ bias,
    u16* __restrict__ ohp, u16* __restrict__ olp, float* __restrict__ of)
{
    constexpr int NCH = KDIM / 32;
    const int e = blockIdx.y;
    const int cnt = g_cnt[e];
    const int off = g_off[e];
    const int rbase = blockIdx.z * 32;
    if (rbase >= cnt) return;
    const int n0 = blockIdx.x * 128;

    extern __shared__ __align__(1024) char dsm[];
    const uint32_t sb = smem_u32(dsm);
    const int t = threadIdx.x;
    const int lane = t & 31;
    const int wn = t >> 5;

    int* srcRow = (int*)(dsm + 3 * ESTG);
    if (t < 32) {
        int rr = rbase + t, sr = -1;
        if (rr < cnt) sr = GATHER ? (g_perm[off + rr] >> 1) : (off + rr);
        srcRow[t] = sr;
    }
    __syncthreads();

    const float* wbase = Wt + (size_t)e * KDIM * NDIM + n0;

    auto fill = [&](int st, int c) {
        const uint32_t stg = sb + (uint32_t)st * ESTG;
        const int kb = c * 32;
        if (t < 128) {
            const int rr = t >> 2, sg = t & 3;
            const int sr = srcRow[rr];
            const size_t ai = (sr < 0) ? 0 : ((size_t)sr * KDIM + kb + sg * 8);
            const uint32_t d = SWZ64((uint32_t)(rr * 64 + sg * 16));
            cp16(stg + d, Ahi + ai, sr < 0 ? 0 : 16);
            cp16(stg + 2048 + d, Alo + ai, sr < 0 ? 0 : 16);
        }
#pragma unroll
        for (int i = 0; i < 4; i++) {
            const int task = t + i * 256;
            const int k = task >> 5, sgw = task & 31;
            cp16(stg + 4096 + (uint32_t)(k * 512 + sgw * 16),
                 wbase + (size_t)(kb + k) * NDIM + sgw * 4, 16);
        }
    };

    float acc[2][2][4];
#pragma unroll
    for (int a = 0; a < 2; a++)
#pragma unroll
        for (int b = 0; b < 2; b++)
#pragma unroll
            for (int cj = 0; cj < 4; cj++) acc[a][b][cj] = 0.f;

    fill(0, 0);
    CP_COMMIT();
    fill(1, 1);
    CP_COMMIT();

    int st = 0;
    for (int c = 0; c < NCH; c++) {
        if (c + 1 < NCH) { CP_WAIT(1); } else { CP_WAIT(0); }
        __syncthreads();
        if (c + 2 < NCH) {
            fill(st >= 1 ? st - 1 : st + 2, c + 2);
            CP_COMMIT();
        }
        char* stgc = dsm + (size_t)st * ESTG;
        // ---- convert W fp32 tile -> Whi (SW64, n-major) ----
        {
            const int k = t >> 3, ng = t & 7;
#pragma unroll
            for (int j = 0; j < 4; j++) {
                const float4 w =
                    *(const float4*)(stgc + 4096 + k * 512 + ng * 64 + j * 16);
                const float vv[4] = {w.x, w.y, w.z, w.w};
#pragma unroll
                for (int jj = 0; jj < 4; jj++) {
                    const int n = ng * 16 + j * 4 + jj;
                    *(u16*)(stgc + 20480 + SWZ64((uint32_t)(n * 64 + 2 * k))) =
                        __half_as_ushort(__float2half_rn(vv[jj]));
                }
            }
        }
        __syncthreads();

        const uint32_t stg = sb + (uint32_t)st * ESTG;
#pragma unroll
        for (int ks = 0; ks < 2; ks++) {
            const int c0 = ks * 32;
            uint32_t ah[2][4], al[2][4], bh[4];
#pragma unroll
            for (int mt = 0; mt < 2; mt++) {
                const int row = mt * 16 + (lane & 15);
                const uint32_t o = SWZ64((uint32_t)(row * 64 + c0 + (lane >> 4) * 16));
                ldsm4(ah[mt][0], ah[mt][1], ah[mt][2], ah[mt][3], stg + o);
                ldsm4(al[mt][0], al[mt][1], al[mt][2], al[mt][3], stg + 2048 + o);
            }
            {
                const int row = wn * 16 + (lane & 7) + (lane >> 4) * 8;
                const uint32_t o =
                    SWZ64((uint32_t)(row * 64 + c0 + ((lane >> 3) & 1) * 16));
                ldsm4(bh[0], bh[1], bh[2], bh[3], stg + 20480 + o);
            }
#pragma unroll
            for (int mt = 0; mt < 2; mt++)
#pragma unroll
                for (int nt = 0; nt < 2; nt++) {
                    mma16816(acc[mt][nt], ah[mt], &bh[nt * 2]);
                    mma16816(acc[mt][nt], al[mt], &bh[nt * 2]);
                }
        }
        st = (st + 1 == 3) ? 0 : st + 1;
    }

    // ---- epilogue ----
#pragma unroll
    for (int mt = 0; mt < 2; mt++)
#pragma unroll
        for (int half = 0; half < 2; half++) {
            const int rr = rbase + mt * 16 + (lane >> 2) + half * 8;
            if (rr >= cnt) continue;
            const int gr = off + rr;
#pragma unroll
            for (int nt = 0; nt < 2; nt++)
#pragma unroll
                for (int j = 0; j < 2; j++) {
                    const int n = n0 + wn * 16 + nt * 8 + (lane & 3) * 2 + j;
                    float v = acc[mt][nt][half * 2 + j] + bias[(size_t)e * NDIM + n];
                    if (RELU) v = v > 0.f ? v : 0.f;
                    if (PACKOUT) {
                        u16 hb, lb;
                        split2(v, &hb, &lb);
                        ohp[(size_t)gr * NDIM + n] = hb;
                        olp[(size_t)gr * NDIM + n] = lb;
                    } else {
                        of[(size_t)gr * NDIM + n] = v;
                    }
                }
        }
}

// ---------- conv1: fp32 SIMT (CI=3) with fused pool+split epilogue ---------
#define CONV1_DSM 68608

__global__ __launch_bounds__(256, 1) void conv1_kernel(
    const float* __restrict__ in, const float* __restrict__ wt,
    const float* __restrict__ bias, u16* __restrict__ outhi,
    u16* __restrict__ outlo)
{
    constexpr int CI = 3, H = 64, W = 64;
    constexpr int BK = 27;
    constexpr int HW = H * W;

    extern __shared__ __align__(1024) char dsm[];
    float (*As)[132] = (float(*)[132])dsm;
    float (*Bs)[132] = (float(*)[132])(dsm + 14784);

    const int t = threadIdx.x;
    const int m0 = blockIdx.x * 128;
    const int tx = t & 15;
    const int ty = t >> 4;

    float acc[8][8];
#pragma unroll
    for (int i = 0; i < 8; i++)
#pragma unroll
        for (int j = 0; j < 8; j++) acc[i][j] = 0.f;

#pragma unroll
    for (int j = 0; j < 14; j++) {
        int e = j * 256 + t;
        if (e >= 27 * 128) break;
        int k = e >> 7;
        int p = e & 127;
        int ci = k / 9;
        int rc = k % 9;
        int s = m0 + p;
        int b = s / HW;
        int rr = s % HW;
        int y = rr / W, x = rr % W;
        int iy = y + rc / 3 - 1;
        int ix = x + rc % 3 - 1;
        float v = 0.f;
        if (iy >= 0 && iy < H && ix >= 0 && ix < W)
            v = in[((size_t)(b * CI + ci) * H + iy) * W + ix];
        As[k][p] = v;
    }
    if (t < 128) {
        const float* wp = wt + (size_t)t * 27;
#pragma unroll
        for (int k = 0; k < 27; k++) Bs[k][t] = wp[k];
    }
    __syncthreads();

#pragma unroll
    for (int kk = 0; kk < BK; kk++) {
        float a[8], bv[8];
        *(float4*)&a[0] = *(const float4*)&As[kk][tx * 8];
        *(float4*)&a[4] = *(const float4*)&As[kk][tx * 8 + 4];
        *(float4*)&bv[0] = *(const float4*)&Bs[kk][ty * 8];
        *(float4*)&bv[4] = *(const float4*)&Bs[kk][ty * 8 + 4];
#pragma unroll
        for (int i = 0; i < 8; i++)
#pragma unroll
            for (int j = 0; j < 8; j++) acc[i][j] += a[i] * bv[j];
    }
    __syncthreads();

    float* S = (float*)dsm;
#pragma unroll
    for (int i = 0; i < 8; i++) {
        const int r = tx * 8 + i;
#pragma unroll
        for (int j = 0; j < 8; j++) {
            const int cl = ty * 8 + j;
            float v = acc[i][j] + bias[cl];
            S[r * 132 + cl] = v > 0.f ? v : 0.f;
        }
    }
    __syncthreads();

    for (int idx = t; idx < 32 * 128; idx += 256) {
        const int pp = idx >> 7;
        const int cl = idx & 127;
        const int lm = pp * 2;
        const int m = m0 + lm;
        const int b = m >> 12;
        const int rem = m & 4095;
        const int y = rem >> 6, x = rem & 63;
        const float* p = S + lm * 132 + cl;
        float v = fmaxf(fmaxf(p[0], p[132]), fmaxf(p[64 * 132], p[65 * 132]));
        u16 hb, lb;
        split2(v, &hb, &lb);
        const size_t oi = ((size_t)b * 1024 + (y >> 1) * 32 + (x >> 1)) * 128 + cl;
        outhi[oi] = hb;
        outlo[oi] = lb;
    }
}

// ----------------------------- gate logits ---------------------------------
__global__ void gate_logits_kernel(const float* __restrict__ feats,
                                   const float* __restrict__ wg)
{
    int t = blockIdx.x * blockDim.x + threadIdx.x;
    if (t >= BATCH * NEXP) return;
    int b = t >> 4, e = t & 15;
    const float* f = feats + (size_t)b * DFEAT;
    float s = 0.f;
    for (int d = 0; d < DFEAT; d++) s += f[d] * wg[d * NEXP + e];
    g_logits[t] = s;
}

// ------------------- top-2 + gate softmax + perm (fused) -------------------
__global__ void topk_perm_kernel()
{
    __shared__ int scnt[NEXP], soff[NEXP], scur[NEXP];
    const int t = threadIdx.x;  // 512
    if (t < BATCH) {
        const int b = t;
        float l[NEXP];
#pragma unroll
        for (int e = 0; e < NEXP; e++) l[e] = g_logits[b * NEXP + e];
        float b1v = -INFINITY, b2v = -INFINITY;
        int b1i = 0, b2i = 0;
#pragma unroll
        for (int e = 0; e < NEXP; e++) {
            float v = l[e];
            if (v > b1v) { b2v = b1v; b2i = b1i; b1v = v; b1i = e; }
            else if (v > b2v) { b2v = v; b2i = e; }
        }
        float e2 = expf(b2v - b1v);
        float denom = 1.f + e2;
        float gate1 = 1.f / denom;
        float gate2 = e2 / denom;
#pragma unroll
        for (int e = 0; e < NEXP; e++) g_gates[b * NEXP + e] = 0.f;
        g_gates[b * NEXP + b1i] = gate1;
        g_gates[b * NEXP + b2i] = gate2;
        g_pairE[2 * b] = b1i;     g_pairG[2 * b] = gate1;
        g_pairE[2 * b + 1] = b2i; g_pairG[2 * b + 1] = gate2;
    }
    if (t < NEXP) { scnt[t] = 0; scur[t] = 0; }
    __syncthreads();
    const int e = g_pairE[t];
    atomicAdd(&scnt[e], 1);
    __syncthreads();
    if (t == 0) {
        int o = 0;
        for (int i = 0; i < NEXP; i++) { soff[i] = o; o += scnt[i]; }
    }
    __syncthreads();
    const int slot = soff[e] + atomicAdd(&scur[e], 1);
    g_perm[slot] = t;
    if (t < NEXP) { g_cnt[t] = scnt[t]; g_off[t] = soff[t]; }
}

// -------------------------- zero output buffer -----------------------------
__global__ void zero_kernel(float* __restrict__ p, int n)
{
    int i = blockIdx.x * blockDim.x + threadIdx.x;
    if (i < n) p[i] = 0.f;
}

// ------------------- softmax over experts' logits + combine ----------------
__global__ void softmax_combine_kernel(float* __restrict__ y)
{
    const int gr = blockIdx.x;
    const int t = threadIdx.x;
    const int pair = g_perm[gr];
    const int token = pair >> 1;
    const float gate = g_pairG[pair];
    const float* row = g_o + (size_t)gr * OUTD;

    __shared__ float red[256];
    float m = -INFINITY;
    for (int j = t; j < OUTD; j += 256) m = fmaxf(m, row[j]);
    red[t] = m;
    __syncthreads();
    for (int s = 128; s > 0; s >>= 1) {
        if (t < s) red[t] = fmaxf(red[t], red[t + s]);
        __syncthreads();
    }
    const float M = red[0];
    __syncthreads();

    float s = 0.f;
    for (int j = t; j < OUTD; j += 256) s += expf(row[j] - M);
    red[t] = s;
    __syncthreads();
    for (int st = 128; st > 0; st >>= 1) {
        if (t < st) red[t] += red[t + st];
        __syncthreads();
    }
    const float scale = gate / red[0];

    for (int j = t; j < OUTD; j += 256)
        atomicAdd(&y[(size_t)token * OUTD + j], expf(row[j] - M) * scale);
}

// ------------------------------- aux loss ----------------------------------
__global__ void aux_kernel(float* __restrict__ out, int out_size)
{
    __shared__ float imp[NEXP], loadv[NEXP];
    int t = threadIdx.x;
    if (t < NEXP) {
        float s = 0.f, L = 0.f;
        for (int b = 0; b < BATCH; b++) {
            float gv = g_gates[b * NEXP + t];
            s += gv;
            if (gv > 0.f) L += 1.f;
        }
        imp[t] = s;
        loadv[t] = L;
    }
    __syncthreads();
    if (t == 0 && out_size > BATCH * OUTD) {
        float mi = 0.f, ml = 0.f;
        for (int e = 0; e < NEXP; e++) { mi += imp[e]; ml += loadv[e]; }
        mi /= NEXP; ml /= NEXP;
        float vi = 0.f, vl = 0.f;
        for (int e = 0; e < NEXP; e++) {
            float di = imp[e] - mi, dl = loadv[e] - ml;
            vi += di * di; vl += dl * dl;
        }
        vi /= NEXP; vl /= NEXP;
        out[BATCH * OUTD] =
            0.01f * (vi / (mi * mi + 1e-10f) + vl / (ml * ml + 1e-10f));
    }
}

// ------------------------------- launcher ----------------------------------
extern "C" void kernel_launch(void* const* d_in, const int* in_sizes, int n_in,
                              void* d_out, int out_size)
{
    (void)in_sizes; (void)n_in;
    const float* x   = (const float*)d_in[0];
    const float* cw1 = (const float*)d_in[1];
    const float* cb1 = (const float*)d_in[2];
    const float* cw2 = (const float*)d_in[3];
    const float* cb2 = (const float*)d_in[4];
    const float* cw3 = (const float*)d_in[5];
    const float* cb3 = (const float*)d_in[6];
    const float* cw4 = (const float*)d_in[7];
    const float* cb4 = (const float*)d_in[8];
    const float* cw5 = (const float*)d_in[9];
    const float* cb5 = (const float*)d_in[10];
    const float* w1  = (const float*)d_in[11];
    const float* b1  = (const float*)d_in[12];
    const float* w2  = (const float*)d_in[13];
    const float* b2  = (const float*)d_in[14];
    const float* wg  = (const float*)d_in[15];
    float* y = (float*)d_out;

    float *pool_s, *o_s;
    u16 *hiA, *loA, *hiB, *loB, *whi, *feathi, *featlo, *hhi, *hlo;
    cudaGetSymbolAddress((void**)&pool_s, g_pool);
    cudaGetSymbolAddress((void**)&o_s, g_o);
    cudaGetSymbolAddress((void**)&hiA, g_hiA);
    cudaGetSymbolAddress((void**)&loA, g_loA);
    cudaGetSymbolAddress((void**)&hiB, g_hiB);
    cudaGetSymbolAddress((void**)&loB, g_loB);
    cudaGetSymbolAddress((void**)&whi, g_whi);
    cudaGetSymbolAddress((void**)&feathi, g_feathi);
    cudaGetSymbolAddress((void**)&featlo, g_featlo);
    cudaGetSymbolAddress((void**)&hhi, g_hhi);
    cudaGetSymbolAddress((void**)&hlo, g_hlo);

    cudaFuncSetAttribute(conv1_kernel,
                         cudaFuncAttributeMaxDynamicSharedMemorySize, CONV1_DSM);
    cudaFuncSetAttribute(conv_mma_kernel<128, 32, 32, 256, false>,
                         cudaFuncAttributeMaxDynamicSharedMemorySize, CONV_DSM);
    cudaFuncSetAttribute(conv_mma_kernel<256, 16, 16, 256, false>,
                         cudaFuncAttributeMaxDynamicSharedMemorySize, CONV_DSM);
    cudaFuncSetAttribute(conv_mma_kernel<256, 8, 8, 512, false>,
                         cudaFuncAttributeMaxDynamicSharedMemorySize, CONV_DSM);
    cudaFuncSetAttribute(conv_mma_kernel<512, 4, 4, 512, true>,
                         cudaFuncAttributeMaxDynamicSharedMemorySize, CONV_DSM);
    cudaFuncSetAttribute(expert_mma_kernel<DFEAT, HID, true, true, true>,
                         cudaFuncAttributeMaxDynamicSharedMemorySize, EXP_DSM);
    cudaFuncSetAttribute(expert_mma_kernel<HID, OUTD, false, false, false>,
                         cudaFuncAttributeMaxDynamicSharedMemorySize, EXP_DSM);

    // weight offsets within g_whi (elements)
    const size_t OFF2 = 0, OFF3 = 294912, OFF4 = 884736, OFF5 = 2064384;

    // ---- all conv weight packs upfront ----
    wpack_kernel<<<(256 * 128 * 9 + 255) / 256, 256>>>(cw2, whi + OFF2, 256, 128);
    wpack_kernel<<<(256 * 256 * 9 + 255) / 256, 256>>>(cw3, whi + OFF3, 256, 256);
    wpack_kernel<<<(512 * 256 * 9 + 255) / 256, 256>>>(cw4, whi + OFF4, 512, 256);
    wpack_kernel<<<(512 * 512 * 9 + 255) / 256, 256>>>(cw5, whi + OFF5, 512, 512);

    // ---- conv stack ----
    conv1_kernel<<<8192, 256, CONV1_DSM>>>(x, cw1, cb1, hiA, loA);
    conv_mma_kernel<128, 32, 32, 256, false><<<dim3(2048, 2), 512, CONV_DSM>>>(
        hiA, loA, whi + OFF2, cb2, hiB, loB, nullptr);
    conv_mma_kernel<256, 16, 16, 256, false><<<dim3(512, 2), 512, CONV_DSM>>>(
        hiB, loB, whi + OFF3, cb3, hiA, loA, nullptr);
    conv_mma_kernel<256, 8, 8, 512, false><<<dim3(128, 4), 512, CONV_DSM>>>(
        hiA, loA, whi + OFF4, cb4, hiB, loB, nullptr);
    conv_mma_kernel<512, 4, 4, 512, true><<<dim3(32, 4), 512, CONV_DSM>>>(
        hiB, loB, whi + OFF5, cb5, feathi, featlo, pool_s);

    // ---- gating ----
    gate_logits_kernel<<<NEXP, 256>>>(pool_s, wg);
    topk_perm_kernel<<<1, 512>>>();

    // ---- sparse expert MLPs (fp16 mma) ----
    expert_mma_kernel<DFEAT, HID, true, true, true>
        <<<dim3(HID / 128, NEXP, 8), 256, EXP_DSM>>>(feathi, featlo, w1, b1,
                                                     hhi, hlo, nullptr);
    expert_mma_kernel<HID, OUTD, false, false, false>
        <<<dim3(OUTD / 128, NEXP, 8), 256, EXP_DSM>>>(hhi, hlo, w2, b2,
                                                      nullptr, nullptr, o_s);

    // ---- combine + aux ----
    zero_kernel<<<(out_size + 255) / 256, 256>>>(y, out_size);
    softmax_combine_kernel<<<NPAIR, 256>>>(y);
    aux_kernel<<<1, 256>>>(y, out_size);
}

// round 9
// speedup vs baseline: 1.7781x; 1.2505x over previous
#include <cuda_runtime.h>
#include <cuda_fp16.h>
#include <math.h>
#include <stdint.h>

// ---------------------------------------------------------------------------
// ToyMoE: conv stack (5x conv3x3+relu+maxpool2) -> top-2 gating (eval)
//         -> sparse top-2 expert MLPs -> softmax -> gated combine + aux loss
// conv2-5: PURE fp16 mma.sync (1 pass). experts: fp16 2-term (Ahi+Alo)*Whi.
// Fused pool/pack epilogues. 512-thread conv CTAs, 3-stage cp.async pipe.
// ---------------------------------------------------------------------------

#define BATCH 256
#define DFEAT 2048
#define HID 4096
#define OUTD 1024
#define NEXP 16
#define NPAIR (BATCH * 2)

typedef unsigned short u16;

template <int X> struct LG { static constexpr int v = 1 + LG<X / 2>::v; };
template <> struct LG<1> { static constexpr int v = 0; };

// ------------------------- scratch (device globals) ------------------------
__device__ u16   g_hiA[(size_t)256 * 1024 * 128];  // hi acts (L1/L3 out)
__device__ u16   g_hiB[(size_t)256 * 256 * 256];   // hi acts (L2/L4 out)
__device__ u16   g_whi[4423680];                   // conv weights fp16
__device__ float g_pool[BATCH * DFEAT];            // feats fp32 (gating)
__device__ u16   g_feathi[BATCH * DFEAT];
__device__ u16   g_featlo[BATCH * DFEAT];
__device__ u16   g_hhi[(size_t)NPAIR * HID];
__device__ u16   g_hlo[(size_t)NPAIR * HID];
__device__ float g_logits[BATCH * NEXP];
__device__ float g_gates[BATCH * NEXP];
__device__ int   g_pairE[NPAIR];
__device__ float g_pairG[NPAIR];
__device__ int   g_perm[NPAIR];
__device__ int   g_cnt[NEXP];
__device__ int   g_off[NEXP];
__device__ float g_o[(size_t)NPAIR * OUTD];

// ------------------------------ PTX helpers --------------------------------
__device__ __forceinline__ uint32_t smem_u32(const void* p) {
    uint32_t a;
    asm("{ .reg .u64 t; cvta.to.shared.u64 t, %1; cvt.u32.u64 %0, t; }"
        : "=r"(a) : "l"(p));
    return a;
}

#define SWZ64(x) ((x) ^ (((x) >> 3) & 0x30))

__device__ __forceinline__ void cp16(uint32_t dst, const void* src, int sz) {
    asm volatile("cp.async.cg.shared.global [%0], [%1], 16, %2;"
                 :: "r"(dst), "l"(src), "r"(sz) : "memory");
}
#define CP_COMMIT() asm volatile("cp.async.commit_group;" ::: "memory")
#define CP_WAIT(n)  asm volatile("cp.async.wait_group %0;" :: "n"(n) : "memory")

__device__ __forceinline__ void ldsm4(uint32_t& r0, uint32_t& r1,
                                      uint32_t& r2, uint32_t& r3, uint32_t a) {
    asm volatile("ldmatrix.sync.aligned.m8n8.x4.shared.b16 {%0,%1,%2,%3}, [%4];"
                 : "=r"(r0), "=r"(r1), "=r"(r2), "=r"(r3) : "r"(a));
}
__device__ __forceinline__ void mma16816(float* d, const uint32_t* a,
                                         const uint32_t* b) {
    asm volatile(
        "mma.sync.aligned.m16n8k16.row.col.f32.f16.f16.f32 "
        "{%0,%1,%2,%3}, {%4,%5,%6,%7}, {%8,%9}, {%0,%1,%2,%3};"
        : "+f"(d[0]), "+f"(d[1]), "+f"(d[2]), "+f"(d[3])
        : "r"(a[0]), "r"(a[1]), "r"(a[2]), "r"(a[3]), "r"(b[0]), "r"(b[1]));
}
// fp16 residual split: v = hi + lo, |lo| <= ulp(hi)/2 ~ v*2^-11
__device__ __forceinline__ void split2(float v, u16* hi, u16* lo) {
    __half h = __float2half_rn(v);
    __half l = __float2half_rn(v - __half2float(h));
    *hi = __half_as_ushort(h);
    *lo = __half_as_ushort(l);
}

// --------------------- fp16 mma.sync conv3x3 (SAME, relu, fused pool) ------
// PURE fp16, 1 pass per 32-channel tap chunk: Ahi*Whi.
// Stage 16KB = Ahi(8K) Whi(8K), SW64. 3 stages, 1 sync/chunk.
#define STG 16384
#define CONV_DSM 67584   // max(3*STG=49152, epilogue 128*132*4=67584)

template <int CI, int H, int W, int CO, bool FEATS>
__global__ void __launch_bounds__(512, 1) conv_mma_kernel(
    const u16* __restrict__ inhi, const u16* __restrict__ whi,
    const float* __restrict__ bias,
    u16* __restrict__ outhi, u16* __restrict__ outlo, float* __restrict__ outf)
{
    constexpr int HW = H * W;
    constexpr int LHW = LG<HW>::v;
    constexpr int LW = LG<W>::v;
    constexpr int CPT = CI / 32;
    constexpr int NCH = 9 * CPT;
    constexpr int WROW = 9 * CI;

    extern __shared__ __align__(1024) char dsm[];
    const uint32_t sb = smem_u32(dsm);
    const int t = threadIdx.x;
    const int lane = t & 31;
    const int wid = t >> 5;
    const int wm = wid & 3, wn = wid >> 2;     // 4x4 warp grid, 32x32 tiles
    const int m0 = blockIdx.x * 128, n0 = blockIdx.y * 128;

    // fill metadata: one 64B row per thread (r = t>>2, seg = t&3)
    const int r = t >> 2, sg = t & 3;
    const int m = m0 + r;
    const int bI = m >> LHW;
    const int pos = m & (HW - 1);
    const int yy = pos >> LW, xx = pos & (W - 1);
    const size_t wro = (size_t)(n0 + r) * WROW + sg * 8;
    const uint32_t dstA = SWZ64((uint32_t)(r * 64 + sg * 16));

    auto fill = [&](int st, int c) {
        const uint32_t stg = sb + (uint32_t)st * STG;
        const int tap = c / CPT;
        const int cib = (c % CPT) * 32;
        const int dy = tap / 3 - 1, dx = tap % 3 - 1;
        const int iy = yy + dy, ix = xx + dx;
        const bool ok = (iy >= 0 && iy < H && ix >= 0 && ix < W);
        const size_t ai =
            (((size_t)bI * H + (ok ? iy : 0)) * W + (ok ? ix : 0)) * CI + cib + sg * 8;
        cp16(stg + dstA, inhi + ai, ok ? 16 : 0);
        cp16(stg + 8192 + dstA, whi + wro + tap * CI + cib, 16);
    };

    float acc[2][4][4];
#pragma unroll
    for (int a = 0; a < 2; a++)
#pragma unroll
        for (int b = 0; b < 4; b++)
#pragma unroll
            for (int cj = 0; cj < 4; cj++) acc[a][b][cj] = 0.f;

    fill(0, 0);
    CP_COMMIT();
    fill(1, 1);
    CP_COMMIT();

    int st = 0;
    for (int c = 0; c < NCH; c++) {
        if (c + 1 < NCH) { CP_WAIT(1); } else { CP_WAIT(0); }
        __syncthreads();
        if (c + 2 < NCH) {
            fill(st >= 1 ? st - 1 : st + 2, c + 2);
            CP_COMMIT();
        }
        const uint32_t stg = sb + (uint32_t)st * STG;
#pragma unroll
        for (int ks = 0; ks < 2; ks++) {
            const int c0 = ks * 32;
            uint32_t ah[2][4], bh[8];
#pragma unroll
            for (int mt = 0; mt < 2; mt++) {
                const int row = wm * 32 + mt * 16 + (lane & 15);
                const uint32_t off = SWZ64((uint32_t)(row * 64 + c0 + (lane >> 4) * 16));
                ldsm4(ah[mt][0], ah[mt][1], ah[mt][2], ah[mt][3], stg + off);
            }
#pragma unroll
            for (int p = 0; p < 2; p++) {
                const int row = wn * 32 + p * 16 + (lane & 7) + (lane >> 4) * 8;
                const uint32_t off =
                    SWZ64((uint32_t)(row * 64 + c0 + ((lane >> 3) & 1) * 16));
                ldsm4(bh[p * 4], bh[p * 4 + 1], bh[p * 4 + 2], bh[p * 4 + 3],
                      stg + 8192 + off);
            }
#pragma unroll
            for (int mt = 0; mt < 2; mt++)
#pragma unroll
                for (int nt = 0; nt < 4; nt++)
                    mma16816(acc[mt][nt], ah[mt], &bh[nt * 2]);
        }
        st = (st + 1 == 3) ? 0 : st + 1;
    }
    __syncthreads();

    // ---- epilogue: bias+relu -> SMEM tile -> 2x2 pool -> outputs ----
    float* S = (float*)dsm;  // [128][132]
#pragma unroll
    for (int mt = 0; mt < 2; mt++)
#pragma unroll
        for (int half = 0; half < 2; half++) {
            const int rr = wm * 32 + mt * 16 + (lane >> 2) + half * 8;
#pragma unroll
            for (int nt = 0; nt < 4; nt++)
#pragma unroll
                for (int j = 0; j < 2; j++) {
                    const int ncl = wn * 32 + nt * 8 + (lane & 3) * 2 + j;
                    float v = acc[mt][nt][half * 2 + j] + bias[n0 + ncl];
                    S[rr * 132 + ncl] = v > 0.f ? v : 0.f;
                }
        }
    __syncthreads();

    constexpr int Wo = W / 2;
    constexpr int HWo = HW / 4;
    for (int idx = t; idx < 32 * 128; idx += 512) {
        const int pp = idx >> 7;
        const int cl = idx & 127;
        const int lpy = pp / Wo;
        const int lpx = pp % Wo;
        const int lm = lpy * 2 * W + lpx * 2;
        const int mm = m0 + lm;
        const int b = mm >> LHW;
        const int rem = mm & (HW - 1);
        const int y = rem >> LW, x = rem & (W - 1);
        const float* p = S + lm * 132 + cl;
        float v = fmaxf(fmaxf(p[0], p[132]), fmaxf(p[W * 132], p[(W + 1) * 132]));
        const int posn = (y >> 1) * Wo + (x >> 1);
        if (FEATS) {
            u16 hb, lb;
            split2(v, &hb, &lb);
            const int d = (n0 + cl) * HWo + posn;
            outf[(size_t)b * DFEAT + d] = v;
            outhi[(size_t)b * DFEAT + d] = hb;
            outlo[(size_t)b * DFEAT + d] = lb;
        } else {
            const size_t oi = ((size_t)b * HWo + posn) * CO + (n0 + cl);
            outhi[oi] = __half_as_ushort(__float2half_rn(v));
        }
    }
}

// ---- weight pack: OIHW -> [co][tap*CI+ci] fp16 ----------------------------
__global__ void wpack_kernel(const float* __restrict__ w,
                             u16* __restrict__ ohi, int CO, int CI)
{
    const int i = blockIdx.x * 256 + threadIdx.x;
    if (i >= CO * CI * 9) return;
    const int tap = i % 9;
    const int ci = (i / 9) % CI;
    const int co = i / (9 * CI);
    ohi[(size_t)co * CI * 9 + (size_t)tap * CI + ci] =
        __half_as_ushort(__float2half_rn(w[i]));
}

// -------------- grouped expert GEMM, fp16 2-term (fc1 / fc2) ---------------
// M-tile 32 x N-tile 128, chunk = 32 k. (Ahi+Alo)*Whi; W fp32 -> fp16 in-kernel.
#define ESTG 28672
#define EXP_DSM (3 * ESTG + 128)

template <int KDIM, int NDIM, bool RELU, bool GATHER, bool PACKOUT>
__global__ void __launch_bounds__(256, 2) expert_mma_kernel(
    const u16* __restrict__ Ahi, const u16* __restrict__ Alo,
    const float* __restrict__ Wt, const float* __restrict__ bias,
    u16* __restrict__ ohp, u16* __restrict__ olp, float* __restrict__ of)
{
    constexpr int NCH = KDIM / 32;
    const int e = blockIdx.y;
    const int cnt = g_cnt[e];
    const int off = g_off[e];
    const int rbase = blockIdx.z * 32;
    if (rbase >= cnt) return;
    const int n0 = blockIdx.x * 128;

    extern __shared__ __align__(1024) char dsm[];
    const uint32_t sb = smem_u32(dsm);
    const int t = threadIdx.x;
    const int lane = t & 31;
    const int wn = t >> 5;

    int* srcRow = (int*)(dsm + 3 * ESTG);
    if (t < 32) {
        int rr = rbase + t, sr = -1;
        if (rr < cnt) sr = GATHER ? (g_perm[off + rr] >> 1) : (off + rr);
        srcRow[t] = sr;
    }
    __syncthreads();

    const float* wbase = Wt + (size_t)e * KDIM * NDIM + n0;

    auto fill = [&](int st, int c) {
        const uint32_t stg = sb + (uint32_t)st * ESTG;
        const int kb = c * 32;
        if (t < 128) {
            const int rr = t >> 2, sg = t & 3;
            const int sr = srcRow[rr];
            const size_t ai = (sr < 0) ? 0 : ((size_t)sr * KDIM + kb + sg * 8);
            const uint32_t d = SWZ64((uint32_t)(rr * 64 + sg * 16));
            cp16(stg + d, Ahi + ai, sr < 0 ? 0 : 16);
            cp16(stg + 2048 + d, Alo + ai, sr < 0 ? 0 : 16);
        }
#pragma unroll
        for (int i = 0; i < 4; i++) {
            const int task = t + i * 256;
            const int k = task >> 5, sgw = task & 31;
            cp16(stg + 4096 + (uint32_t)(k * 512 + sgw * 16),
                 wbase + (size_t)(kb + k) * NDIM + sgw * 4, 16);
        }
    };

    float acc[2][2][4];
#pragma unroll
    for (int a = 0; a < 2; a++)
#pragma unroll
        for (int b = 0; b < 2; b++)
#pragma unroll
            for (int cj = 0; cj < 4; cj++) acc[a][b][cj] = 0.f;

    fill(0, 0);
    CP_COMMIT();
    fill(1, 1);
    CP_COMMIT();

    int st = 0;
    for (int c = 0; c < NCH; c++) {
        if (c + 1 < NCH) { CP_WAIT(1); } else { CP_WAIT(0); }
        __syncthreads();
        if (c + 2 < NCH) {
            fill(st >= 1 ? st - 1 : st + 2, c + 2);
            CP_COMMIT();
        }
        char* stgc = dsm + (size_t)st * ESTG;
        // ---- convert W fp32 tile -> Whi (SW64, n-major) ----
        {
            const int k = t >> 3, ng = t & 7;
#pragma unroll
            for (int j = 0; j < 4; j++) {
                const float4 w =
                    *(const float4*)(stgc + 4096 + k * 512 + ng * 64 + j * 16);
                const float vv[4] = {w.x, w.y, w.z, w.w};
#pragma unroll
                for (int jj = 0; jj < 4; jj++) {
                    const int n = ng * 16 + j * 4 + jj;
                    *(u16*)(stgc + 20480 + SWZ64((uint32_t)(n * 64 + 2 * k))) =
                        __half_as_ushort(__float2half_rn(vv[jj]));
                }
            }
        }
        __syncthreads();

        const uint32_t stg = sb + (uint32_t)st * ESTG;
#pragma unroll
        for (int ks = 0; ks < 2; ks++) {
            const int c0 = ks * 32;
            uint32_t ah[2][4], al[2][4], bh[4];
#pragma unroll
            for (int mt = 0; mt < 2; mt++) {
                const int row = mt * 16 + (lane & 15);
                const uint32_t o = SWZ64((uint32_t)(row * 64 + c0 + (lane >> 4) * 16));
                ldsm4(ah[mt][0], ah[mt][1], ah[mt][2], ah[mt][3], stg + o);
                ldsm4(al[mt][0], al[mt][1], al[mt][2], al[mt][3], stg + 2048 + o);
            }
            {
                const int row = wn * 16 + (lane & 7) + (lane >> 4) * 8;
                const uint32_t o =
                    SWZ64((uint32_t)(row * 64 + c0 + ((lane >> 3) & 1) * 16));
                ldsm4(bh[0], bh[1], bh[2], bh[3], stg + 20480 + o);
            }
#pragma unroll
            for (int mt = 0; mt < 2; mt++)
#pragma unroll
                for (int nt = 0; nt < 2; nt++) {
                    mma16816(acc[mt][nt], ah[mt], &bh[nt * 2]);
                    mma16816(acc[mt][nt], al[mt], &bh[nt * 2]);
                }
        }
        st = (st + 1 == 3) ? 0 : st + 1;
    }

    // ---- epilogue ----
#pragma unroll
    for (int mt = 0; mt < 2; mt++)
#pragma unroll
        for (int half = 0; half < 2; half++) {
            const int rr = rbase + mt * 16 + (lane >> 2) + half * 8;
            if (rr >= cnt) continue;
            const int gr = off + rr;
#pragma unroll
            for (int nt = 0; nt < 2; nt++)
#pragma unroll
                for (int j = 0; j < 2; j++) {
                    const int n = n0 + wn * 16 + nt * 8 + (lane & 3) * 2 + j;
                    float v = acc[mt][nt][half * 2 + j] + bias[(size_t)e * NDIM + n];
                    if (RELU) v = v > 0.f ? v : 0.f;
                    if (PACKOUT) {
                        u16 hb, lb;
                        split2(v, &hb, &lb);
                        ohp[(size_t)gr * NDIM + n] = hb;
                        olp[(size_t)gr * NDIM + n] = lb;
                    } else {
                        of[(size_t)gr * NDIM + n] = v;
                    }
                }
        }
}

// ---------- conv1: fp32 SIMT (CI=3) with fused pool+pack epilogue ----------
#define CONV1_DSM 68608

__global__ __launch_bounds__(256, 1) void conv1_kernel(
    const float* __restrict__ in, const float* __restrict__ wt,
    const float* __restrict__ bias, u16* __restrict__ outhi)
{
    constexpr int CI = 3, H = 64, W = 64;
    constexpr int BK = 27;
    constexpr int HW = H * W;

    extern __shared__ __align__(1024) char dsm[];
    float (*As)[132] = (float(*)[132])dsm;
    float (*Bs)[132] = (float(*)[132])(dsm + 14784);

    const int t = threadIdx.x;
    const int m0 = blockIdx.x * 128;
    const int tx = t & 15;
    const int ty = t >> 4;

    float acc[8][8];
#pragma unroll
    for (int i = 0; i < 8; i++)
#pragma unroll
        for (int j = 0; j < 8; j++) acc[i][j] = 0.f;

#pragma unroll
    for (int j = 0; j < 14; j++) {
        int e = j * 256 + t;
        if (e >= 27 * 128) break;
        int k = e >> 7;
        int p = e & 127;
        int ci = k / 9;
        int rc = k % 9;
        int s = m0 + p;
        int b = s / HW;
        int rr = s % HW;
        int y = rr / W, x = rr % W;
        int iy = y + rc / 3 - 1;
        int ix = x + rc % 3 - 1;
        float v = 0.f;
        if (iy >= 0 && iy < H && ix >= 0 && ix < W)
            v = in[((size_t)(b * CI + ci) * H + iy) * W + ix];
        As[k][p] = v;
    }
    if (t < 128) {
        const float* wp = wt + (size_t)t * 27;
#pragma unroll
        for (int k = 0; k < 27; k++) Bs[k][t] = wp[k];
    }
    __syncthreads();

#pragma unroll
    for (int kk = 0; kk < BK; kk++) {
        float a[8], bv[8];
        *(float4*)&a[0] = *(const float4*)&As[kk][tx * 8];
        *(float4*)&a[4] = *(const float4*)&As[kk][tx * 8 + 4];
        *(float4*)&bv[0] = *(const float4*)&Bs[kk][ty * 8];
        *(float4*)&bv[4] = *(const float4*)&Bs[kk][ty * 8 + 4];
#pragma unroll
        for (int i = 0; i < 8; i++)
#pragma unroll
            for (int j = 0; j < 8; j++) acc[i][j] += a[i] * bv[j];
    }
    __syncthreads();

    float* S = (float*)dsm;
#pragma unroll
    for (int i = 0; i < 8; i++) {
        const int r = tx * 8 + i;
#pragma unroll
        for (int j = 0; j < 8; j++) {
            const int cl = ty * 8 + j;
            float v = acc[i][j] + bias[cl];
            S[r * 132 + cl] = v > 0.f ? v : 0.f;
        }
    }
    __syncthreads();

    for (int idx = t; idx < 32 * 128; idx += 256) {
        const int pp = idx >> 7;
        const int cl = idx & 127;
        const int lm = pp * 2;
        const int m = m0 + lm;
        const int b = m >> 12;
        const int rem = m & 4095;
        const int y = rem >> 6, x = rem & 63;
        const float* p = S + lm * 132 + cl;
        float v = fmaxf(fmaxf(p[0], p[132]), fmaxf(p[64 * 132], p[65 * 132]));
        const size_t oi = ((size_t)b * 1024 + (y >> 1) * 32 + (x >> 1)) * 128 + cl;
        outhi[oi] = __half_as_ushort(__float2half_rn(v));
    }
}

// ----------------------------- gate logits ---------------------------------
__global__ void gate_logits_kernel(const float* __restrict__ feats,
                                   const float* __restrict__ wg)
{
    int t = blockIdx.x * blockDim.x + threadIdx.x;
    if (t >= BATCH * NEXP) return;
    int b = t >> 4, e = t & 15;
    const float* f = feats + (size_t)b * DFEAT;
    float s = 0.f;
    for (int d = 0; d < DFEAT; d++) s += f[d] * wg[d * NEXP + e];
    g_logits[t] = s;
}

// ------------------- top-2 + gate softmax + perm (fused) -------------------
__global__ void topk_perm_kernel()
{
    __shared__ int scnt[NEXP], soff[NEXP], scur[NEXP];
    const int t = threadIdx.x;  // 512
    if (t < BATCH) {
        const int b = t;
        float l[NEXP];
#pragma unroll
        for (int e = 0; e < NEXP; e++) l[e] = g_logits[b * NEXP + e];
        float b1v = -INFINITY, b2v = -INFINITY;
        int b1i = 0, b2i = 0;
#pragma unroll
        for (int e = 0; e < NEXP; e++) {
            float v = l[e];
            if (v > b1v) { b2v = b1v; b2i = b1i; b1v = v; b1i = e; }
            else if (v > b2v) { b2v = v; b2i = e; }
        }
        float e2 = expf(b2v - b1v);
        float denom = 1.f + e2;
        float gate1 = 1.f / denom;
        float gate2 = e2 / denom;
#pragma unroll
        for (int e = 0; e < NEXP; e++) g_gates[b * NEXP + e] = 0.f;
        g_gates[b * NEXP + b1i] = gate1;
        g_gates[b * NEXP + b2i] = gate2;
        g_pairE[2 * b] = b1i;     g_pairG[2 * b] = gate1;
        g_pairE[2 * b + 1] = b2i; g_pairG[2 * b + 1] = gate2;
    }
    if (t < NEXP) { scnt[t] = 0; scur[t] = 0; }
    __syncthreads();
    const int e = g_pairE[t];
    atomicAdd(&scnt[e], 1);
    __syncthreads();
    if (t == 0) {
        int o = 0;
        for (int i = 0; i < NEXP; i++) { soff[i] = o; o += scnt[i]; }
    }
    __syncthreads();
    const int slot = soff[e] + atomicAdd(&scur[e], 1);
    g_perm[slot] = t;
    if (t < NEXP) { g_cnt[t] = scnt[t]; g_off[t] = soff[t]; }
}

// -------------------------- zero output buffer -----------------------------
__global__ void zero_kernel(float* __restrict__ p, int n)
{
    int i = blockIdx.x * blockDim.x + threadIdx.x;
    if (i < n) p[i] = 0.f;
}

// ------------------- softmax over experts' logits + combine ----------------
__global__ void softmax_combine_kernel(float* __restrict__ y)
{
    const int gr = blockIdx.x;
    const int t = threadIdx.x;
    const int pair = g_perm[gr];
    const int token = pair >> 1;
    const float gate = g_pairG[pair];
    const float* row = g_o + (size_t)gr * OUTD;

    __shared__ float red[256];
    float m = -INFINITY;
    for (int j = t; j < OUTD; j += 256) m = fmaxf(m, row[j]);
    red[t] = m;
    __syncthreads();
    for (int s = 128; s > 0; s >>= 1) {
        if (t < s) red[t] = fmaxf(red[t], red[t + s]);
        __syncthreads();
    }
    const float M = red[0];
    __syncthreads();

    float s = 0.f;
    for (int j = t; j < OUTD; j += 256) s += expf(row[j] - M);
    red[t] = s;
    __syncthreads();
    for (int st = 128; st > 0; st >>= 1) {
        if (t < st) red[t] += red[t + st];
        __syncthreads();
    }
    const float scale = gate / red[0];

    for (int j = t; j < OUTD; j += 256)
        atomicAdd(&y[(size_t)token * OUTD + j], expf(row[j] - M) * scale);
}

// ------------------------------- aux loss ----------------------------------
__global__ void aux_kernel(float* __restrict__ out, int out_size)
{
    __shared__ float imp[NEXP], loadv[NEXP];
    int t = threadIdx.x;
    if (t < NEXP) {
        float s = 0.f, L = 0.f;
        for (int b = 0; b < BATCH; b++) {
            float gv = g_gates[b * NEXP + t];
            s += gv;
            if (gv > 0.f) L += 1.f;
        }
        imp[t] = s;
        loadv[t] = L;
    }
    __syncthreads();
    if (t == 0 && out_size > BATCH * OUTD) {
        float mi = 0.f, ml = 0.f;
        for (int e = 0; e < NEXP; e++) { mi += imp[e]; ml += loadv[e]; }
        mi /= NEXP; ml /= NEXP;
        float vi = 0.f, vl = 0.f;
        for (int e = 0; e < NEXP; e++) {
            float di = imp[e] - mi, dl = loadv[e] - ml;
            vi += di * di; vl += dl * dl;
        }
        vi /= NEXP; vl /= NEXP;
        out[BATCH * OUTD] =
            0.01f * (vi / (mi * mi + 1e-10f) + vl / (ml * ml + 1e-10f));
    }
}

// ------------------------------- launcher ----------------------------------
extern "C" void kernel_launch(void* const* d_in, const int* in_sizes, int n_in,
                              void* d_out, int out_size)
{
    (void)in_sizes; (void)n_in;
    const float* x   = (const float*)d_in[0];
    const float* cw1 = (const float*)d_in[1];
    const float* cb1 = (const float*)d_in[2];
    const float* cw2 = (const float*)d_in[3];
    const float* cb2 = (const float*)d_in[4];
    const float* cw3 = (const float*)d_in[5];
    const float* cb3 = (const float*)d_in[6];
    const float* cw4 = (const float*)d_in[7];
    const float* cb4 = (const float*)d_in[8];
    const float* cw5 = (const float*)d_in[9];
    const float* cb5 = (const float*)d_in[10];
    const float* w1  = (const float*)d_in[11];
    const float* b1  = (const float*)d_in[12];
    const float* w2  = (const float*)d_in[13];
    const float* b2  = (const float*)d_in[14];
    const float* wg  = (const float*)d_in[15];
    float* y = (float*)d_out;

    float *pool_s, *o_s;
    u16 *hiA, *hiB, *whi, *feathi, *featlo, *hhi, *hlo;
    cudaGetSymbolAddress((void**)&pool_s, g_pool);
    cudaGetSymbolAddress((void**)&o_s, g_o);
    cudaGetSymbolAddress((void**)&hiA, g_hiA);
    cudaGetSymbolAddress((void**)&hiB, g_hiB);
    cudaGetSymbolAddress((void**)&whi, g_whi);
    cudaGetSymbolAddress((void**)&feathi, g_feathi);
    cudaGetSymbolAddress((void**)&featlo, g_featlo);
    cudaGetSymbolAddress((void**)&hhi, g_hhi);
    cudaGetSymbolAddress((void**)&hlo, g_hlo);

    cudaFuncSetAttribute(conv1_kernel,
                         cudaFuncAttributeMaxDynamicSharedMemorySize, CONV1_DSM);
    cudaFuncSetAttribute(conv_mma_kernel<128, 32, 32, 256, false>,
                         cudaFuncAttributeMaxDynamicSharedMemorySize, CONV_DSM);
    cudaFuncSetAttribute(conv_mma_kernel<256, 16, 16, 256, false>,
                         cudaFuncAttributeMaxDynamicSharedMemorySize, CONV_DSM);
    cudaFuncSetAttribute(conv_mma_kernel<256, 8, 8, 512, false>,
                         cudaFuncAttributeMaxDynamicSharedMemorySize, CONV_DSM);
    cudaFuncSetAttribute(conv_mma_kernel<512, 4, 4, 512, true>,
                         cudaFuncAttributeMaxDynamicSharedMemorySize, CONV_DSM);
    cudaFuncSetAttribute(expert_mma_kernel<DFEAT, HID, true, true, true>,
                         cudaFuncAttributeMaxDynamicSharedMemorySize, EXP_DSM);
    cudaFuncSetAttribute(expert_mma_kernel<HID, OUTD, false, false, false>,
                         cudaFuncAttributeMaxDynamicSharedMemorySize, EXP_DSM);

    // weight offsets within g_whi (elements)
    const size_t OFF2 = 0, OFF3 = 294912, OFF4 = 884736, OFF5 = 2064384;

    // ---- all conv weight packs upfront ----
    wpack_kernel<<<(256 * 128 * 9 + 255) / 256, 256>>>(cw2, whi + OFF2, 256, 128);
    wpack_kernel<<<(256 * 256 * 9 + 255) / 256, 256>>>(cw3, whi + OFF3, 256, 256);
    wpack_kernel<<<(512 * 256 * 9 + 255) / 256, 256>>>(cw4, whi + OFF4, 512, 256);
    wpack_kernel<<<(512 * 512 * 9 + 255) / 256, 256>>>(cw5, whi + OFF5, 512, 512);

    // ---- conv stack ----
    conv1_kernel<<<8192, 256, CONV1_DSM>>>(x, cw1, cb1, hiA);
    conv_mma_kernel<128, 32, 32, 256, false><<<dim3(2048, 2), 512, CONV_DSM>>>(
        hiA, whi + OFF2, cb2, hiB, nullptr, nullptr);
    conv_mma_kernel<256, 16, 16, 256, false><<<dim3(512, 2), 512, CONV_DSM>>>(
        hiB, whi + OFF3, cb3, hiA, nullptr, nullptr);
    conv_mma_kernel<256, 8, 8, 512, false><<<dim3(128, 4), 512, CONV_DSM>>>(
        hiA, whi + OFF4, cb4, hiB, nullptr, nullptr);
    conv_mma_kernel<512, 4, 4, 512, true><<<dim3(32, 4), 512, CONV_DSM>>>(
        hiB, whi + OFF5, cb5, feathi, featlo, pool_s);

    // ---- gating ----
    gate_logits_kernel<<<NEXP, 256>>>(pool_s, wg);
    topk_perm_kernel<<<1, 512>>>();

    // ---- sparse expert MLPs (fp16 2-term mma) ----
    expert_mma_kernel<DFEAT, HID, true, true, true>
        <<<dim3(HID / 128, NEXP, 8), 256, EXP_DSM>>>(feathi, featlo, w1, b1,
                                                     hhi, hlo, nullptr);
    expert_mma_kernel<HID, OUTD, false, false, false>
        <<<dim3(OUTD / 128, NEXP, 8), 256, EXP_DSM>>>(hhi, hlo, w2, b2,
                                                      nullptr, nullptr, o_s);

    // ---- combine + aux ----
    zero_kernel<<<(out_size + 255) / 256, 256>>>(y, out_size);
    softmax_combine_kernel<<<NPAIR, 256>>>(y);
    aux_kernel<<<1, 256>>>(y, out_size);
}

// round 10
// speedup vs baseline: 1.9017x; 1.0695x over previous
#include <cuda_runtime.h>
#include <cuda_fp16.h>
#include <math.h>
#include <stdint.h>

// ---------------------------------------------------------------------------
// ToyMoE: conv stack (5x conv3x3+relu+maxpool2) -> top-2 gating (eval)
//         -> sparse top-2 expert MLPs -> softmax -> gated combine + aux loss
// ALL convs + experts on fp16 mma.sync. conv2-5: 1-pass fp16.
// conv1: K=27 (pad 32) im2col mma. experts: fp16 2-term (Ahi+Alo)*Whi.
// ---------------------------------------------------------------------------

#define BATCH 256
#define DFEAT 2048
#define HID 4096
#define OUTD 1024
#define NEXP 16
#define NPAIR (BATCH * 2)

typedef unsigned short u16;

template <int X> struct LG { static constexpr int v = 1 + LG<X / 2>::v; };
template <> struct LG<1> { static constexpr int v = 0; };

// ------------------------- scratch (device globals) ------------------------
__device__ u16   g_hiA[(size_t)256 * 1024 * 128];  // hi acts (L1/L3 out)
__device__ u16   g_hiB[(size_t)256 * 256 * 256];   // hi acts (L2/L4 out)
__device__ u16   g_whi[4423680];                   // conv weights fp16
__device__ float g_pool[BATCH * DFEAT];            // feats fp32 (gating)
__device__ u16   g_feathi[BATCH * DFEAT];
__device__ u16   g_featlo[BATCH * DFEAT];
__device__ u16   g_hhi[(size_t)NPAIR * HID];
__device__ u16   g_hlo[(size_t)NPAIR * HID];
__device__ float g_logits[BATCH * NEXP];
__device__ float g_gates[BATCH * NEXP];
__device__ int   g_pairE[NPAIR];
__device__ float g_pairG[NPAIR];
__device__ int   g_perm[NPAIR];
__device__ int   g_cnt[NEXP];
__device__ int   g_off[NEXP];
__device__ float g_o[(size_t)NPAIR * OUTD];

// ------------------------------ PTX helpers --------------------------------
__device__ __forceinline__ uint32_t smem_u32(const void* p) {
    uint32_t a;
    asm("{ .reg .u64 t; cvta.to.shared.u64 t, %1; cvt.u32.u64 %0, t; }"
        : "=r"(a) : "l"(p));
    return a;
}

#define SWZ64(x) ((x) ^ (((x) >> 3) & 0x30))

__device__ __forceinline__ void cp16(uint32_t dst, const void* src, int sz) {
    asm volatile("cp.async.cg.shared.global [%0], [%1], 16, %2;"
                 :: "r"(dst), "l"(src), "r"(sz) : "memory");
}
#define CP_COMMIT() asm volatile("cp.async.commit_group;" ::: "memory")
#define CP_WAIT(n)  asm volatile("cp.async.wait_group %0;" :: "n"(n) : "memory")

__device__ __forceinline__ void ldsm4(uint32_t& r0, uint32_t& r1,
                                      uint32_t& r2, uint32_t& r3, uint32_t a) {
    asm volatile("ldmatrix.sync.aligned.m8n8.x4.shared.b16 {%0,%1,%2,%3}, [%4];"
                 : "=r"(r0), "=r"(r1), "=r"(r2), "=r"(r3) : "r"(a));
}
__device__ __forceinline__ void mma16816(float* d, const uint32_t* a,
                                         const uint32_t* b) {
    asm volatile(
        "mma.sync.aligned.m16n8k16.row.col.f32.f16.f16.f32 "
        "{%0,%1,%2,%3}, {%4,%5,%6,%7}, {%8,%9}, {%0,%1,%2,%3};"
        : "+f"(d[0]), "+f"(d[1]), "+f"(d[2]), "+f"(d[3])
        : "r"(a[0]), "r"(a[1]), "r"(a[2]), "r"(a[3]), "r"(b[0]), "r"(b[1]));
}
__device__ __forceinline__ void split2(float v, u16* hi, u16* lo) {
    __half h = __float2half_rn(v);
    __half l = __float2half_rn(v - __half2float(h));
    *hi = __half_as_ushort(h);
    *lo = __half_as_ushort(l);
}

// --------------------- fp16 mma.sync conv3x3 (SAME, relu, fused pool) ------
// PURE fp16, 1 pass per 32-channel tap chunk: Ahi*Whi.
// Stage 16KB = Ahi(8K) Whi(8K), SW64. 3 stages, 1 sync/chunk.
#define STG 16384
#define CONV_DSM 67584   // max(3*STG=49152, epilogue 128*132*4=67584)

template <int CI, int H, int W, int CO, bool FEATS>
__global__ void __launch_bounds__(512, 1) conv_mma_kernel(
    const u16* __restrict__ inhi, const u16* __restrict__ whi,
    const float* __restrict__ bias,
    u16* __restrict__ outhi, u16* __restrict__ outlo, float* __restrict__ outf)
{
    constexpr int HW = H * W;
    constexpr int LHW = LG<HW>::v;
    constexpr int LW = LG<W>::v;
    constexpr int CPT = CI / 32;
    constexpr int NCH = 9 * CPT;
    constexpr int WROW = 9 * CI;

    extern __shared__ __align__(1024) char dsm[];
    const uint32_t sb = smem_u32(dsm);
    const int t = threadIdx.x;
    const int lane = t & 31;
    const int wid = t >> 5;
    const int wm = wid & 3, wn = wid >> 2;     // 4x4 warp grid, 32x32 tiles
    const int m0 = blockIdx.x * 128, n0 = blockIdx.y * 128;

    const int r = t >> 2, sg = t & 3;
    const int m = m0 + r;
    const int bI = m >> LHW;
    const int pos = m & (HW - 1);
    const int yy = pos >> LW, xx = pos & (W - 1);
    const size_t wro = (size_t)(n0 + r) * WROW + sg * 8;
    const uint32_t dstA = SWZ64((uint32_t)(r * 64 + sg * 16));

    auto fill = [&](int st, int c) {
        const uint32_t stg = sb + (uint32_t)st * STG;
        const int tap = c / CPT;
        const int cib = (c % CPT) * 32;
        const int dy = tap / 3 - 1, dx = tap % 3 - 1;
        const int iy = yy + dy, ix = xx + dx;
        const bool ok = (iy >= 0 && iy < H && ix >= 0 && ix < W);
        const size_t ai =
            (((size_t)bI * H + (ok ? iy : 0)) * W + (ok ? ix : 0)) * CI + cib + sg * 8;
        cp16(stg + dstA, inhi + ai, ok ? 16 : 0);
        cp16(stg + 8192 + dstA, whi + wro + tap * CI + cib, 16);
    };

    float acc[2][4][4];
#pragma unroll
    for (int a = 0; a < 2; a++)
#pragma unroll
        for (int b = 0; b < 4; b++)
#pragma unroll
            for (int cj = 0; cj < 4; cj++) acc[a][b][cj] = 0.f;

    fill(0, 0);
    CP_COMMIT();
    fill(1, 1);
    CP_COMMIT();

    int st = 0;
    for (int c = 0; c < NCH; c++) {
        if (c + 1 < NCH) { CP_WAIT(1); } else { CP_WAIT(0); }
        __syncthreads();
        if (c + 2 < NCH) {
            fill(st >= 1 ? st - 1 : st + 2, c + 2);
            CP_COMMIT();
        }
        const uint32_t stg = sb + (uint32_t)st * STG;
#pragma unroll
        for (int ks = 0; ks < 2; ks++) {
            const int c0 = ks * 32;
            uint32_t ah[2][4], bh[8];
#pragma unroll
            for (int mt = 0; mt < 2; mt++) {
                const int row = wm * 32 + mt * 16 + (lane & 15);
                const uint32_t off = SWZ64((uint32_t)(row * 64 + c0 + (lane >> 4) * 16));
                ldsm4(ah[mt][0], ah[mt][1], ah[mt][2], ah[mt][3], stg + off);
            }
#pragma unroll
            for (int p = 0; p < 2; p++) {
                const int row = wn * 32 + p * 16 + (lane & 7) + (lane >> 4) * 8;
                const uint32_t off =
                    SWZ64((uint32_t)(row * 64 + c0 + ((lane >> 3) & 1) * 16));
                ldsm4(bh[p * 4], bh[p * 4 + 1], bh[p * 4 + 2], bh[p * 4 + 3],
                      stg + 8192 + off);
            }
#pragma unroll
            for (int mt = 0; mt < 2; mt++)
#pragma unroll
                for (int nt = 0; nt < 4; nt++)
                    mma16816(acc[mt][nt], ah[mt], &bh[nt * 2]);
        }
        st = (st + 1 == 3) ? 0 : st + 1;
    }
    __syncthreads();

    // ---- epilogue: bias+relu -> SMEM tile -> 2x2 pool -> outputs ----
    float* S = (float*)dsm;  // [128][132]
#pragma unroll
    for (int mt = 0; mt < 2; mt++)
#pragma unroll
        for (int half = 0; half < 2; half++) {
            const int rr = wm * 32 + mt * 16 + (lane >> 2) + half * 8;
#pragma unroll
            for (int nt = 0; nt < 4; nt++)
#pragma unroll
                for (int j = 0; j < 2; j++) {
                    const int ncl = wn * 32 + nt * 8 + (lane & 3) * 2 + j;
                    float v = acc[mt][nt][half * 2 + j] + bias[n0 + ncl];
                    S[rr * 132 + ncl] = v > 0.f ? v : 0.f;
                }
        }
    __syncthreads();

    constexpr int Wo = W / 2;
    constexpr int HWo = HW / 4;
    for (int idx = t; idx < 32 * 128; idx += 512) {
        const int pp = idx >> 7;
        const int cl = idx & 127;
        const int lpy = pp / Wo;
        const int lpx = pp % Wo;
        const int lm = lpy * 2 * W + lpx * 2;
        const int mm = m0 + lm;
        const int b = mm >> LHW;
        const int rem = mm & (HW - 1);
        const int y = rem >> LW, x = rem & (W - 1);
        const float* p = S + lm * 132 + cl;
        float v = fmaxf(fmaxf(p[0], p[132]), fmaxf(p[W * 132], p[(W + 1) * 132]));
        const int posn = (y >> 1) * Wo + (x >> 1);
        if (FEATS) {
            u16 hb, lb;
            split2(v, &hb, &lb);
            const int d = (n0 + cl) * HWo + posn;
            outf[(size_t)b * DFEAT + d] = v;
            outhi[(size_t)b * DFEAT + d] = hb;
            outlo[(size_t)b * DFEAT + d] = lb;
        } else {
            const size_t oi = ((size_t)b * HWo + posn) * CO + (n0 + cl);
            outhi[oi] = __half_as_ushort(__float2half_rn(v));
        }
    }
}

// ---------- conv1: fp16 mma (K=27 pad 32, ci-major k), fused pool ----------
// A: 128x32 fp16 im2col (scalar gather + cvt). B: 128 co x 27 contiguous wt.
// Single chunk. Epilogue identical to conv_mma (pool -> fp16 hi NHWC).
#define CONV1_DSM 67584

__global__ void __launch_bounds__(512, 1) conv1_mma_kernel(
    const float* __restrict__ in, const float* __restrict__ wt,
    const float* __restrict__ bias, u16* __restrict__ outhi)
{
    constexpr int H = 64, W = 64, HW = 4096;

    extern __shared__ __align__(1024) char dsm[];
    const uint32_t sb = smem_u32(dsm);
    const int t = threadIdx.x;
    const int lane = t & 31;
    const int wid = t >> 5;
    const int wm = wid & 3, wn = wid >> 2;
    const int m0 = blockIdx.x * 128;

    // ---- fill A: r = t>>2 rows, sg = t&3 -> k = sg*8..sg*8+7 (k = ci*9+tap)
    {
        const int r = t >> 2, sg = t & 3;
        const int m = m0 + r;
        const int bI = m >> 12;
        const int pos = m & 4095;
        const int yy = pos >> 6, xx = pos & 63;
        u16 vals[8];
#pragma unroll
        for (int j = 0; j < 8; j++) {
            const int k = sg * 8 + j;
            float v = 0.f;
            if (k < 27) {
                const int ci = k / 9;
                const int tap = k - ci * 9;
                const int iy = yy + tap / 3 - 1;
                const int ix = xx + tap % 3 - 1;
                if (iy >= 0 && iy < H && ix >= 0 && ix < W)
                    v = in[((size_t)(bI * 3 + ci) * H + iy) * W + ix];
            }
            vals[j] = __half_as_ushort(__float2half_rn(v));
        }
        *(uint4*)(dsm + SWZ64((uint32_t)(r * 64 + sg * 16))) = *(uint4*)vals;
    }
    // ---- fill B: t<128 -> co = t, 27 contiguous weights ----
    if (t < 128) {
        const float* wp = wt + (size_t)t * 27;
        u16 vals[32];
#pragma unroll
        for (int k = 0; k < 27; k++)
            vals[k] = __half_as_ushort(__float2half_rn(wp[k]));
#pragma unroll
        for (int k = 27; k < 32; k++) vals[k] = 0;
#pragma unroll
        for (int sg = 0; sg < 4; sg++)
            *(uint4*)(dsm + 8192 + SWZ64((uint32_t)(t * 64 + sg * 16))) =
                *(uint4*)&vals[sg * 8];
    }
    __syncthreads();

    float acc[2][4][4];
#pragma unroll
    for (int a = 0; a < 2; a++)
#pragma unroll
        for (int b = 0; b < 4; b++)
#pragma unroll
            for (int cj = 0; cj < 4; cj++) acc[a][b][cj] = 0.f;

#pragma unroll
    for (int ks = 0; ks < 2; ks++) {
        const int c0 = ks * 32;
        uint32_t ah[2][4], bh[8];
#pragma unroll
        for (int mt = 0; mt < 2; mt++) {
            const int row = wm * 32 + mt * 16 + (lane & 15);
            const uint32_t off = SWZ64((uint32_t)(row * 64 + c0 + (lane >> 4) * 16));
            ldsm4(ah[mt][0], ah[mt][1], ah[mt][2], ah[mt][3], sb + off);
        }
#pragma unroll
        for (int p = 0; p < 2; p++) {
            const int row = wn * 32 + p * 16 + (lane & 7) + (lane >> 4) * 8;
            const uint32_t off =
                SWZ64((uint32_t)(row * 64 + c0 + ((lane >> 3) & 1) * 16));
            ldsm4(bh[p * 4], bh[p * 4 + 1], bh[p * 4 + 2], bh[p * 4 + 3],
                  sb + 8192 + off);
        }
#pragma unroll
        for (int mt = 0; mt < 2; mt++)
#pragma unroll
            for (int nt = 0; nt < 4; nt++)
                mma16816(acc[mt][nt], ah[mt], &bh[nt * 2]);
    }
    __syncthreads();

    // ---- epilogue: bias+relu -> SMEM -> 2x2 pool -> fp16 hi NHWC ----
    float* S = (float*)dsm;  // [128][132]
#pragma unroll
    for (int mt = 0; mt < 2; mt++)
#pragma unroll
        for (int half = 0; half < 2; half++) {
            const int rr = wm * 32 + mt * 16 + (lane >> 2) + half * 8;
#pragma unroll
            for (int nt = 0; nt < 4; nt++)
#pragma unroll
                for (int j = 0; j < 2; j++) {
                    const int ncl = wn * 32 + nt * 8 + (lane & 3) * 2 + j;
                    float v = acc[mt][nt][half * 2 + j] + bias[ncl];
                    S[rr * 132 + ncl] = v > 0.f ? v : 0.f;
                }
        }
    __syncthreads();

    for (int idx = t; idx < 32 * 128; idx += 512) {
        const int pp = idx >> 7;   // pooled x 0..31
        const int cl = idx & 127;
        const int lm = pp * 2;
        const int mm = m0 + lm;
        const int b = mm >> 12;
        const int rem = mm & 4095;
        const int y = rem >> 6, x = rem & 63;
        const float* p = S + lm * 132 + cl;
        float v = fmaxf(fmaxf(p[0], p[132]), fmaxf(p[64 * 132], p[65 * 132]));
        const size_t oi = ((size_t)b * 1024 + (y >> 1) * 32 + (x >> 1)) * 128 + cl;
        outhi[oi] = __half_as_ushort(__float2half_rn(v));
    }
}

// ---- weight pack: OIHW -> [co][tap*CI+ci] fp16 ----------------------------
__global__ void wpack_kernel(const float* __restrict__ w,
                             u16* __restrict__ ohi, int CO, int CI)
{
    const int i = blockIdx.x * 256 + threadIdx.x;
    if (i >= CO * CI * 9) return;
    const int tap = i % 9;
    const int ci = (i / 9) % CI;
    const int co = i / (9 * CI);
    ohi[(size_t)co * CI * 9 + (size_t)tap * CI + ci] =
        __half_as_ushort(__float2half_rn(w[i]));
}

// -------------- grouped expert GEMM, fp16 2-term (fc1 / fc2) ---------------
#define ESTG 28672
#define EXP_DSM (3 * ESTG + 128)

template <int KDIM, int NDIM, bool RELU, bool GATHER, bool PACKOUT>
__global__ void __launch_bounds__(256, 2) expert_mma_kernel(
    const u16* __restrict__ Ahi, const u16* __restrict__ Alo,
    const float* __restrict__ Wt, const float* __restrict__ bias,
    u16* __restrict__ ohp, u16* __restrict__ olp, float* __restrict__ of)
{
    constexpr int NCH = KDIM / 32;
    const int e = blockIdx.y;
    const int cnt = g_cnt[e];
    const int off = g_off[e];
    const int rbase = blockIdx.z * 32;
    if (rbase >= cnt) return;
    const int n0 = blockIdx.x * 128;

    extern __shared__ __align__(1024) char dsm[];
    const uint32_t sb = smem_u32(dsm);
    const int t = threadIdx.x;
    const int lane = t & 31;
    const int wn = t >> 5;

    int* srcRow = (int*)(dsm + 3 * ESTG);
    if (t < 32) {
        int rr = rbase + t, sr = -1;
        if (rr < cnt) sr = GATHER ? (g_perm[off + rr] >> 1) : (off + rr);
        srcRow[t] = sr;
    }
    __syncthreads();

    const float* wbase = Wt + (size_t)e * KDIM * NDIM + n0;

    auto fill = [&](int st, int c) {
        const uint32_t stg = sb + (uint32_t)st * ESTG;
        const int kb = c * 32;
        if (t < 128) {
            const int rr = t >> 2, sg = t & 3;
            const int sr = srcRow[rr];
            const size_t ai = (sr < 0) ? 0 : ((size_t)sr * KDIM + kb + sg * 8);
            const uint32_t d = SWZ64((uint32_t)(rr * 64 + sg * 16));
            cp16(stg + d, Ahi + ai, sr < 0 ? 0 : 16);
            cp16(stg + 2048 + d, Alo + ai, sr < 0 ? 0 : 16);
        }
#pragma unroll
        for (int i = 0; i < 4; i++) {
            const int task = t + i * 256;
            const int k = task >> 5, sgw = task & 31;
            cp16(stg + 4096 + (uint32_t)(k * 512 + sgw * 16),
                 wbase + (size_t)(kb + k) * NDIM + sgw * 4, 16);
        }
    };

    float acc[2][2][4];
#pragma unroll
    for (int a = 0; a < 2; a++)
#pragma unroll
        for (int b = 0; b < 2; b++)
#pragma unroll
            for (int cj = 0; cj < 4; cj++) acc[a][b][cj] = 0.f;

    fill(0, 0);
    CP_COMMIT();
    fill(1, 1);
    CP_COMMIT();

    int st = 0;
    for (int c = 0; c < NCH; c++) {
        if (c + 1 < NCH) { CP_WAIT(1); } else { CP_WAIT(0); }
        __syncthreads();
        if (c + 2 < NCH) {
            fill(st >= 1 ? st - 1 : st + 2, c + 2);
            CP_COMMIT();
        }
        char* stgc = dsm + (size_t)st * ESTG;
        // ---- convert W fp32 tile -> Whi (SW64, n-major) ----
        {
            const int k = t >> 3, ng = t & 7;
#pragma unroll
            for (int j = 0; j < 4; j++) {
                const float4 w =
                    *(const float4*)(stgc + 4096 + k * 512 + ng * 64 + j * 16);
                const float vv[4] = {w.x, w.y, w.z, w.w};
#pragma unroll
                for (int jj = 0; jj < 4; jj++) {
                    const int n = ng * 16 + j * 4 + jj;
                    *(u16*)(stgc + 20480 + SWZ64((uint32_t)(n * 64 + 2 * k))) =
                        __half_as_ushort(__float2half_rn(vv[jj]));
                }
            }
        }
        __syncthreads();

        const uint32_t stg = sb + (uint32_t)st * ESTG;
#pragma unroll
        for (int ks = 0; ks < 2; ks++) {
            const int c0 = ks * 32;
            uint32_t ah[2][4], al[2][4], bh[4];
#pragma unroll
            for (int mt = 0; mt < 2; mt++) {
                const int row = mt * 16 + (lane & 15);
                const uint32_t o = SWZ64((uint32_t)(row * 64 + c0 + (lane >> 4) * 16));
                ldsm4(ah[mt][0], ah[mt][1], ah[mt][2], ah[mt][3], stg + o);
                ldsm4(al[mt][0], al[mt][1], al[mt][2], al[mt][3], stg + 2048 + o);
            }
            {
                const int row = wn * 16 + (lane & 7) + (lane >> 4) * 8;
                const uint32_t o =
                    SWZ64((uint32_t)(row * 64 + c0 + ((lane >> 3) & 1) * 16));
                ldsm4(bh[0], bh[1], bh[2], bh[3], stg + 20480 + o);
            }
#pragma unroll
            for (int mt = 0; mt < 2; mt++)
#pragma unroll
                for (int nt = 0; nt < 2; nt++) {
                    mma16816(acc[mt][nt], ah[mt], &bh[nt * 2]);
                    mma16816(acc[mt][nt], al[mt], &bh[nt * 2]);
                }
        }
        st = (st + 1 == 3) ? 0 : st + 1;
    }

    // ---- epilogue ----
#pragma unroll
    for (int mt = 0; mt < 2; mt++)
#pragma unroll
        for (int half = 0; half < 2; half++) {
            const int rr = rbase + mt * 16 + (lane >> 2) + half * 8;
            if (rr >= cnt) continue;
            const int gr = off + rr;
#pragma unroll
            for (int nt = 0; nt < 2; nt++)
#pragma unroll
                for (int j = 0; j < 2; j++) {
                    const int n = n0 + wn * 16 + nt * 8 + (lane & 3) * 2 + j;
                    float v = acc[mt][nt][half * 2 + j] + bias[(size_t)e * NDIM + n];
                    if (RELU) v = v > 0.f ? v : 0.f;
                    if (PACKOUT) {
                        u16 hb, lb;
                        split2(v, &hb, &lb);
                        ohp[(size_t)gr * NDIM + n] = hb;
                        olp[(size_t)gr * NDIM + n] = lb;
                    } else {
                        of[(size_t)gr * NDIM + n] = v;
                    }
                }
        }
}

// ----------------------------- gate logits ---------------------------------
__global__ void gate_logits_kernel(const float* __restrict__ feats,
                                   const float* __restrict__ wg)
{
    int t = blockIdx.x * blockDim.x + threadIdx.x;
    if (t >= BATCH * NEXP) return;
    int b = t >> 4, e = t & 15;
    const float* f = feats + (size_t)b * DFEAT;
    float s = 0.f;
    for (int d = 0; d < DFEAT; d++) s += f[d] * wg[d * NEXP + e];
    g_logits[t] = s;
}

// ------------------- top-2 + gate softmax + perm (fused) -------------------
__global__ void topk_perm_kernel()
{
    __shared__ int scnt[NEXP], soff[NEXP], scur[NEXP];
    const int t = threadIdx.x;  // 512
    if (t < BATCH) {
        const int b = t;
        float l[NEXP];
#pragma unroll
        for (int e = 0; e < NEXP; e++) l[e] = g_logits[b * NEXP + e];
        float b1v = -INFINITY, b2v = -INFINITY;
        int b1i = 0, b2i = 0;
#pragma unroll
        for (int e = 0; e < NEXP; e++) {
            float v = l[e];
            if (v > b1v) { b2v = b1v; b2i = b1i; b1v = v; b1i = e; }
            else if (v > b2v) { b2v = v; b2i = e; }
        }
        float e2 = expf(b2v - b1v);
        float denom = 1.f + e2;
        float gate1 = 1.f / denom;
        float gate2 = e2 / denom;
#pragma unroll
        for (int e = 0; e < NEXP; e++) g_gates[b * NEXP + e] = 0.f;
        g_gates[b * NEXP + b1i] = gate1;
        g_gates[b * NEXP + b2i] = gate2;
        g_pairE[2 * b] = b1i;     g_pairG[2 * b] = gate1;
        g_pairE[2 * b + 1] = b2i; g_pairG[2 * b + 1] = gate2;
    }
    if (t < NEXP) { scnt[t] = 0; scur[t] = 0; }
    __syncthreads();
    const int e = g_pairE[t];
    atomicAdd(&scnt[e], 1);
    __syncthreads();
    if (t == 0) {
        int o = 0;
        for (int i = 0; i < NEXP; i++) { soff[i] = o; o += scnt[i]; }
    }
    __syncthreads();
    const int slot = soff[e] + atomicAdd(&scur[e], 1);
    g_perm[slot] = t;
    if (t < NEXP) { g_cnt[t] = scnt[t]; g_off[t] = soff[t]; }
}

// -------------------------- zero output buffer -----------------------------
__global__ void zero_kernel(float* __restrict__ p, int n)
{
    int i = blockIdx.x * blockDim.x + threadIdx.x;
    if (i < n) p[i] = 0.f;
}

// ------------------- softmax over experts' logits + combine ----------------
__global__ void softmax_combine_kernel(float* __restrict__ y)
{
    const int gr = blockIdx.x;
    const int t = threadIdx.x;
    const int pair = g_perm[gr];
    const int token = pair >> 1;
    const float gate = g_pairG[pair];
    const float* row = g_o + (size_t)gr * OUTD;

    __shared__ float red[256];
    float m = -INFINITY;
    for (int j = t; j < OUTD; j += 256) m = fmaxf(m, row[j]);
    red[t] = m;
    __syncthreads();
    for (int s = 128; s > 0; s >>= 1) {
        if (t < s) red[t] = fmaxf(red[t], red[t + s]);
        __syncthreads();
    }
    const float M = red[0];
    __syncthreads();

    float s = 0.f;
    for (int j = t; j < OUTD; j += 256) s += expf(row[j] - M);
    red[t] = s;
    __syncthreads();
    for (int st = 128; st > 0; st >>= 1) {
        if (t < st) red[t] += red[t + st];
        __syncthreads();
    }
    const float scale = gate / red[0];

    for (int j = t; j < OUTD; j += 256)
        atomicAdd(&y[(size_t)token * OUTD + j], expf(row[j] - M) * scale);
}

// ------------------------------- aux loss ----------------------------------
__global__ void aux_kernel(float* __restrict__ out, int out_size)
{
    __shared__ float imp[NEXP], loadv[NEXP];
    int t = threadIdx.x;
    if (t < NEXP) {
        float s = 0.f, L = 0.f;
        for (int b = 0; b < BATCH; b++) {
            float gv = g_gates[b * NEXP + t];
            s += gv;
            if (gv > 0.f) L += 1.f;
        }
        imp[t] = s;
        loadv[t] = L;
    }
    __syncthreads();
    if (t == 0 && out_size > BATCH * OUTD) {
        float mi = 0.f, ml = 0.f;
        for (int e = 0; e < NEXP; e++) { mi += imp[e]; ml += loadv[e]; }
        mi /= NEXP; ml /= NEXP;
        float vi = 0.f, vl = 0.f;
        for (int e = 0; e < NEXP; e++) {
            float di = imp[e] - mi, dl = loadv[e] - ml;
            vi += di * di; vl += dl * dl;
        }
        vi /= NEXP; vl /= NEXP;
        out[BATCH * OUTD] =
            0.01f * (vi / (mi * mi + 1e-10f) + vl / (ml * ml + 1e-10f));
    }
}

// ------------------------------- launcher ----------------------------------
extern "C" void kernel_launch(void* const* d_in, const int* in_sizes, int n_in,
                              void* d_out, int out_size)
{
    (void)in_sizes; (void)n_in;
    const float* x   = (const float*)d_in[0];
    const float* cw1 = (const float*)d_in[1];
    const float* cb1 = (const float*)d_in[2];
    const float* cw2 = (const float*)d_in[3];
    const float* cb2 = (const float*)d_in[4];
    const float* cw3 = (const float*)d_in[5];
    const float* cb3 = (const float*)d_in[6];
    const float* cw4 = (const float*)d_in[7];
    const float* cb4 = (const float*)d_in[8];
    const float* cw5 = (const float*)d_in[9];
    const float* cb5 = (const float*)d_in[10];
    const float* w1  = (const float*)d_in[11];
    const float* b1  = (const float*)d_in[12];
    const float* w2  = (const float*)d_in[13];
    const float* b2  = (const float*)d_in[14];
    const float* wg  = (const float*)d_in[15];
    float* y = (float*)d_out;

    float *pool_s, *o_s;
    u16 *hiA, *hiB, *whi, *feathi, *featlo, *hhi, *hlo;
    cudaGetSymbolAddress((void**)&pool_s, g_pool);
    cudaGetSymbolAddress((void**)&o_s, g_o);
    cudaGetSymbolAddress((void**)&hiA, g_hiA);
    cudaGetSymbolAddress((void**)&hiB, g_hiB);
    cudaGetSymbolAddress((void**)&whi, g_whi);
    cudaGetSymbolAddress((void**)&feathi, g_feathi);
    cudaGetSymbolAddress((void**)&featlo, g_featlo);
    cudaGetSymbolAddress((void**)&hhi, g_hhi);
    cudaGetSymbolAddress((void**)&hlo, g_hlo);

    cudaFuncSetAttribute(conv1_mma_kernel,
                         cudaFuncAttributeMaxDynamicSharedMemorySize, CONV1_DSM);
    cudaFuncSetAttribute(conv_mma_kernel<128, 32, 32, 256, false>,
                         cudaFuncAttributeMaxDynamicSharedMemorySize, CONV_DSM);
    cudaFuncSetAttribute(conv_mma_kernel<256, 16, 16, 256, false>,
                         cudaFuncAttributeMaxDynamicSharedMemorySize, CONV_DSM);
    cudaFuncSetAttribute(conv_mma_kernel<256, 8, 8, 512, false>,
                         cudaFuncAttributeMaxDynamicSharedMemorySize, CONV_DSM);
    cudaFuncSetAttribute(conv_mma_kernel<512, 4, 4, 512, true>,
                         cudaFuncAttributeMaxDynamicSharedMemorySize, CONV_DSM);
    cudaFuncSetAttribute(expert_mma_kernel<DFEAT, HID, true, true, true>,
                         cudaFuncAttributeMaxDynamicSharedMemorySize, EXP_DSM);
    cudaFuncSetAttribute(expert_mma_kernel<HID, OUTD, false, false, false>,
                         cudaFuncAttributeMaxDynamicSharedMemorySize, EXP_DSM);

    // weight offsets within g_whi (elements)
    const size_t OFF2 = 0, OFF3 = 294912, OFF4 = 884736, OFF5 = 2064384;

    // ---- all conv weight packs upfront ----
    wpack_kernel<<<(256 * 128 * 9 + 255) / 256, 256>>>(cw2, whi + OFF2, 256, 128);
    wpack_kernel<<<(256 * 256 * 9 + 255) / 256, 256>>>(cw3, whi + OFF3, 256, 256);
    wpack_kernel<<<(512 * 256 * 9 + 255) / 256, 256>>>(cw4, whi + OFF4, 512, 256);
    wpack_kernel<<<(512 * 512 * 9 + 255) / 256, 256>>>(cw5, whi + OFF5, 512, 512);

    // ---- conv stack (all tensor-core now) ----
    conv1_mma_kernel<<<8192, 512, CONV1_DSM>>>(x, cw1, cb1, hiA);
    conv_mma_kernel<128, 32, 32, 256, false><<<dim3(2048, 2), 512, CONV_DSM>>>(
        hiA, whi + OFF2, cb2, hiB, nullptr, nullptr);
    conv_mma_kernel<256, 16, 16, 256, false><<<dim3(512, 2), 512, CONV_DSM>>>(
        hiB, whi + OFF3, cb3, hiA, nullptr, nullptr);
    conv_mma_kernel<256, 8, 8, 512, false><<<dim3(128, 4), 512, CONV_DSM>>>(
        hiA, whi + OFF4, cb4, hiB, nullptr, nullptr);
    conv_mma_kernel<512, 4, 4, 512, true><<<dim3(32, 4), 512, CONV_DSM>>>(
        hiB, whi + OFF5, cb5, feathi, featlo, pool_s);

    // ---- gating ----
    gate_logits_kernel<<<NEXP, 256>>>(pool_s, wg);
    topk_perm_kernel<<<1, 512>>>();

    // ---- sparse expert MLPs (fp16 2-term mma) ----
    expert_mma_kernel<DFEAT, HID, true, true, true>
        <<<dim3(HID / 128, NEXP, 8), 256, EXP_DSM>>>(feathi, featlo, w1, b1,
                                                     hhi, hlo, nullptr);
    expert_mma_kernel<HID, OUTD, false, false, false>
        <<<dim3(OUTD / 128, NEXP, 8), 256, EXP_DSM>>>(hhi, hlo, w2, b2,
                                                      nullptr, nullptr, o_s);

    // ---- combine + aux ----
    zero_kernel<<<(out_size + 255) / 256, 256>>>(y, out_size);
    softmax_combine_kernel<<<NPAIR, 256>>>(y);
    aux_kernel<<<1, 256>>>(y, out_size);
}

// round 11
// speedup vs baseline: 2.2466x; 1.1814x over previous
#include <cuda_runtime.h>
#include <cuda_fp16.h>
#include <math.h>
#include <stdint.h>

// ---------------------------------------------------------------------------
// ToyMoE: conv stack (5x conv3x3+relu+maxpool2) -> top-2 gating (eval)
//         -> sparse top-2 expert MLPs -> softmax -> gated combine + aux loss
// ALL convs + experts on fp16 mma.sync. conv2-5: 1-pass fp16, K-chunk 64.
// conv1: K=27 (pad 32) im2col mma. experts: fp16 2-term, M-tile 64.
// ---------------------------------------------------------------------------

#define BATCH 256
#define DFEAT 2048
#define HID 4096
#define OUTD 1024
#define NEXP 16
#define NPAIR (BATCH * 2)

typedef unsigned short u16;

template <int X> struct LG { static constexpr int v = 1 + LG<X / 2>::v; };
template <> struct LG<1> { static constexpr int v = 0; };

// ------------------------- scratch (device globals) ------------------------
__device__ u16   g_hiA[(size_t)256 * 1024 * 128];  // hi acts (L1/L3 out)
__device__ u16   g_hiB[(size_t)256 * 256 * 256];   // hi acts (L2/L4 out)
__device__ u16   g_whi[4423680];                   // conv weights fp16
__device__ float g_pool[BATCH * DFEAT];            // feats fp32 (gating)
__device__ u16   g_feathi[BATCH * DFEAT];
__device__ u16   g_featlo[BATCH * DFEAT];
__device__ u16   g_hhi[(size_t)NPAIR * HID];
__device__ u16   g_hlo[(size_t)NPAIR * HID];
__device__ float g_logits[BATCH * NEXP];
__device__ float g_gates[BATCH * NEXP];
__device__ int   g_pairE[NPAIR];
__device__ float g_pairG[NPAIR];
__device__ int   g_perm[NPAIR];
__device__ int   g_cnt[NEXP];
__device__ int   g_off[NEXP];
__device__ float g_o[(size_t)NPAIR * OUTD];

// ------------------------------ PTX helpers --------------------------------
__device__ __forceinline__ uint32_t smem_u32(const void* p) {
    uint32_t a;
    asm("{ .reg .u64 t; cvta.to.shared.u64 t, %1; cvt.u32.u64 %0, t; }"
        : "=r"(a) : "l"(p));
    return a;
}

#define SWZ128(x) ((x) ^ (((x) >> 3) & 0x70))
#define SWZ64(x)  ((x) ^ (((x) >> 3) & 0x30))

__device__ __forceinline__ void cp16(uint32_t dst, const void* src, int sz) {
    asm volatile("cp.async.cg.shared.global [%0], [%1], 16, %2;"
                 :: "r"(dst), "l"(src), "r"(sz) : "memory");
}
#define CP_COMMIT() asm volatile("cp.async.commit_group;" ::: "memory")
#define CP_WAIT(n)  asm volatile("cp.async.wait_group %0;" :: "n"(n) : "memory")

__device__ __forceinline__ void ldsm4(uint32_t& r0, uint32_t& r1,
                                      uint32_t& r2, uint32_t& r3, uint32_t a) {
    asm volatile("ldmatrix.sync.aligned.m8n8.x4.shared.b16 {%0,%1,%2,%3}, [%4];"
                 : "=r"(r0), "=r"(r1), "=r"(r2), "=r"(r3) : "r"(a));
}
__device__ __forceinline__ void mma16816(float* d, const uint32_t* a,
                                         const uint32_t* b) {
    asm volatile(
        "mma.sync.aligned.m16n8k16.row.col.f32.f16.f16.f32 "
        "{%0,%1,%2,%3}, {%4,%5,%6,%7}, {%8,%9}, {%0,%1,%2,%3};"
        : "+f"(d[0]), "+f"(d[1]), "+f"(d[2]), "+f"(d[3])
        : "r"(a[0]), "r"(a[1]), "r"(a[2]), "r"(a[3]), "r"(b[0]), "r"(b[1]));
}
__device__ __forceinline__ void split2(float v, u16* hi, u16* lo) {
    __half h = __float2half_rn(v);
    __half l = __float2half_rn(v - __half2float(h));
    *hi = __half_as_ushort(h);
    *lo = __half_as_ushort(l);
}

// --------------------- fp16 mma.sync conv3x3 (SAME, relu, fused pool) ------
// PURE fp16, K-chunk 64 channels of one tap. Stage 32KB = Ahi(16K) Whi(16K),
// SW128 128B rows. 3 stages, 1 sync/chunk.
#define STG 32768
#define CONV_DSM 98304

template <int CI, int H, int W, int CO, bool FEATS>
__global__ void __launch_bounds__(512, 1) conv_mma_kernel(
    const u16* __restrict__ inhi, const u16* __restrict__ whi,
    const float* __restrict__ bias,
    u16* __restrict__ outhi, u16* __restrict__ outlo, float* __restrict__ outf)
{
    constexpr int HW = H * W;
    constexpr int LHW = LG<HW>::v;
    constexpr int LW = LG<W>::v;
    constexpr int CPT = CI / 64;
    constexpr int NCH = 9 * CPT;
    constexpr int WROW = 9 * CI;

    extern __shared__ __align__(1024) char dsm[];
    const uint32_t sb = smem_u32(dsm);
    const int t = threadIdx.x;
    const int lane = t & 31;
    const int wid = t >> 5;
    const int wm = wid & 3, wn = wid >> 2;     // 4x4 warp grid, 32x32 tiles
    const int m0 = blockIdx.x * 128, n0 = blockIdx.y * 128;

    // fill metadata: row r = t>>2 (0..127), quarter sg = t&3 (32B each)
    const int r = t >> 2, sg = t & 3;
    const int m = m0 + r;
    const int bI = m >> LHW;
    const int pos = m & (HW - 1);
    const int yy = pos >> LW, xx = pos & (W - 1);
    const size_t wro = (size_t)(n0 + r) * WROW;
    const uint32_t d1 = SWZ128((uint32_t)(r * 128 + sg * 32));
    const uint32_t d2 = SWZ128((uint32_t)(r * 128 + sg * 32 + 16));

    auto fill = [&](int st, int c) {
        const uint32_t stg = sb + (uint32_t)st * STG;
        const int tap = c / CPT;
        const int cib = (c % CPT) * 64;
        const int dy = tap / 3 - 1, dx = tap % 3 - 1;
        const int iy = yy + dy, ix = xx + dx;
        const bool ok = (iy >= 0 && iy < H && ix >= 0 && ix < W);
        const size_t ai =
            (((size_t)bI * H + (ok ? iy : 0)) * W + (ok ? ix : 0)) * CI + cib + sg * 16;
        cp16(stg + d1, inhi + ai, ok ? 16 : 0);
        cp16(stg + d2, inhi + ai + 8, ok ? 16 : 0);
        const size_t wi = wro + tap * CI + cib + sg * 16;
        cp16(stg + 16384 + d1, whi + wi, 16);
        cp16(stg + 16384 + d2, whi + wi + 8, 16);
    };

    float acc[2][4][4];
#pragma unroll
    for (int a = 0; a < 2; a++)
#pragma unroll
        for (int b = 0; b < 4; b++)
#pragma unroll
            for (int cj = 0; cj < 4; cj++) acc[a][b][cj] = 0.f;

    fill(0, 0);
    CP_COMMIT();
    fill(1, 1);
    CP_COMMIT();

    int st = 0;
    for (int c = 0; c < NCH; c++) {
        if (c + 1 < NCH) { CP_WAIT(1); } else { CP_WAIT(0); }
        __syncthreads();
        if (c + 2 < NCH) {
            fill(st >= 1 ? st - 1 : st + 2, c + 2);
            CP_COMMIT();
        }
        const uint32_t stg = sb + (uint32_t)st * STG;
#pragma unroll
        for (int ks = 0; ks < 4; ks++) {
            const int c0 = ks * 32;
            uint32_t ah[2][4], bh[8];
#pragma unroll
            for (int mt = 0; mt < 2; mt++) {
                const int row = wm * 32 + mt * 16 + (lane & 15);
                const uint32_t off =
                    SWZ128((uint32_t)(row * 128 + c0 + (lane >> 4) * 16));
                ldsm4(ah[mt][0], ah[mt][1], ah[mt][2], ah[mt][3], stg + off);
            }
#pragma unroll
            for (int p = 0; p < 2; p++) {
                const int row = wn * 32 + p * 16 + (lane & 7) + (lane >> 4) * 8;
                const uint32_t off =
                    SWZ128((uint32_t)(row * 128 + c0 + ((lane >> 3) & 1) * 16));
                ldsm4(bh[p * 4], bh[p * 4 + 1], bh[p * 4 + 2], bh[p * 4 + 3],
                      stg + 16384 + off);
            }
#pragma unroll
            for (int mt = 0; mt < 2; mt++)
#pragma unroll
                for (int nt = 0; nt < 4; nt++)
                    mma16816(acc[mt][nt], ah[mt], &bh[nt * 2]);
        }
        st = (st + 1 == 3) ? 0 : st + 1;
    }
    __syncthreads();

    // ---- epilogue: bias+relu -> SMEM tile -> 2x2 pool -> outputs ----
    float* S = (float*)dsm;  // [128][132]
#pragma unroll
    for (int mt = 0; mt < 2; mt++)
#pragma unroll
        for (int half = 0; half < 2; half++) {
            const int rr = wm * 32 + mt * 16 + (lane >> 2) + half * 8;
#pragma unroll
            for (int nt = 0; nt < 4; nt++)
#pragma unroll
                for (int j = 0; j < 2; j++) {
                    const int ncl = wn * 32 + nt * 8 + (lane & 3) * 2 + j;
                    float v = acc[mt][nt][half * 2 + j] + bias[n0 + ncl];
                    S[rr * 132 + ncl] = v > 0.f ? v : 0.f;
                }
        }
    __syncthreads();

    constexpr int Wo = W / 2;
    constexpr int HWo = HW / 4;
    for (int idx = t; idx < 32 * 128; idx += 512) {
        const int pp = idx >> 7;
        const int cl = idx & 127;
        const int lpy = pp / Wo;
        const int lpx = pp % Wo;
        const int lm = lpy * 2 * W + lpx * 2;
        const int mm = m0 + lm;
        const int b = mm >> LHW;
        const int rem = mm & (HW - 1);
        const int y = rem >> LW, x = rem & (W - 1);
        const float* p = S + lm * 132 + cl;
        float v = fmaxf(fmaxf(p[0], p[132]), fmaxf(p[W * 132], p[(W + 1) * 132]));
        const int posn = (y >> 1) * Wo + (x >> 1);
        if (FEATS) {
            u16 hb, lb;
            split2(v, &hb, &lb);
            const int d = (n0 + cl) * HWo + posn;
            outf[(size_t)b * DFEAT + d] = v;
            outhi[(size_t)b * DFEAT + d] = hb;
            outlo[(size_t)b * DFEAT + d] = lb;
        } else {
            const size_t oi = ((size_t)b * HWo + posn) * CO + (n0 + cl);
            outhi[oi] = __half_as_ushort(__float2half_rn(v));
        }
    }
}

// ---------- conv1: fp16 mma (K=27 pad 32, ci-major k), fused pool ----------
#define CONV1_DSM 67584

__global__ void __launch_bounds__(512, 1) conv1_mma_kernel(
    const float* __restrict__ in, const float* __restrict__ wt,
    const float* __restrict__ bias, u16* __restrict__ outhi)
{
    constexpr int H = 64, W = 64;

    extern __shared__ __align__(1024) char dsm[];
    const uint32_t sb = smem_u32(dsm);
    const int t = threadIdx.x;
    const int lane = t & 31;
    const int wid = t >> 5;
    const int wm = wid & 3, wn = wid >> 2;
    const int m0 = blockIdx.x * 128;

    {
        const int r = t >> 2, sg = t & 3;
        const int m = m0 + r;
        const int bI = m >> 12;
        const int pos = m & 4095;
        const int yy = pos >> 6, xx = pos & 63;
        u16 vals[8];
#pragma unroll
        for (int j = 0; j < 8; j++) {
            const int k = sg * 8 + j;
            float v = 0.f;
            if (k < 27) {
                const int ci = k / 9;
                const int tap = k - ci * 9;
                const int iy = yy + tap / 3 - 1;
                const int ix = xx + tap % 3 - 1;
                if (iy >= 0 && iy < H && ix >= 0 && ix < W)
                    v = in[((size_t)(bI * 3 + ci) * H + iy) * W + ix];
            }
            vals[j] = __half_as_ushort(__float2half_rn(v));
        }
        *(uint4*)(dsm + SWZ64((uint32_t)(r * 64 + sg * 16))) = *(uint4*)vals;
    }
    if (t < 128) {
        const float* wp = wt + (size_t)t * 27;
        u16 vals[32];
#pragma unroll
        for (int k = 0; k < 27; k++)
            vals[k] = __half_as_ushort(__float2half_rn(wp[k]));
#pragma unroll
        for (int k = 27; k < 32; k++) vals[k] = 0;
#pragma unroll
        for (int sg = 0; sg < 4; sg++)
            *(uint4*)(dsm + 8192 + SWZ64((uint32_t)(t * 64 + sg * 16))) =
                *(uint4*)&vals[sg * 8];
    }
    __syncthreads();

    float acc[2][4][4];
#pragma unroll
    for (int a = 0; a < 2; a++)
#pragma unroll
        for (int b = 0; b < 4; b++)
#pragma unroll
            for (int cj = 0; cj < 4; cj++) acc[a][b][cj] = 0.f;

#pragma unroll
    for (int ks = 0; ks < 2; ks++) {
        const int c0 = ks * 32;
        uint32_t ah[2][4], bh[8];
#pragma unroll
        for (int mt = 0; mt < 2; mt++) {
            const int row = wm * 32 + mt * 16 + (lane & 15);
            const uint32_t off = SWZ64((uint32_t)(row * 64 + c0 + (lane >> 4) * 16));
            ldsm4(ah[mt][0], ah[mt][1], ah[mt][2], ah[mt][3], sb + off);
        }
#pragma unroll
        for (int p = 0; p < 2; p++) {
            const int row = wn * 32 + p * 16 + (lane & 7) + (lane >> 4) * 8;
            const uint32_t off =
                SWZ64((uint32_t)(row * 64 + c0 + ((lane >> 3) & 1) * 16));
            ldsm4(bh[p * 4], bh[p * 4 + 1], bh[p * 4 + 2], bh[p * 4 + 3],
                  sb + 8192 + off);
        }
#pragma unroll
        for (int mt = 0; mt < 2; mt++)
#pragma unroll
            for (int nt = 0; nt < 4; nt++)
                mma16816(acc[mt][nt], ah[mt], &bh[nt * 2]);
    }
    __syncthreads();

    float* S = (float*)dsm;
#pragma unroll
    for (int mt = 0; mt < 2; mt++)
#pragma unroll
        for (int half = 0; half < 2; half++) {
            const int rr = wm * 32 + mt * 16 + (lane >> 2) + half * 8;
#pragma unroll
            for (int nt = 0; nt < 4; nt++)
#pragma unroll
                for (int j = 0; j < 2; j++) {
                    const int ncl = wn * 32 + nt * 8 + (lane & 3) * 2 + j;
                    float v = acc[mt][nt][half * 2 + j] + bias[ncl];
                    S[rr * 132 + ncl] = v > 0.f ? v : 0.f;
                }
        }
    __syncthreads();

    for (int idx = t; idx < 32 * 128; idx += 512) {
        const int pp = idx >> 7;
        const int cl = idx & 127;
        const int lm = pp * 2;
        const int mm = m0 + lm;
        const int b = mm >> 12;
        const int rem = mm & 4095;
        const int y = rem >> 6, x = rem & 63;
        const float* p = S + lm * 132 + cl;
        float v = fmaxf(fmaxf(p[0], p[132]), fmaxf(p[64 * 132], p[65 * 132]));
        const size_t oi = ((size_t)b * 1024 + (y >> 1) * 32 + (x >> 1)) * 128 + cl;
        outhi[oi] = __half_as_ushort(__float2half_rn(v));
    }
}

// ---- weight pack: OIHW -> [co][tap*CI+ci] fp16 ----------------------------
__global__ void wpack_kernel(const float* __restrict__ w,
                             u16* __restrict__ ohi, int CO, int CI)
{
    const int i = blockIdx.x * 256 + threadIdx.x;
    if (i >= CO * CI * 9) return;
    const int tap = i % 9;
    const int ci = (i / 9) % CI;
    const int co = i / (9 * CI);
    ohi[(size_t)co * CI * 9 + (size_t)tap * CI + ci] =
        __half_as_ushort(__float2half_rn(w[i]));
}

// -------------- grouped expert GEMM, fp16 2-term, M-tile 64 ---------------
// Stage 32KB: Ahi 4K @0, Alo 4K @4096, Wf32 16K @8192, Whi 8K @24576.
#define ESTG 32768
#define EXP_DSM (3 * ESTG + 256)

template <int KDIM, int NDIM, bool RELU, bool GATHER, bool PACKOUT>
__global__ void __launch_bounds__(256, 2) expert_mma_kernel(
    const u16* __restrict__ Ahi, const u16* __restrict__ Alo,
    const float* __restrict__ Wt, const float* __restrict__ bias,
    u16* __restrict__ ohp, u16* __restrict__ olp, float* __restrict__ of)
{
    constexpr int NCH = KDIM / 32;
    const int e = blockIdx.y;
    const int cnt = g_cnt[e];
    const int off = g_off[e];
    const int rbase = blockIdx.z * 64;
    if (rbase >= cnt) return;
    const int n0 = blockIdx.x * 128;

    extern __shared__ __align__(1024) char dsm[];
    const uint32_t sb = smem_u32(dsm);
    const int t = threadIdx.x;
    const int lane = t & 31;
    const int wn = t >> 5;

    int* srcRow = (int*)(dsm + 3 * ESTG);
    if (t < 64) {
        int rr = rbase + t, sr = -1;
        if (rr < cnt) sr = GATHER ? (g_perm[off + rr] >> 1) : (off + rr);
        srcRow[t] = sr;
    }
    __syncthreads();

    const float* wbase = Wt + (size_t)e * KDIM * NDIM + n0;

    auto fill = [&](int st, int c) {
        const uint32_t stg = sb + (uint32_t)st * ESTG;
        const int kb = c * 32;
        {
            const int rr = t >> 2, sg = t & 3;   // 64 rows x 4 segs
            const int sr = srcRow[rr];
            const size_t ai = (sr < 0) ? 0 : ((size_t)sr * KDIM + kb + sg * 8);
            const uint32_t d = SWZ64((uint32_t)(rr * 64 + sg * 16));
            cp16(stg + d, Ahi + ai, sr < 0 ? 0 : 16);
            cp16(stg + 4096 + d, Alo + ai, sr < 0 ? 0 : 16);
        }
#pragma unroll
        for (int i = 0; i < 4; i++) {
            const int task = t + i * 256;
            const int k = task >> 5, sgw = task & 31;
            cp16(stg + 8192 + (uint32_t)(k * 512 + sgw * 16),
                 wbase + (size_t)(kb + k) * NDIM + sgw * 4, 16);
        }
    };

    float acc[4][2][4];
#pragma unroll
    for (int a = 0; a < 4; a++)
#pragma unroll
        for (int b = 0; b < 2; b++)
#pragma unroll
            for (int cj = 0; cj < 4; cj++) acc[a][b][cj] = 0.f;

    fill(0, 0);
    CP_COMMIT();
    fill(1, 1);
    CP_COMMIT();

    int st = 0;
    for (int c = 0; c < NCH; c++) {
        if (c + 1 < NCH) { CP_WAIT(1); } else { CP_WAIT(0); }
        __syncthreads();
        if (c + 2 < NCH) {
            fill(st >= 1 ? st - 1 : st + 2, c + 2);
            CP_COMMIT();
        }
        char* stgc = dsm + (size_t)st * ESTG;
        // ---- convert W fp32 tile -> Whi (SW64, n-major) ----
        {
            const int k = t >> 3, ng = t & 7;
#pragma unroll
            for (int j = 0; j < 4; j++) {
                const float4 w =
                    *(const float4*)(stgc + 8192 + k * 512 + ng * 64 + j * 16);
                const float vv[4] = {w.x, w.y, w.z, w.w};
#pragma unroll
                for (int jj = 0; jj < 4; jj++) {
                    const int n = ng * 16 + j * 4 + jj;
                    *(u16*)(stgc + 24576 + SWZ64((uint32_t)(n * 64 + 2 * k))) =
                        __half_as_ushort(__float2half_rn(vv[jj]));
                }
            }
        }
        __syncthreads();

        const uint32_t stg = sb + (uint32_t)st * ESTG;
#pragma unroll
        for (int ks = 0; ks < 2; ks++) {
            const int c0 = ks * 32;
            uint32_t ah[4][4], al[4][4], bh[4];
#pragma unroll
            for (int mt = 0; mt < 4; mt++) {
                const int row = mt * 16 + (lane & 15);
                const uint32_t o = SWZ64((uint32_t)(row * 64 + c0 + (lane >> 4) * 16));
                ldsm4(ah[mt][0], ah[mt][1], ah[mt][2], ah[mt][3], stg + o);
                ldsm4(al[mt][0], al[mt][1], al[mt][2], al[mt][3], stg + 4096 + o);
            }
            {
                const int row = wn * 16 + (lane & 7) + (lane >> 4) * 8;
                const uint32_t o =
                    SWZ64((uint32_t)(row * 64 + c0 + ((lane >> 3) & 1) * 16));
                ldsm4(bh[0], bh[1], bh[2], bh[3], stg + 24576 + o);
            }
#pragma unroll
            for (int mt = 0; mt < 4; mt++)
#pragma unroll
                for (int nt = 0; nt < 2; nt++) {
                    mma16816(acc[mt][nt], ah[mt], &bh[nt * 2]);
                    mma16816(acc[mt][nt], al[mt], &bh[nt * 2]);
                }
        }
        st = (st + 1 == 3) ? 0 : st + 1;
    }

    // ---- epilogue ----
#pragma unroll
    for (int mt = 0; mt < 4; mt++)
#pragma unroll
        for (int half = 0; half < 2; half++) {
            const int rr = rbase + mt * 16 + (lane >> 2) + half * 8;
            if (rr >= cnt) continue;
            const int gr = off + rr;
#pragma unroll
            for (int nt = 0; nt < 2; nt++)
#pragma unroll
                for (int j = 0; j < 2; j++) {
                    const int n = n0 + wn * 16 + nt * 8 + (lane & 3) * 2 + j;
                    float v = acc[mt][nt][half * 2 + j] + bias[(size_t)e * NDIM + n];
                    if (RELU) v = v > 0.f ? v : 0.f;
                    if (PACKOUT) {
                        u16 hb, lb;
                        split2(v, &hb, &lb);
                        ohp[(size_t)gr * NDIM + n] = hb;
                        olp[(size_t)gr * NDIM + n] = lb;
                    } else {
                        of[(size_t)gr * NDIM + n] = v;
                    }
                }
        }
}

// ------------- gate logits: 1 block/token, deterministic reduce ------------
__global__ void gate_logits_kernel(const float* __restrict__ feats,
                                   const float* __restrict__ wg)
{
    const int b = blockIdx.x;
    const int t = threadIdx.x;  // 128
    const float* f = feats + (size_t)b * DFEAT;
    float p[NEXP];
#pragma unroll
    for (int e = 0; e < NEXP; e++) p[e] = 0.f;
    for (int d = t; d < DFEAT; d += 128) {
        const float fv = f[d];
        const float* wr = wg + (size_t)d * NEXP;
#pragma unroll
        for (int e = 0; e < NEXP; e++) p[e] += fv * wr[e];
    }
#pragma unroll
    for (int e = 0; e < NEXP; e++)
#pragma unroll
        for (int o = 16; o > 0; o >>= 1)
            p[e] += __shfl_xor_sync(0xffffffffu, p[e], o);
    __shared__ float sp[4][NEXP];
    if ((t & 31) == 0)
#pragma unroll
        for (int e = 0; e < NEXP; e++) sp[t >> 5][e] = p[e];
    __syncthreads();
    if (t < NEXP)
        g_logits[b * NEXP + t] =
            ((sp[0][t] + sp[1][t]) + (sp[2][t] + sp[3][t]));
}

// ------------------- top-2 + gate softmax + perm (fused) -------------------
__global__ void topk_perm_kernel()
{
    __shared__ int scnt[NEXP], soff[NEXP], scur[NEXP];
    const int t = threadIdx.x;  // 512
    if (t < BATCH) {
        const int b = t;
        float l[NEXP];
#pragma unroll
        for (int e = 0; e < NEXP; e++) l[e] = g_logits[b * NEXP + e];
        float b1v = -INFINITY, b2v = -INFINITY;
        int b1i = 0, b2i = 0;
#pragma unroll
        for (int e = 0; e < NEXP; e++) {
            float v = l[e];
            if (v > b1v) { b2v = b1v; b2i = b1i; b1v = v; b1i = e; }
            else if (v > b2v) { b2v = v; b2i = e; }
        }
        float e2 = expf(b2v - b1v);
        float denom = 1.f + e2;
        float gate1 = 1.f / denom;
        float gate2 = e2 / denom;
#pragma unroll
        for (int e = 0; e < NEXP; e++) g_gates[b * NEXP + e] = 0.f;
        g_gates[b * NEXP + b1i] = gate1;
        g_gates[b * NEXP + b2i] = gate2;
        g_pairE[2 * b] = b1i;     g_pairG[2 * b] = gate1;
        g_pairE[2 * b + 1] = b2i; g_pairG[2 * b + 1] = gate2;
    }
    if (t < NEXP) { scnt[t] = 0; scur[t] = 0; }
    __syncthreads();
    const int e = g_pairE[t];
    atomicAdd(&scnt[e], 1);
    __syncthreads();
    if (t == 0) {
        int o = 0;
        for (int i = 0; i < NEXP; i++) { soff[i] = o; o += scnt[i]; }
    }
    __syncthreads();
    const int slot = soff[e] + atomicAdd(&scur[e], 1);
    g_perm[slot] = t;
    if (t < NEXP) { g_cnt[t] = scnt[t]; g_off[t] = soff[t]; }
}

// -------------------------- zero output buffer -----------------------------
__global__ void zero_kernel(float* __restrict__ p, int n)
{
    int i = blockIdx.x * blockDim.x + threadIdx.x;
    if (i < n) p[i] = 0.f;
}

// ------------------- softmax over experts' logits + combine ----------------
__global__ void softmax_combine_kernel(float* __restrict__ y)
{
    const int gr = blockIdx.x;
    const int t = threadIdx.x;
    const int pair = g_perm[gr];
    const int token = pair >> 1;
    const float gate = g_pairG[pair];
    const float* row = g_o + (size_t)gr * OUTD;

    __shared__ float red[256];
    float m = -INFINITY;
    for (int j = t; j < OUTD; j += 256) m = fmaxf(m, row[j]);
    red[t] = m;
    __syncthreads();
    for (int s = 128; s > 0; s >>= 1) {
        if (t < s) red[t] = fmaxf(red[t], red[t + s]);
        __syncthreads();
    }
    const float M = red[0];
    __syncthreads();

    float s = 0.f;
    for (int j = t; j < OUTD; j += 256) s += expf(row[j] - M);
    red[t] = s;
    __syncthreads();
    for (int st = 128; st > 0; st >>= 1) {
        if (t < st) red[t] += red[t + st];
        __syncthreads();
    }
    const float scale = gate / red[0];

    for (int j = t; j < OUTD; j += 256)
        atomicAdd(&y[(size_t)token * OUTD + j], expf(row[j] - M) * scale);
}

// ------------------------------- aux loss ----------------------------------
__global__ void aux_kernel(float* __restrict__ out, int out_size)
{
    __shared__ float imp[NEXP], loadv[NEXP];
    int t = threadIdx.x;
    if (t < NEXP) {
        float s = 0.f, L = 0.f;
        for (int b = 0; b < BATCH; b++) {
            float gv = g_gates[b * NEXP + t];
            s += gv;
            if (gv > 0.f) L += 1.f;
        }
        imp[t] = s;
        loadv[t] = L;
    }
    __syncthreads();
    if (t == 0 && out_size > BATCH * OUTD) {
        float mi = 0.f, ml = 0.f;
        for (int e = 0; e < NEXP; e++) { mi += imp[e]; ml += loadv[e]; }
        mi /= NEXP; ml /= NEXP;
        float vi = 0.f, vl = 0.f;
        for (int e = 0; e < NEXP; e++) {
            float di = imp[e] - mi, dl = loadv[e] - ml;
            vi += di * di; vl += dl * dl;
        }
        vi /= NEXP; vl /= NEXP;
        out[BATCH * OUTD] =
            0.01f * (vi / (mi * mi + 1e-10f) + vl / (ml * ml + 1e-10f));
    }
}

// ------------------------------- launcher ----------------------------------
extern "C" void kernel_launch(void* const* d_in, const int* in_sizes, int n_in,
                              void* d_out, int out_size)
{
    (void)in_sizes; (void)n_in;
    const float* x   = (const float*)d_in[0];
    const float* cw1 = (const float*)d_in[1];
    const float* cb1 = (const float*)d_in[2];
    const float* cw2 = (const float*)d_in[3];
    const float* cb2 = (const float*)d_in[4];
    const float* cw3 = (const float*)d_in[5];
    const float* cb3 = (const float*)d_in[6];
    const float* cw4 = (const float*)d_in[7];
    const float* cb4 = (const float*)d_in[8];
    const float* cw5 = (const float*)d_in[9];
    const float* cb5 = (const float*)d_in[10];
    const float* w1  = (const float*)d_in[11];
    const float* b1  = (const float*)d_in[12];
    const float* w2  = (const float*)d_in[13];
    const float* b2  = (const float*)d_in[14];
    const float* wg  = (const float*)d_in[15];
    float* y = (float*)d_out;

    float *pool_s, *o_s;
    u16 *hiA, *hiB, *whi, *feathi, *featlo, *hhi, *hlo;
    cudaGetSymbolAddress((void**)&pool_s, g_pool);
    cudaGetSymbolAddress((void**)&o_s, g_o);
    cudaGetSymbolAddress((void**)&hiA, g_hiA);
    cudaGetSymbolAddress((void**)&hiB, g_hiB);
    cudaGetSymbolAddress((void**)&whi, g_whi);
    cudaGetSymbolAddress((void**)&feathi, g_feathi);
    cudaGetSymbolAddress((void**)&featlo, g_featlo);
    cudaGetSymbolAddress((void**)&hhi, g_hhi);
    cudaGetSymbolAddress((void**)&hlo, g_hlo);

    cudaFuncSetAttribute(conv1_mma_kernel,
                         cudaFuncAttributeMaxDynamicSharedMemorySize, CONV1_DSM);
    cudaFuncSetAttribute(conv_mma_kernel<128, 32, 32, 256, false>,
                         cudaFuncAttributeMaxDynamicSharedMemorySize, CONV_DSM);
    cudaFuncSetAttribute(conv_mma_kernel<256, 16, 16, 256, false>,
                         cudaFuncAttributeMaxDynamicSharedMemorySize, CONV_DSM);
    cudaFuncSetAttribute(conv_mma_kernel<256, 8, 8, 512, false>,
                         cudaFuncAttributeMaxDynamicSharedMemorySize, CONV_DSM);
    cudaFuncSetAttribute(conv_mma_kernel<512, 4, 4, 512, true>,
                         cudaFuncAttributeMaxDynamicSharedMemorySize, CONV_DSM);
    cudaFuncSetAttribute(expert_mma_kernel<DFEAT, HID, true, true, true>,
                         cudaFuncAttributeMaxDynamicSharedMemorySize, EXP_DSM);
    cudaFuncSetAttribute(expert_mma_kernel<HID, OUTD, false, false, false>,
                         cudaFuncAttributeMaxDynamicSharedMemorySize, EXP_DSM);

    // weight offsets within g_whi (elements)
    const size_t OFF2 = 0, OFF3 = 294912, OFF4 = 884736, OFF5 = 2064384;

    // ---- all conv weight packs upfront ----
    wpack_kernel<<<(256 * 128 * 9 + 255) / 256, 256>>>(cw2, whi + OFF2, 256, 128);
    wpack_kernel<<<(256 * 256 * 9 + 255) / 256, 256>>>(cw3, whi + OFF3, 256, 256);
    wpack_kernel<<<(512 * 256 * 9 + 255) / 256, 256>>>(cw4, whi + OFF4, 512, 256);
    wpack_kernel<<<(512 * 512 * 9 + 255) / 256, 256>>>(cw5, whi + OFF5, 512, 512);

    // ---- conv stack (all tensor-core) ----
    conv1_mma_kernel<<<8192, 512, CONV1_DSM>>>(x, cw1, cb1, hiA);
    conv_mma_kernel<128, 32, 32, 256, false><<<dim3(2048, 2), 512, CONV_DSM>>>(
        hiA, whi + OFF2, cb2, hiB, nullptr, nullptr);
    conv_mma_kernel<256, 16, 16, 256, false><<<dim3(512, 2), 512, CONV_DSM>>>(
        hiB, whi + OFF3, cb3, hiA, nullptr, nullptr);
    conv_mma_kernel<256, 8, 8, 512, false><<<dim3(128, 4), 512, CONV_DSM>>>(
        hiA, whi + OFF4, cb4, hiB, nullptr, nullptr);
    conv_mma_kernel<512, 4, 4, 512, true><<<dim3(32, 4), 512, CONV_DSM>>>(
        hiB, whi + OFF5, cb5, feathi, featlo, pool_s);

    // ---- gating ----
    gate_logits_kernel<<<BATCH, 128>>>(pool_s, wg);
    topk_perm_kernel<<<1, 512>>>();

    // ---- sparse expert MLPs (fp16 2-term mma, M-tile 64) ----
    expert_mma_kernel<DFEAT, HID, true, true, true>
        <<<dim3(HID / 128, NEXP, 8), 256, EXP_DSM>>>(feathi, featlo, w1, b1,
                                                     hhi, hlo, nullptr);
    expert_mma_kernel<HID, OUTD, false, false, false>
        <<<dim3(OUTD / 128, NEXP, 8), 256, EXP_DSM>>>(hhi, hlo, w2, b2,
                                                      nullptr, nullptr, o_s);

    // ---- combine + aux ----
    zero_kernel<<<(out_size + 255) / 256, 256>>>(y, out_size);
    softmax_combine_kernel<<<NPAIR, 256>>>(y);
    aux_kernel<<<1, 256>>>(y, out_size);
}

// round 12
// speedup vs baseline: 2.2550x; 1.0037x over previous
#include <cuda_runtime.h>
#include <cuda_fp16.h>
#include <math.h>
#include <stdint.h>

// ---------------------------------------------------------------------------
// ToyMoE: conv stack (5x conv3x3+relu+maxpool2) -> top-2 gating (eval)
//         -> sparse top-2 expert MLPs -> softmax -> gated combine + aux loss
// ALL convs + experts on fp16 mma.sync. conv2-5: 1-pass fp16, K-chunk 128
// (two 64-ch sub-planes/stage). conv1: K=27 im2col mma. experts: fp16
// 2-term, M-tile 64.
// ---------------------------------------------------------------------------

#define BATCH 256
#define DFEAT 2048
#define HID 4096
#define OUTD 1024
#define NEXP 16
#define NPAIR (BATCH * 2)

typedef unsigned short u16;

template <int X> struct LG { static constexpr int v = 1 + LG<X / 2>::v; };
template <> struct LG<1> { static constexpr int v = 0; };

// ------------------------- scratch (device globals) ------------------------
__device__ u16   g_hiA[(size_t)256 * 1024 * 128];  // hi acts (L1/L3 out)
__device__ u16   g_hiB[(size_t)256 * 256 * 256];   // hi acts (L2/L4 out)
__device__ u16   g_whi[4423680];                   // conv weights fp16
__device__ float g_pool[BATCH * DFEAT];            // feats fp32 (gating)
__device__ u16   g_feathi[BATCH * DFEAT];
__device__ u16   g_featlo[BATCH * DFEAT];
__device__ u16   g_hhi[(size_t)NPAIR * HID];
__device__ u16   g_hlo[(size_t)NPAIR * HID];
__device__ float g_logits[BATCH * NEXP];
__device__ float g_gates[BATCH * NEXP];
__device__ int   g_pairE[NPAIR];
__device__ float g_pairG[NPAIR];
__device__ int   g_perm[NPAIR];
__device__ int   g_cnt[NEXP];
__device__ int   g_off[NEXP];
__device__ float g_o[(size_t)NPAIR * OUTD];

// ------------------------------ PTX helpers --------------------------------
__device__ __forceinline__ uint32_t smem_u32(const void* p) {
    uint32_t a;
    asm("{ .reg .u64 t; cvta.to.shared.u64 t, %1; cvt.u32.u64 %0, t; }"
        : "=r"(a) : "l"(p));
    return a;
}

#define SWZ128(x) ((x) ^ (((x) >> 3) & 0x70))
#define SWZ64(x)  ((x) ^ (((x) >> 3) & 0x30))

__device__ __forceinline__ void cp16(uint32_t dst, const void* src, int sz) {
    asm volatile("cp.async.cg.shared.global [%0], [%1], 16, %2;"
                 :: "r"(dst), "l"(src), "r"(sz) : "memory");
}
#define CP_COMMIT() asm volatile("cp.async.commit_group;" ::: "memory")
#define CP_WAIT(n)  asm volatile("cp.async.wait_group %0;" :: "n"(n) : "memory")

__device__ __forceinline__ void ldsm4(uint32_t& r0, uint32_t& r1,
                                      uint32_t& r2, uint32_t& r3, uint32_t a) {
    asm volatile("ldmatrix.sync.aligned.m8n8.x4.shared.b16 {%0,%1,%2,%3}, [%4];"
                 : "=r"(r0), "=r"(r1), "=r"(r2), "=r"(r3) : "r"(a));
}
__device__ __forceinline__ void mma16816(float* d, const uint32_t* a,
                                         const uint32_t* b) {
    asm volatile(
        "mma.sync.aligned.m16n8k16.row.col.f32.f16.f16.f32 "
        "{%0,%1,%2,%3}, {%4,%5,%6,%7}, {%8,%9}, {%0,%1,%2,%3};"
        : "+f"(d[0]), "+f"(d[1]), "+f"(d[2]), "+f"(d[3])
        : "r"(a[0]), "r"(a[1]), "r"(a[2]), "r"(a[3]), "r"(b[0]), "r"(b[1]));
}
__device__ __forceinline__ void split2(float v, u16* hi, u16* lo) {
    __half h = __float2half_rn(v);
    __half l = __float2half_rn(v - __half2float(h));
    *hi = __half_as_ushort(h);
    *lo = __half_as_ushort(l);
}

// --------------------- fp16 mma.sync conv3x3 (SAME, relu, fused pool) ------
// PURE fp16, K-chunk 128 channels of one tap = two 64-ch planes.
// Plane layout (proven): A 16K @0, W 16K @16384; plane1 at +32768.
// Stage 64KB, 3 stages = 192KB, 1 sync/chunk.
#define STG 65536
#define CONV_DSM 196608

template <int CI, int H, int W, int CO, bool FEATS>
__global__ void __launch_bounds__(512, 1) conv_mma_kernel(
    const u16* __restrict__ inhi, const u16* __restrict__ whi,
    const float* __restrict__ bias,
    u16* __restrict__ outhi, u16* __restrict__ outlo, float* __restrict__ outf)
{
    constexpr int HW = H * W;
    constexpr int LHW = LG<HW>::v;
    constexpr int LW = LG<W>::v;
    constexpr int CPT = CI / 128;
    constexpr int NCH = 9 * CPT;
    constexpr int WROW = 9 * CI;

    extern __shared__ __align__(1024) char dsm[];
    const uint32_t sb = smem_u32(dsm);
    const int t = threadIdx.x;
    const int lane = t & 31;
    const int wid = t >> 5;
    const int wm = wid & 3, wn = wid >> 2;     // 4x4 warp grid, 32x32 tiles
    const int m0 = blockIdx.x * 128, n0 = blockIdx.y * 128;

    // fill metadata: row r = t>>2 (0..127), quarter sg = t&3 (32B each)
    const int r = t >> 2, sg = t & 3;
    const int m = m0 + r;
    const int bI = m >> LHW;
    const int pos = m & (HW - 1);
    const int yy = pos >> LW, xx = pos & (W - 1);
    const size_t wro = (size_t)(n0 + r) * WROW;
    const uint32_t d1 = SWZ128((uint32_t)(r * 128 + sg * 32));
    const uint32_t d2 = SWZ128((uint32_t)(r * 128 + sg * 32 + 16));

    auto fill = [&](int st, int c) {
        const uint32_t stg = sb + (uint32_t)st * STG;
        const int tap = c / CPT;
        const int cib = (c % CPT) * 128;
        const int dy = tap / 3 - 1, dx = tap % 3 - 1;
        const int iy = yy + dy, ix = xx + dx;
        const bool ok = (iy >= 0 && iy < H && ix >= 0 && ix < W);
        const size_t abase =
            (((size_t)bI * H + (ok ? iy : 0)) * W + (ok ? ix : 0)) * CI + cib;
        const size_t wbase = wro + tap * CI + cib;
#pragma unroll
        for (int p = 0; p < 2; p++) {
            const uint32_t po = stg + (uint32_t)p * 32768;
            const size_t ai = abase + p * 64 + sg * 16;
            cp16(po + d1, inhi + ai, ok ? 16 : 0);
            cp16(po + d2, inhi + ai + 8, ok ? 16 : 0);
            const size_t wi = wbase + p * 64 + sg * 16;
            cp16(po + 16384 + d1, whi + wi, 16);
            cp16(po + 16384 + d2, whi + wi + 8, 16);
        }
    };

    float acc[2][4][4];
#pragma unroll
    for (int a = 0; a < 2; a++)
#pragma unroll
        for (int b = 0; b < 4; b++)
#pragma unroll
            for (int cj = 0; cj < 4; cj++) acc[a][b][cj] = 0.f;

    fill(0, 0);
    CP_COMMIT();
    if (NCH > 1) { fill(1, 1); CP_COMMIT(); }

    int st = 0;
    for (int c = 0; c < NCH; c++) {
        if (c + 1 < NCH) { CP_WAIT(1); } else { CP_WAIT(0); }
        __syncthreads();
        if (c + 2 < NCH) {
            fill(st >= 1 ? st - 1 : st + 2, c + 2);
            CP_COMMIT();
        }
        const uint32_t stg = sb + (uint32_t)st * STG;
#pragma unroll
        for (int p = 0; p < 2; p++) {
            const uint32_t po = stg + (uint32_t)p * 32768;
#pragma unroll
            for (int ks = 0; ks < 4; ks++) {
                const int c0 = ks * 32;
                uint32_t ah[2][4], bh[8];
#pragma unroll
                for (int mt = 0; mt < 2; mt++) {
                    const int row = wm * 32 + mt * 16 + (lane & 15);
                    const uint32_t off =
                        SWZ128((uint32_t)(row * 128 + c0 + (lane >> 4) * 16));
                    ldsm4(ah[mt][0], ah[mt][1], ah[mt][2], ah[mt][3], po + off);
                }
#pragma unroll
                for (int q = 0; q < 2; q++) {
                    const int row =
                        wn * 32 + q * 16 + (lane & 7) + (lane >> 4) * 8;
                    const uint32_t off =
                        SWZ128((uint32_t)(row * 128 + c0 + ((lane >> 3) & 1) * 16));
                    ldsm4(bh[q * 4], bh[q * 4 + 1], bh[q * 4 + 2], bh[q * 4 + 3],
                          po + 16384 + off);
                }
#pragma unroll
                for (int mt = 0; mt < 2; mt++)
#pragma unroll
                    for (int nt = 0; nt < 4; nt++)
                        mma16816(acc[mt][nt], ah[mt], &bh[nt * 2]);
            }
        }
        st = (st + 1 == 3) ? 0 : st + 1;
    }
    __syncthreads();

    // ---- epilogue: bias+relu -> SMEM tile -> 2x2 pool -> outputs ----
    float* S = (float*)dsm;  // [128][132]
#pragma unroll
    for (int mt = 0; mt < 2; mt++)
#pragma unroll
        for (int half = 0; half < 2; half++) {
            const int rr = wm * 32 + mt * 16 + (lane >> 2) + half * 8;
#pragma unroll
            for (int nt = 0; nt < 4; nt++)
#pragma unroll
                for (int j = 0; j < 2; j++) {
                    const int ncl = wn * 32 + nt * 8 + (lane & 3) * 2 + j;
                    float v = acc[mt][nt][half * 2 + j] + bias[n0 + ncl];
                    S[rr * 132 + ncl] = v > 0.f ? v : 0.f;
                }
        }
    __syncthreads();

    constexpr int Wo = W / 2;
    constexpr int HWo = HW / 4;
    for (int idx = t; idx < 32 * 128; idx += 512) {
        const int pp = idx >> 7;
        const int cl = idx & 127;
        const int lpy = pp / Wo;
        const int lpx = pp % Wo;
        const int lm = lpy * 2 * W + lpx * 2;
        const int mm = m0 + lm;
        const int b = mm >> LHW;
        const int rem = mm & (HW - 1);
        const int y = rem >> LW, x = rem & (W - 1);
        const float* p = S + lm * 132 + cl;
        float v = fmaxf(fmaxf(p[0], p[132]), fmaxf(p[W * 132], p[(W + 1) * 132]));
        const int posn = (y >> 1) * Wo + (x >> 1);
        if (FEATS) {
            u16 hb, lb;
            split2(v, &hb, &lb);
            const int d = (n0 + cl) * HWo + posn;
            outf[(size_t)b * DFEAT + d] = v;
            outhi[(size_t)b * DFEAT + d] = hb;
            outlo[(size_t)b * DFEAT + d] = lb;
        } else {
            const size_t oi = ((size_t)b * HWo + posn) * CO + (n0 + cl);
            outhi[oi] = __half_as_ushort(__float2half_rn(v));
        }
    }
}

// ---------- conv1: fp16 mma (K=27 pad 32, ci-major k), fused pool ----------
#define CONV1_DSM 67584

__global__ void __launch_bounds__(512, 1) conv1_mma_kernel(
    const float* __restrict__ in, const float* __restrict__ wt,
    const float* __restrict__ bias, u16* __restrict__ outhi)
{
    constexpr int H = 64, W = 64;

    extern __shared__ __align__(1024) char dsm[];
    const uint32_t sb = smem_u32(dsm);
    const int t = threadIdx.x;
    const int lane = t & 31;
    const int wid = t >> 5;
    const int wm = wid & 3, wn = wid >> 2;
    const int m0 = blockIdx.x * 128;

    {
        const int r = t >> 2, sg = t & 3;
        const int m = m0 + r;
        const int bI = m >> 12;
        const int pos = m & 4095;
        const int yy = pos >> 6, xx = pos & 63;
        u16 vals[8];
#pragma unroll
        for (int j = 0; j < 8; j++) {
            const int k = sg * 8 + j;
            float v = 0.f;
            if (k < 27) {
                const int ci = k / 9;
                const int tap = k - ci * 9;
                const int iy = yy + tap / 3 - 1;
                const int ix = xx + tap % 3 - 1;
                if (iy >= 0 && iy < H && ix >= 0 && ix < W)
                    v = in[((size_t)(bI * 3 + ci) * H + iy) * W + ix];
            }
            vals[j] = __half_as_ushort(__float2half_rn(v));
        }
        *(uint4*)(dsm + SWZ64((uint32_t)(r * 64 + sg * 16))) = *(uint4*)vals;
    }
    if (t < 128) {
        const float* wp = wt + (size_t)t * 27;
        u16 vals[32];
#pragma unroll
        for (int k = 0; k < 27; k++)
            vals[k] = __half_as_ushort(__float2half_rn(wp[k]));
#pragma unroll
        for (int k = 27; k < 32; k++) vals[k] = 0;
#pragma unroll
        for (int sg = 0; sg < 4; sg++)
            *(uint4*)(dsm + 8192 + SWZ64((uint32_t)(t * 64 + sg * 16))) =
                *(uint4*)&vals[sg * 8];
    }
    __syncthreads();

    float acc[2][4][4];
#pragma unroll
    for (int a = 0; a < 2; a++)
#pragma unroll
        for (int b = 0; b < 4; b++)
#pragma unroll
            for (int cj = 0; cj < 4; cj++) acc[a][b][cj] = 0.f;

#pragma unroll
    for (int ks = 0; ks < 2; ks++) {
        const int c0 = ks * 32;
        uint32_t ah[2][4], bh[8];
#pragma unroll
        for (int mt = 0; mt < 2; mt++) {
            const int row = wm * 32 + mt * 16 + (lane & 15);
            const uint32_t off = SWZ64((uint32_t)(row * 64 + c0 + (lane >> 4) * 16));
            ldsm4(ah[mt][0], ah[mt][1], ah[mt][2], ah[mt][3], sb + off);
        }
#pragma unroll
        for (int p = 0; p < 2; p++) {
            const int row = wn * 32 + p * 16 + (lane & 7) + (lane >> 4) * 8;
            const uint32_t off =
                SWZ64((uint32_t)(row * 64 + c0 + ((lane >> 3) & 1) * 16));
            ldsm4(bh[p * 4], bh[p * 4 + 1], bh[p * 4 + 2], bh[p * 4 + 3],
                  sb + 8192 + off);
        }
#pragma unroll
        for (int mt = 0; mt < 2; mt++)
#pragma unroll
            for (int nt = 0; nt < 4; nt++)
                mma16816(acc[mt][nt], ah[mt], &bh[nt * 2]);
    }
    __syncthreads();

    float* S = (float*)dsm;
#pragma unroll
    for (int mt = 0; mt < 2; mt++)
#pragma unroll
        for (int half = 0; half < 2; half++) {
            const int rr = wm * 32 + mt * 16 + (lane >> 2) + half * 8;
#pragma unroll
            for (int nt = 0; nt < 4; nt++)
#pragma unroll
                for (int j = 0; j < 2; j++) {
                    const int ncl = wn * 32 + nt * 8 + (lane & 3) * 2 + j;
                    float v = acc[mt][nt][half * 2 + j] + bias[ncl];
                    S[rr * 132 + ncl] = v > 0.f ? v : 0.f;
                }
        }
    __syncthreads();

    for (int idx = t; idx < 32 * 128; idx += 512) {
        const int pp = idx >> 7;
        const int cl = idx & 127;
        const int lm = pp * 2;
        const int mm = m0 + lm;
        const int b = mm >> 12;
        const int rem = mm & 4095;
        const int y = rem >> 6, x = rem & 63;
        const float* p = S + lm * 132 + cl;
        float v = fmaxf(fmaxf(p[0], p[132]), fmaxf(p[64 * 132], p[65 * 132]));
        const size_t oi = ((size_t)b * 1024 + (y >> 1) * 32 + (x >> 1)) * 128 + cl;
        outhi[oi] = __half_as_ushort(__float2half_rn(v));
    }
}

// ---- weight pack: OIHW -> [co][tap*CI+ci] fp16 ----------------------------
__global__ void wpack_kernel(const float* __restrict__ w,
                             u16* __restrict__ ohi, int CO, int CI)
{
    const int i = blockIdx.x * 256 + threadIdx.x;
    if (i >= CO * CI * 9) return;
    const int tap = i % 9;
    const int ci = (i / 9) % CI;
    const int co = i / (9 * CI);
    ohi[(size_t)co * CI * 9 + (size_t)tap * CI + ci] =
        __half_as_ushort(__float2half_rn(w[i]));
}

// -------------- grouped expert GEMM, fp16 2-term, M-tile 64 ---------------
// Stage 32KB: Ahi 4K @0, Alo 4K @4096, Wf32 16K @8192, Whi 8K @24576.
#define ESTG 32768
#define EXP_DSM (3 * ESTG + 256)

template <int KDIM, int NDIM, bool RELU, bool GATHER, bool PACKOUT>
__global__ void __launch_bounds__(256, 2) expert_mma_kernel(
    const u16* __restrict__ Ahi, const u16* __restrict__ Alo,
    const float* __restrict__ Wt, const float* __restrict__ bias,
    u16* __restrict__ ohp, u16* __restrict__ olp, float* __restrict__ of)
{
    constexpr int NCH = KDIM / 32;
    const int e = blockIdx.y;
    const int cnt = g_cnt[e];
    const int off = g_off[e];
    const int rbase = blockIdx.z * 64;
    if (rbase >= cnt) return;
    const int n0 = blockIdx.x * 128;

    extern __shared__ __align__(1024) char dsm[];
    const uint32_t sb = smem_u32(dsm);
    const int t = threadIdx.x;
    const int lane = t & 31;
    const int wn = t >> 5;

    int* srcRow = (int*)(dsm + 3 * ESTG);
    if (t < 64) {
        int rr = rbase + t, sr = -1;
        if (rr < cnt) sr = GATHER ? (g_perm[off + rr] >> 1) : (off + rr);
        srcRow[t] = sr;
    }
    __syncthreads();

    const float* wbase = Wt + (size_t)e * KDIM * NDIM + n0;

    auto fill = [&](int st, int c) {
        const uint32_t stg = sb + (uint32_t)st * ESTG;
        const int kb = c * 32;
        {
            const int rr = t >> 2, sg = t & 3;
            const int sr = srcRow[rr];
            const size_t ai = (sr < 0) ? 0 : ((size_t)sr * KDIM + kb + sg * 8);
            const uint32_t d = SWZ64((uint32_t)(rr * 64 + sg * 16));
            cp16(stg + d, Ahi + ai, sr < 0 ? 0 : 16);
            cp16(stg + 4096 + d, Alo + ai, sr < 0 ? 0 : 16);
        }
#pragma unroll
        for (int i = 0; i < 4; i++) {
            const int task = t + i * 256;
            const int k = task >> 5, sgw = task & 31;
            cp16(stg + 8192 + (uint32_t)(k * 512 + sgw * 16),
                 wbase + (size_t)(kb + k) * NDIM + sgw * 4, 16);
        }
    };

    float acc[4][2][4];
#pragma unroll
    for (int a = 0; a < 4; a++)
#pragma unroll
        for (int b = 0; b < 2; b++)
#pragma unroll
            for (int cj = 0; cj < 4; cj++) acc[a][b][cj] = 0.f;

    fill(0, 0);
    CP_COMMIT();
    fill(1, 1);
    CP_COMMIT();

    int st = 0;
    for (int c = 0; c < NCH; c++) {
        if (c + 1 < NCH) { CP_WAIT(1); } else { CP_WAIT(0); }
        __syncthreads();
        if (c + 2 < NCH) {
            fill(st >= 1 ? st - 1 : st + 2, c + 2);
            CP_COMMIT();
        }
        char* stgc = dsm + (size_t)st * ESTG;
        // ---- convert W fp32 tile -> Whi (SW64, n-major) ----
        {
            const int k = t >> 3, ng = t & 7;
#pragma unroll
            for (int j = 0; j < 4; j++) {
                const float4 w =
                    *(const float4*)(stgc + 8192 + k * 512 + ng * 64 + j * 16);
                const float vv[4] = {w.x, w.y, w.z, w.w};
#pragma unroll
                for (int jj = 0; jj < 4; jj++) {
                    const int n = ng * 16 + j * 4 + jj;
                    *(u16*)(stgc + 24576 + SWZ64((uint32_t)(n * 64 + 2 * k))) =
                        __half_as_ushort(__float2half_rn(vv[jj]));
                }
            }
        }
        __syncthreads();

        const uint32_t stg = sb + (uint32_t)st * ESTG;
#pragma unroll
        for (int ks = 0; ks < 2; ks++) {
            const int c0 = ks * 32;
            uint32_t ah[4][4], al[4][4], bh[4];
#pragma unroll
            for (int mt = 0; mt < 4; mt++) {
                const int row = mt * 16 + (lane & 15);
                const uint32_t o = SWZ64((uint32_t)(row * 64 + c0 + (lane >> 4) * 16));
                ldsm4(ah[mt][0], ah[mt][1], ah[mt][2], ah[mt][3], stg + o);
                ldsm4(al[mt][0], al[mt][1], al[mt][2], al[mt][3], stg + 4096 + o);
            }
            {
                const int row = wn * 16 + (lane & 7) + (lane >> 4) * 8;
                const uint32_t o =
                    SWZ64((uint32_t)(row * 64 + c0 + ((lane >> 3) & 1) * 16));
                ldsm4(bh[0], bh[1], bh[2], bh[3], stg + 24576 + o);
            }
#pragma unroll
            for (int mt = 0; mt < 4; mt++)
#pragma unroll
                for (int nt = 0; nt < 2; nt++) {
                    mma16816(acc[mt][nt], ah[mt], &bh[nt * 2]);
                    mma16816(acc[mt][nt], al[mt], &bh[nt * 2]);
                }
        }
        st = (st + 1 == 3) ? 0 : st + 1;
    }

    // ---- epilogue ----
#pragma unroll
    for (int mt = 0; mt < 4; mt++)
#pragma unroll
        for (int half = 0; half < 2; half++) {
            const int rr = rbase + mt * 16 + (lane >> 2) + half * 8;
            if (rr >= cnt) continue;
            const int gr = off + rr;
#pragma unroll
            for (int nt = 0; nt < 2; nt++)
#pragma unroll
                for (int j = 0; j < 2; j++) {
                    const int n = n0 + wn * 16 + nt * 8 + (lane & 3) * 2 + j;
                    float v = acc[mt][nt][half * 2 + j] + bias[(size_t)e * NDIM + n];
                    if (RELU) v = v > 0.f ? v : 0.f;
                    if (PACKOUT) {
                        u16 hb, lb;
                        split2(v, &hb, &lb);
                        ohp[(size_t)gr * NDIM + n] = hb;
                        olp[(size_t)gr * NDIM + n] = lb;
                    } else {
                        of[(size_t)gr * NDIM + n] = v;
                    }
                }
        }
}

// ------------- gate logits: 1 block/token, deterministic reduce ------------
__global__ void gate_logits_kernel(const float* __restrict__ feats,
                                   const float* __restrict__ wg)
{
    const int b = blockIdx.x;
    const int t = threadIdx.x;  // 128
    const float* f = feats + (size_t)b * DFEAT;
    float p[NEXP];
#pragma unroll
    for (int e = 0; e < NEXP; e++) p[e] = 0.f;
    for (int d = t; d < DFEAT; d += 128) {
        const float fv = f[d];
        const float* wr = wg + (size_t)d * NEXP;
#pragma unroll
        for (int e = 0; e < NEXP; e++) p[e] += fv * wr[e];
    }
#pragma unroll
    for (int e = 0; e < NEXP; e++)
#pragma unroll
        for (int o = 16; o > 0; o >>= 1)
            p[e] += __shfl_xor_sync(0xffffffffu, p[e], o);
    __shared__ float sp[4][NEXP];
    if ((t & 31) == 0)
#pragma unroll
        for (int e = 0; e < NEXP; e++) sp[t >> 5][e] = p[e];
    __syncthreads();
    if (t < NEXP)
        g_logits[b * NEXP + t] =
            ((sp[0][t] + sp[1][t]) + (sp[2][t] + sp[3][t]));
}

// ------------------- top-2 + gate softmax + perm (fused) -------------------
__global__ void topk_perm_kernel()
{
    __shared__ int scnt[NEXP], soff[NEXP], scur[NEXP];
    const int t = threadIdx.x;  // 512
    if (t < BATCH) {
        const int b = t;
        float l[NEXP];
#pragma unroll
        for (int e = 0; e < NEXP; e++) l[e] = g_logits[b * NEXP + e];
        float b1v = -INFINITY, b2v = -INFINITY;
        int b1i = 0, b2i = 0;
#pragma unroll
        for (int e = 0; e < NEXP; e++) {
            float v = l[e];
            if (v > b1v) { b2v = b1v; b2i = b1i; b1v = v; b1i = e; }
            else if (v > b2v) { b2v = v; b2i = e; }
        }
        float e2 = expf(b2v - b1v);
        float denom = 1.f + e2;
        float gate1 = 1.f / denom;
        float gate2 = e2 / denom;
#pragma unroll
        for (int e = 0; e < NEXP; e++) g_gates[b * NEXP + e] = 0.f;
        g_gates[b * NEXP + b1i] = gate1;
        g_gates[b * NEXP + b2i] = gate2;
        g_pairE[2 * b] = b1i;     g_pairG[2 * b] = gate1;
        g_pairE[2 * b + 1] = b2i; g_pairG[2 * b + 1] = gate2;
    }
    if (t < NEXP) { scnt[t] = 0; scur[t] = 0; }
    __syncthreads();
    const int e = g_pairE[t];
    atomicAdd(&scnt[e], 1);
    __syncthreads();
    if (t == 0) {
        int o = 0;
        for (int i = 0; i < NEXP; i++) { soff[i] = o; o += scnt[i]; }
    }
    __syncthreads();
    const int slot = soff[e] + atomicAdd(&scur[e], 1);
    g_perm[slot] = t;
    if (t < NEXP) { g_cnt[t] = scnt[t]; g_off[t] = soff[t]; }
}

// -------------------------- zero output buffer -----------------------------
__global__ void zero_kernel(float* __restrict__ p, int n)
{
    int i = blockIdx.x * blockDim.x + threadIdx.x;
    if (i < n) p[i] = 0.f;
}

// ------------------- softmax over experts' logits + combine ----------------
__global__ void softmax_combine_kernel(float* __restrict__ y)
{
    const int gr = blockIdx.x;
    const int t = threadIdx.x;
    const int pair = g_perm[gr];
    const int token = pair >> 1;
    const float gate = g_pairG[pair];
    const float* row = g_o + (size_t)gr * OUTD;

    __shared__ float red[256];
    float m = -INFINITY;
    for (int j = t; j < OUTD; j += 256) m = fmaxf(m, row[j]);
    red[t] = m;
    __syncthreads();
    for (int s = 128; s > 0; s >>= 1) {
        if (t < s) red[t] = fmaxf(red[t], red[t + s]);
        __syncthreads();
    }
    const float M = red[0];
    __syncthreads();

    float s = 0.f;
    for (int j = t; j < OUTD; j += 256) s += expf(row[j] - M);
    red[t] = s;
    __syncthreads();
    for (int st = 128; st > 0; st >>= 1) {
        if (t < st) red[t] += red[t + st];
        __syncthreads();
    }
    const float scale = gate / red[0];

    for (int j = t; j < OUTD; j += 256)
        atomicAdd(&y[(size_t)token * OUTD + j], expf(row[j] - M) * scale);
}

// ------------------------------- aux loss ----------------------------------
__global__ void aux_kernel(float* __restrict__ out, int out_size)
{
    __shared__ float imp[NEXP], loadv[NEXP];
    int t = threadIdx.x;
    if (t < NEXP) {
        float s = 0.f, L = 0.f;
        for (int b = 0; b < BATCH; b++) {
            float gv = g_gates[b * NEXP + t];
            s += gv;
            if (gv > 0.f) L += 1.f;
        }
        imp[t] = s;
        loadv[t] = L;
    }
    __syncthreads();
    if (t == 0 && out_size > BATCH * OUTD) {
        float mi = 0.f, ml = 0.f;
        for (int e = 0; e < NEXP; e++) { mi += imp[e]; ml += loadv[e]; }
        mi /= NEXP; ml /= NEXP;
        float vi = 0.f, vl = 0.f;
        for (int e = 0; e < NEXP; e++) {
            float di = imp[e] - mi, dl = loadv[e] - ml;
            vi += di * di; vl += dl * dl;
        }
        vi /= NEXP; vl /= NEXP;
        out[BATCH * OUTD] =
            0.01f * (vi / (mi * mi + 1e-10f) + vl / (ml * ml + 1e-10f));
    }
}

// ------------------------------- launcher ----------------------------------
extern "C" void kernel_launch(void* const* d_in, const int* in_sizes, int n_in,
                              void* d_out, int out_size)
{
    (void)in_sizes; (void)n_in;
    const float* x   = (const float*)d_in[0];
    const float* cw1 = (const float*)d_in[1];
    const float* cb1 = (const float*)d_in[2];
    const float* cw2 = (const float*)d_in[3];
    const float* cb2 = (const float*)d_in[4];
    const float* cw3 = (const float*)d_in[5];
    const float* cb3 = (const float*)d_in[6];
    const float* cw4 = (const float*)d_in[7];
    const float* cb4 = (const float*)d_in[8];
    const float* cw5 = (const float*)d_in[9];
    const float* cb5 = (const float*)d_in[10];
    const float* w1  = (const float*)d_in[11];
    const float* b1  = (const float*)d_in[12];
    const float* w2  = (const float*)d_in[13];
    const float* b2  = (const float*)d_in[14];
    const float* wg  = (const float*)d_in[15];
    float* y = (float*)d_out;

    float *pool_s, *o_s;
    u16 *hiA, *hiB, *whi, *feathi, *featlo, *hhi, *hlo;
    cudaGetSymbolAddress((void**)&pool_s, g_pool);
    cudaGetSymbolAddress((void**)&o_s, g_o);
    cudaGetSymbolAddress((void**)&hiA, g_hiA);
    cudaGetSymbolAddress((void**)&hiB, g_hiB);
    cudaGetSymbolAddress((void**)&whi, g_whi);
    cudaGetSymbolAddress((void**)&feathi, g_feathi);
    cudaGetSymbolAddress((void**)&featlo, g_featlo);
    cudaGetSymbolAddress((void**)&hhi, g_hhi);
    cudaGetSymbolAddress((void**)&hlo, g_hlo);

    cudaFuncSetAttribute(conv1_mma_kernel,
                         cudaFuncAttributeMaxDynamicSharedMemorySize, CONV1_DSM);
    cudaFuncSetAttribute(conv_mma_kernel<128, 32, 32, 256, false>,
                         cudaFuncAttributeMaxDynamicSharedMemorySize, CONV_DSM);
    cudaFuncSetAttribute(conv_mma_kernel<256, 16, 16, 256, false>,
                         cudaFuncAttributeMaxDynamicSharedMemorySize, CONV_DSM);
    cudaFuncSetAttribute(conv_mma_kernel<256, 8, 8, 512, false>,
                         cudaFuncAttributeMaxDynamicSharedMemorySize, CONV_DSM);
    cudaFuncSetAttribute(conv_mma_kernel<512, 4, 4, 512, true>,
                         cudaFuncAttributeMaxDynamicSharedMemorySize, CONV_DSM);
    cudaFuncSetAttribute(expert_mma_kernel<DFEAT, HID, true, true, true>,
                         cudaFuncAttributeMaxDynamicSharedMemorySize, EXP_DSM);
    cudaFuncSetAttribute(expert_mma_kernel<HID, OUTD, false, false, false>,
                         cudaFuncAttributeMaxDynamicSharedMemorySize, EXP_DSM);

    // weight offsets within g_whi (elements)
    const size_t OFF2 = 0, OFF3 = 294912, OFF4 = 884736, OFF5 = 2064384;

    // ---- all conv weight packs upfront ----
    wpack_kernel<<<(256 * 128 * 9 + 255) / 256, 256>>>(cw2, whi + OFF2, 256, 128);
    wpack_kernel<<<(256 * 256 * 9 + 255) / 256, 256>>>(cw3, whi + OFF3, 256, 256);
    wpack_kernel<<<(512 * 256 * 9 + 255) / 256, 256>>>(cw4, whi + OFF4, 512, 256);
    wpack_kernel<<<(512 * 512 * 9 + 255) / 256, 256>>>(cw5, whi + OFF5, 512, 512);

    // ---- conv stack (all tensor-core) ----
    conv1_mma_kernel<<<8192, 512, CONV1_DSM>>>(x, cw1, cb1, hiA);
    conv_mma_kernel<128, 32, 32, 256, false><<<dim3(2048, 2), 512, CONV_DSM>>>(
        hiA, whi + OFF2, cb2, hiB, nullptr, nullptr);
    conv_mma_kernel<256, 16, 16, 256, false><<<dim3(512, 2), 512, CONV_DSM>>>(
        hiB, whi + OFF3, cb3, hiA, nullptr, nullptr);
    conv_mma_kernel<256, 8, 8, 512, false><<<dim3(128, 4), 512, CONV_DSM>>>(
        hiA, whi + OFF4, cb4, hiB, nullptr, nullptr);
    conv_mma_kernel<512, 4, 4, 512, true><<<dim3(32, 4), 512, CONV_DSM>>>(
        hiB, whi + OFF5, cb5, feathi, featlo, pool_s);

    // ---- gating ----
    gate_logits_kernel<<<BATCH, 128>>>(pool_s, wg);
    topk_perm_kernel<<<1, 512>>>();

    // ---- sparse expert MLPs (fp16 2-term mma, M-tile 64) ----
    expert_mma_kernel<DFEAT, HID, true, true, true>
        <<<dim3(HID / 128, NEXP, 8), 256, EXP_DSM>>>(feathi, featlo, w1, b1,
                                                     hhi, hlo, nullptr);
    expert_mma_kernel<HID, OUTD, false, false, false>
        <<<dim3(OUTD / 128, NEXP, 8), 256, EXP_DSM>>>(hhi, hlo, w2, b2,
                                                      nullptr, nullptr, o_s);

    // ---- combine + aux ----
    zero_kernel<<<(out_size + 255) / 256, 256>>>(y, out_size);
    softmax_combine_kernel<<<NPAIR, 256>>>(y);
    aux_kernel<<<1, 256>>>(y, out_size);
}

// round 13
// speedup vs baseline: 2.2660x; 1.0049x over previous
#include <cuda_runtime.h>
#include <cuda_fp16.h>
#include <math.h>
#include <stdint.h>

// ---------------------------------------------------------------------------
// ToyMoE: conv stack (5x conv3x3+relu+maxpool2) -> top-2 gating (eval)
//         -> sparse top-2 expert MLPs -> softmax -> gated combine + aux loss
// ALL convs + experts on fp16 mma.sync. conv2-5: 1-pass fp16, K-chunk 128.
// conv1: K=27 im2col mma. experts: fp16 2-term, M-tile 64.
// Tail: fused wpack, atomic-free per-token combine.
// ---------------------------------------------------------------------------

#define BATCH 256
#define DFEAT 2048
#define HID 4096
#define OUTD 1024
#define NEXP 16
#define NPAIR (BATCH * 2)

typedef unsigned short u16;

template <int X> struct LG { static constexpr int v = 1 + LG<X / 2>::v; };
template <> struct LG<1> { static constexpr int v = 0; };

// ------------------------- scratch (device globals) ------------------------
__device__ u16   g_hiA[(size_t)256 * 1024 * 128];  // hi acts (L1/L3 out)
__device__ u16   g_hiB[(size_t)256 * 256 * 256];   // hi acts (L2/L4 out)
__device__ u16   g_whi[4423680];                   // conv weights fp16
__device__ float g_pool[BATCH * DFEAT];            // feats fp32 (gating)
__device__ u16   g_feathi[BATCH * DFEAT];
__device__ u16   g_featlo[BATCH * DFEAT];
__device__ u16   g_hhi[(size_t)NPAIR * HID];
__device__ u16   g_hlo[(size_t)NPAIR * HID];
__device__ float g_logits[BATCH * NEXP];
__device__ float g_gates[BATCH * NEXP];
__device__ int   g_pairE[NPAIR];
__device__ float g_pairG[NPAIR];
__device__ int   g_perm[NPAIR];
__device__ int   g_inv[NPAIR];
__device__ int   g_cnt[NEXP];
__device__ int   g_off[NEXP];
__device__ float g_o[(size_t)NPAIR * OUTD];

// ------------------------------ PTX helpers --------------------------------
__device__ __forceinline__ uint32_t smem_u32(const void* p) {
    uint32_t a;
    asm("{ .reg .u64 t; cvta.to.shared.u64 t, %1; cvt.u32.u64 %0, t; }"
        : "=r"(a) : "l"(p));
    return a;
}

#define SWZ128(x) ((x) ^ (((x) >> 3) & 0x70))
#define SWZ64(x)  ((x) ^ (((x) >> 3) & 0x30))

__device__ __forceinline__ void cp16(uint32_t dst, const void* src, int sz) {
    asm volatile("cp.async.cg.shared.global [%0], [%1], 16, %2;"
                 :: "r"(dst), "l"(src), "r"(sz) : "memory");
}
#define CP_COMMIT() asm volatile("cp.async.commit_group;" ::: "memory")
#define CP_WAIT(n)  asm volatile("cp.async.wait_group %0;" :: "n"(n) : "memory")

__device__ __forceinline__ void ldsm4(uint32_t& r0, uint32_t& r1,
                                      uint32_t& r2, uint32_t& r3, uint32_t a) {
    asm volatile("ldmatrix.sync.aligned.m8n8.x4.shared.b16 {%0,%1,%2,%3}, [%4];"
                 : "=r"(r0), "=r"(r1), "=r"(r2), "=r"(r3) : "r"(a));
}
__device__ __forceinline__ void mma16816(float* d, const uint32_t* a,
                                         const uint32_t* b) {
    asm volatile(
        "mma.sync.aligned.m16n8k16.row.col.f32.f16.f16.f32 "
        "{%0,%1,%2,%3}, {%4,%5,%6,%7}, {%8,%9}, {%0,%1,%2,%3};"
        : "+f"(d[0]), "+f"(d[1]), "+f"(d[2]), "+f"(d[3])
        : "r"(a[0]), "r"(a[1]), "r"(a[2]), "r"(a[3]), "r"(b[0]), "r"(b[1]));
}
__device__ __forceinline__ void split2(float v, u16* hi, u16* lo) {
    __half h = __float2half_rn(v);
    __half l = __float2half_rn(v - __half2float(h));
    *hi = __half_as_ushort(h);
    *lo = __half_as_ushort(l);
}

// --------------------- fp16 mma.sync conv3x3 (SAME, relu, fused pool) ------
// PURE fp16, K-chunk 128 channels of one tap = two 64-ch planes.
// Plane layout: A 16K @0, W 16K @16384; plane1 at +32768.
// Stage 64KB, 3 stages = 192KB, 1 sync/chunk.
#define STG 65536
#define CONV_DSM 196608

template <int CI, int H, int W, int CO, bool FEATS>
__global__ void __launch_bounds__(512, 1) conv_mma_kernel(
    const u16* __restrict__ inhi, const u16* __restrict__ whi,
    const float* __restrict__ bias,
    u16* __restrict__ outhi, u16* __restrict__ outlo, float* __restrict__ outf)
{
    constexpr int HW = H * W;
    constexpr int LHW = LG<HW>::v;
    constexpr int LW = LG<W>::v;
    constexpr int CPT = CI / 128;
    constexpr int NCH = 9 * CPT;
    constexpr int WROW = 9 * CI;

    extern __shared__ __align__(1024) char dsm[];
    const uint32_t sb = smem_u32(dsm);
    const int t = threadIdx.x;
    const int lane = t & 31;
    const int wid = t >> 5;
    const int wm = wid & 3, wn = wid >> 2;     // 4x4 warp grid, 32x32 tiles
    const int m0 = blockIdx.x * 128, n0 = blockIdx.y * 128;

    const int r = t >> 2, sg = t & 3;
    const int m = m0 + r;
    const int bI = m >> LHW;
    const int pos = m & (HW - 1);
    const int yy = pos >> LW, xx = pos & (W - 1);
    const size_t wro = (size_t)(n0 + r) * WROW;
    const uint32_t d1 = SWZ128((uint32_t)(r * 128 + sg * 32));
    const uint32_t d2 = SWZ128((uint32_t)(r * 128 + sg * 32 + 16));

    auto fill = [&](int st, int c) {
        const uint32_t stg = sb + (uint32_t)st * STG;
        const int tap = c / CPT;
        const int cib = (c % CPT) * 128;
        const int dy = tap / 3 - 1, dx = tap % 3 - 1;
        const int iy = yy + dy, ix = xx + dx;
        const bool ok = (iy >= 0 && iy < H && ix >= 0 && ix < W);
        const size_t abase =
            (((size_t)bI * H + (ok ? iy : 0)) * W + (ok ? ix : 0)) * CI + cib;
        const size_t wbase = wro + tap * CI + cib;
#pragma unroll
        for (int p = 0; p < 2; p++) {
            const uint32_t po = stg + (uint32_t)p * 32768;
            const size_t ai = abase + p * 64 + sg * 16;
            cp16(po + d1, inhi + ai, ok ? 16 : 0);
            cp16(po + d2, inhi + ai + 8, ok ? 16 : 0);
            const size_t wi = wbase + p * 64 + sg * 16;
            cp16(po + 16384 + d1, whi + wi, 16);
            cp16(po + 16384 + d2, whi + wi + 8, 16);
        }
    };

    float acc[2][4][4];
#pragma unroll
    for (int a = 0; a < 2; a++)
#pragma unroll
        for (int b = 0; b < 4; b++)
#pragma unroll
            for (int cj = 0; cj < 4; cj++) acc[a][b][cj] = 0.f;

    fill(0, 0);
    CP_COMMIT();
    if (NCH > 1) { fill(1, 1); CP_COMMIT(); }

    int st = 0;
    for (int c = 0; c < NCH; c++) {
        if (c + 1 < NCH) { CP_WAIT(1); } else { CP_WAIT(0); }
        __syncthreads();
        if (c + 2 < NCH) {
            fill(st >= 1 ? st - 1 : st + 2, c + 2);
            CP_COMMIT();
        }
        const uint32_t stg = sb + (uint32_t)st * STG;
#pragma unroll
        for (int p = 0; p < 2; p++) {
            const uint32_t po = stg + (uint32_t)p * 32768;
#pragma unroll
            for (int ks = 0; ks < 4; ks++) {
                const int c0 = ks * 32;
                uint32_t ah[2][4], bh[8];
#pragma unroll
                for (int mt = 0; mt < 2; mt++) {
                    const int row = wm * 32 + mt * 16 + (lane & 15);
                    const uint32_t off =
                        SWZ128((uint32_t)(row * 128 + c0 + (lane >> 4) * 16));
                    ldsm4(ah[mt][0], ah[mt][1], ah[mt][2], ah[mt][3], po + off);
                }
#pragma unroll
                for (int q = 0; q < 2; q++) {
                    const int row =
                        wn * 32 + q * 16 + (lane & 7) + (lane >> 4) * 8;
                    const uint32_t off =
                        SWZ128((uint32_t)(row * 128 + c0 + ((lane >> 3) & 1) * 16));
                    ldsm4(bh[q * 4], bh[q * 4 + 1], bh[q * 4 + 2], bh[q * 4 + 3],
                          po + 16384 + off);
                }
#pragma unroll
                for (int mt = 0; mt < 2; mt++)
#pragma unroll
                    for (int nt = 0; nt < 4; nt++)
                        mma16816(acc[mt][nt], ah[mt], &bh[nt * 2]);
            }
        }
        st = (st + 1 == 3) ? 0 : st + 1;
    }
    __syncthreads();

    // ---- epilogue: bias+relu -> SMEM tile -> 2x2 pool -> outputs ----
    float* S = (float*)dsm;  // [128][132]
#pragma unroll
    for (int mt = 0; mt < 2; mt++)
#pragma unroll
        for (int half = 0; half < 2; half++) {
            const int rr = wm * 32 + mt * 16 + (lane >> 2) + half * 8;
#pragma unroll
            for (int nt = 0; nt < 4; nt++)
#pragma unroll
                for (int j = 0; j < 2; j++) {
                    const int ncl = wn * 32 + nt * 8 + (lane & 3) * 2 + j;
                    float v = acc[mt][nt][half * 2 + j] + bias[n0 + ncl];
                    S[rr * 132 + ncl] = v > 0.f ? v : 0.f;
                }
        }
    __syncthreads();

    constexpr int Wo = W / 2;
    constexpr int HWo = HW / 4;
    for (int idx = t; idx < 32 * 128; idx += 512) {
        const int pp = idx >> 7;
        const int cl = idx & 127;
        const int lpy = pp / Wo;
        const int lpx = pp % Wo;
        const int lm = lpy * 2 * W + lpx * 2;
        const int mm = m0 + lm;
        const int b = mm >> LHW;
        const int rem = mm & (HW - 1);
        const int y = rem >> LW, x = rem & (W - 1);
        const float* p = S + lm * 132 + cl;
        float v = fmaxf(fmaxf(p[0], p[132]), fmaxf(p[W * 132], p[(W + 1) * 132]));
        const int posn = (y >> 1) * Wo + (x >> 1);
        if (FEATS) {
            u16 hb, lb;
            split2(v, &hb, &lb);
            const int d = (n0 + cl) * HWo + posn;
            outf[(size_t)b * DFEAT + d] = v;
            outhi[(size_t)b * DFEAT + d] = hb;
            outlo[(size_t)b * DFEAT + d] = lb;
        } else {
            const size_t oi = ((size_t)b * HWo + posn) * CO + (n0 + cl);
            outhi[oi] = __half_as_ushort(__float2half_rn(v));
        }
    }
}

// ---------- conv1: fp16 mma (K=27 pad 32, ci-major k), fused pool ----------
#define CONV1_DSM 67584

__global__ void __launch_bounds__(512, 1) conv1_mma_kernel(
    const float* __restrict__ in, const float* __restrict__ wt,
    const float* __restrict__ bias, u16* __restrict__ outhi)
{
    constexpr int H = 64, W = 64;

    extern __shared__ __align__(1024) char dsm[];
    const uint32_t sb = smem_u32(dsm);
    const int t = threadIdx.x;
    const int lane = t & 31;
    const int wid = t >> 5;
    const int wm = wid & 3, wn = wid >> 2;
    const int m0 = blockIdx.x * 128;

    {
        const int r = t >> 2, sg = t & 3;
        const int m = m0 + r;
        const int bI = m >> 12;
        const int pos = m & 4095;
        const int yy = pos >> 6, xx = pos & 63;
        u16 vals[8];
#pragma unroll
        for (int j = 0; j < 8; j++) {
            const int k = sg * 8 + j;
            float v = 0.f;
            if (k < 27) {
                const int ci = k / 9;
                const int tap = k - ci * 9;
                const int iy = yy + tap / 3 - 1;
                const int ix = xx + tap % 3 - 1;
                if (iy >= 0 && iy < H && ix >= 0 && ix < W)
                    v = in[((size_t)(bI * 3 + ci) * H + iy) * W + ix];
            }
            vals[j] = __half_as_ushort(__float2half_rn(v));
        }
        *(uint4*)(dsm + SWZ64((uint32_t)(r * 64 + sg * 16))) = *(uint4*)vals;
    }
    if (t < 128) {
        const float* wp = wt + (size_t)t * 27;
        u16 vals[32];
#pragma unroll
        for (int k = 0; k < 27; k++)
            vals[k] = __half_as_ushort(__float2half_rn(wp[k]));
#pragma unroll
        for (int k = 27; k < 32; k++) vals[k] = 0;
#pragma unroll
        for (int sg = 0; sg < 4; sg++)
            *(uint4*)(dsm + 8192 + SWZ64((uint32_t)(t * 64 + sg * 16))) =
                *(uint4*)&vals[sg * 8];
    }
    __syncthreads();

    float acc[2][4][4];
#pragma unroll
    for (int a = 0; a < 2; a++)
#pragma unroll
        for (int b = 0; b < 4; b++)
#pragma unroll
            for (int cj = 0; cj < 4; cj++) acc[a][b][cj] = 0.f;

#pragma unroll
    for (int ks = 0; ks < 2; ks++) {
        const int c0 = ks * 32;
        uint32_t ah[2][4], bh[8];
#pragma unroll
        for (int mt = 0; mt < 2; mt++) {
            const int row = wm * 32 + mt * 16 + (lane & 15);
            const uint32_t off = SWZ64((uint32_t)(row * 64 + c0 + (lane >> 4) * 16));
            ldsm4(ah[mt][0], ah[mt][1], ah[mt][2], ah[mt][3], sb + off);
        }
#pragma unroll
        for (int p = 0; p < 2; p++) {
            const int row = wn * 32 + p * 16 + (lane & 7) + (lane >> 4) * 8;
            const uint32_t off =
                SWZ64((uint32_t)(row * 64 + c0 + ((lane >> 3) & 1) * 16));
            ldsm4(bh[p * 4], bh[p * 4 + 1], bh[p * 4 + 2], bh[p * 4 + 3],
                  sb + 8192 + off);
        }
#pragma unroll
        for (int mt = 0; mt < 2; mt++)
#pragma unroll
            for (int nt = 0; nt < 4; nt++)
                mma16816(acc[mt][nt], ah[mt], &bh[nt * 2]);
    }
    __syncthreads();

    float* S = (float*)dsm;
#pragma unroll
    for (int mt = 0; mt < 2; mt++)
#pragma unroll
        for (int half = 0; half < 2; half++) {
            const int rr = wm * 32 + mt * 16 + (lane >> 2) + half * 8;
#pragma unroll
            for (int nt = 0; nt < 4; nt++)
#pragma unroll
                for (int j = 0; j < 2; j++) {
                    const int ncl = wn * 32 + nt * 8 + (lane & 3) * 2 + j;
                    float v = acc[mt][nt][half * 2 + j] + bias[ncl];
                    S[rr * 132 + ncl] = v > 0.f ? v : 0.f;
                }
        }
    __syncthreads();

    for (int idx = t; idx < 32 * 128; idx += 512) {
        const int pp = idx >> 7;
        const int cl = idx & 127;
        const int lm = pp * 2;
        const int mm = m0 + lm;
        const int b = mm >> 12;
        const int rem = mm & 4095;
        const int y = rem >> 6, x = rem & 63;
        const float* p = S + lm * 132 + cl;
        float v = fmaxf(fmaxf(p[0], p[132]), fmaxf(p[64 * 132], p[65 * 132]));
        const size_t oi = ((size_t)b * 1024 + (y >> 1) * 32 + (x >> 1)) * 128 + cl;
        outhi[oi] = __half_as_ushort(__float2half_rn(v));
    }
}

// ---- merged weight pack: OIHW -> [co][tap*CI+ci] fp16, all 4 layers -------
#define WP2 294912
#define WP3 884736
#define WP4 2064384
#define WPALL 4423680

__global__ void wpack_all_kernel(const float* __restrict__ w2,
                                 const float* __restrict__ w3,
                                 const float* __restrict__ w4,
                                 const float* __restrict__ w5,
                                 u16* __restrict__ ohi)
{
    const int i = blockIdx.x * 256 + threadIdx.x;
    if (i >= WPALL) return;
    const float* w;
    int CI, li;
    size_t ob;
    if (i < WP2)      { w = w2; CI = 128; li = i;          ob = 0; }
    else if (i < WP3) { w = w3; CI = 256; li = i - WP2;    ob = WP2; }
    else if (i < WP4) { w = w4; CI = 256; li = i - WP3;    ob = WP3; }
    else              { w = w5; CI = 512; li = i - WP4;    ob = WP4; }
    const int tap = li % 9;
    const int ci = (li / 9) % CI;
    const int co = li / (9 * CI);
    ohi[ob + (size_t)co * CI * 9 + (size_t)tap * CI + ci] =
        __half_as_ushort(__float2half_rn(w[li]));
}

// -------------- grouped expert GEMM, fp16 2-term, M-tile 64 ---------------
// Stage 32KB: Ahi 4K @0, Alo 4K @4096, Wf32 16K @8192, Whi 8K @24576.
#define ESTG 32768
#define EXP_DSM (3 * ESTG + 256)

template <int KDIM, int NDIM, bool RELU, bool GATHER, bool PACKOUT>
__global__ void __launch_bounds__(256, 2) expert_mma_kernel(
    const u16* __restrict__ Ahi, const u16* __restrict__ Alo,
    const float* __restrict__ Wt, const float* __restrict__ bias,
    u16* __restrict__ ohp, u16* __restrict__ olp, float* __restrict__ of)
{
    constexpr int NCH = KDIM / 32;
    const int e = blockIdx.y;
    const int cnt = g_cnt[e];
    const int off = g_off[e];
    const int rbase = blockIdx.z * 64;
    if (rbase >= cnt) return;
    const int n0 = blockIdx.x * 128;

    extern __shared__ __align__(1024) char dsm[];
    const uint32_t sb = smem_u32(dsm);
    const int t = threadIdx.x;
    const int lane = t & 31;
    const int wn = t >> 5;

    int* srcRow = (int*)(dsm + 3 * ESTG);
    if (t < 64) {
        int rr = rbase + t, sr = -1;
        if (rr < cnt) sr = GATHER ? (g_perm[off + rr] >> 1) : (off + rr);
        srcRow[t] = sr;
    }
    __syncthreads();

    const float* wbase = Wt + (size_t)e * KDIM * NDIM + n0;

    auto fill = [&](int st, int c) {
        const uint32_t stg = sb + (uint32_t)st * ESTG;
        const int kb = c * 32;
        {
            const int rr = t >> 2, sg = t & 3;
            const int sr = srcRow[rr];
            const size_t ai = (sr < 0) ? 0 : ((size_t)sr * KDIM + kb + sg * 8);
            const uint32_t d = SWZ64((uint32_t)(rr * 64 + sg * 16));
            cp16(stg + d, Ahi + ai, sr < 0 ? 0 : 16);
            cp16(stg + 4096 + d, Alo + ai, sr < 0 ? 0 : 16);
        }
#pragma unroll
        for (int i = 0; i < 4; i++) {
            const int task = t + i * 256;
            const int k = task >> 5, sgw = task & 31;
            cp16(stg + 8192 + (uint32_t)(k * 512 + sgw * 16),
                 wbase + (size_t)(kb + k) * NDIM + sgw * 4, 16);
        }
    };

    float acc[4][2][4];
#pragma unroll
    for (int a = 0; a < 4; a++)
#pragma unroll
        for (int b = 0; b < 2; b++)
#pragma unroll
            for (int cj = 0; cj < 4; cj++) acc[a][b][cj] = 0.f;

    fill(0, 0);
    CP_COMMIT();
    fill(1, 1);
    CP_COMMIT();

    int st = 0;
    for (int c = 0; c < NCH; c++) {
        if (c + 1 < NCH) { CP_WAIT(1); } else { CP_WAIT(0); }
        __syncthreads();
        if (c + 2 < NCH) {
            fill(st >= 1 ? st - 1 : st + 2, c + 2);
            CP_COMMIT();
        }
        char* stgc = dsm + (size_t)st * ESTG;
        // ---- convert W fp32 tile -> Whi (SW64, n-major) ----
        {
            const int k = t >> 3, ng = t & 7;
#pragma unroll
            for (int j = 0; j < 4; j++) {
                const float4 w =
                    *(const float4*)(stgc + 8192 + k * 512 + ng * 64 + j * 16);
                const float vv[4] = {w.x, w.y, w.z, w.w};
#pragma unroll
                for (int jj = 0; jj < 4; jj++) {
                    const int n = ng * 16 + j * 4 + jj;
                    *(u16*)(stgc + 24576 + SWZ64((uint32_t)(n * 64 + 2 * k))) =
                        __half_as_ushort(__float2half_rn(vv[jj]));
                }
            }
        }
        __syncthreads();

        const uint32_t stg = sb + (uint32_t)st * ESTG;
#pragma unroll
        for (int ks = 0; ks < 2; ks++) {
            const int c0 = ks * 32;
            uint32_t ah[4][4], al[4][4], bh[4];
#pragma unroll
            for (int mt = 0; mt < 4; mt++) {
                const int row = mt * 16 + (lane & 15);
                const uint32_t o = SWZ64((uint32_t)(row * 64 + c0 + (lane >> 4) * 16));
                ldsm4(ah[mt][0], ah[mt][1], ah[mt][2], ah[mt][3], stg + o);
                ldsm4(al[mt][0], al[mt][1], al[mt][2], al[mt][3], stg + 4096 + o);
            }
            {
                const int row = wn * 16 + (lane & 7) + (lane >> 4) * 8;
                const uint32_t o =
                    SWZ64((uint32_t)(row * 64 + c0 + ((lane >> 3) & 1) * 16));
                ldsm4(bh[0], bh[1], bh[2], bh[3], stg + 24576 + o);
            }
#pragma unroll
            for (int mt = 0; mt < 4; mt++)
#pragma unroll
                for (int nt = 0; nt < 2; nt++) {
                    mma16816(acc[mt][nt], ah[mt], &bh[nt * 2]);
                    mma16816(acc[mt][nt], al[mt], &bh[nt * 2]);
                }
        }
        st = (st + 1 == 3) ? 0 : st + 1;
    }

    // ---- epilogue ----
#pragma unroll
    for (int mt = 0; mt < 4; mt++)
#pragma unroll
        for (int half = 0; half < 2; half++) {
            const int rr = rbase + mt * 16 + (lane >> 2) + half * 8;
            if (rr >= cnt) continue;
            const int gr = off + rr;
#pragma unroll
            for (int nt = 0; nt < 2; nt++)
#pragma unroll
                for (int j = 0; j < 2; j++) {
                    const int n = n0 + wn * 16 + nt * 8 + (lane & 3) * 2 + j;
                    float v = acc[mt][nt][half * 2 + j] + bias[(size_t)e * NDIM + n];
                    if (RELU) v = v > 0.f ? v : 0.f;
                    if (PACKOUT) {
                        u16 hb, lb;
                        split2(v, &hb, &lb);
                        ohp[(size_t)gr * NDIM + n] = hb;
                        olp[(size_t)gr * NDIM + n] = lb;
                    } else {
                        of[(size_t)gr * NDIM + n] = v;
                    }
                }
        }
}

// ------------- gate logits: 1 block/token, deterministic reduce ------------
__global__ void gate_logits_kernel(const float* __restrict__ feats,
                                   const float* __restrict__ wg)
{
    const int b = blockIdx.x;
    const int t = threadIdx.x;  // 128
    const float* f = feats + (size_t)b * DFEAT;
    float p[NEXP];
#pragma unroll
    for (int e = 0; e < NEXP; e++) p[e] = 0.f;
    for (int d = t; d < DFEAT; d += 128) {
        const float fv = f[d];
        const float* wr = wg + (size_t)d * NEXP;
#pragma unroll
        for (int e = 0; e < NEXP; e++) p[e] += fv * wr[e];
    }
#pragma unroll
    for (int e = 0; e < NEXP; e++)
#pragma unroll
        for (int o = 16; o > 0; o >>= 1)
            p[e] += __shfl_xor_sync(0xffffffffu, p[e], o);
    __shared__ float sp[4][NEXP];
    if ((t & 31) == 0)
#pragma unroll
        for (int e = 0; e < NEXP; e++) sp[t >> 5][e] = p[e];
    __syncthreads();
    if (t < NEXP)
        g_logits[b * NEXP + t] =
            ((sp[0][t] + sp[1][t]) + (sp[2][t] + sp[3][t]));
}

// ---------- top-2 + gate softmax + perm + inverse perm (fused) -------------
__global__ void topk_perm_kernel()
{
    __shared__ int scnt[NEXP], soff[NEXP], scur[NEXP];
    const int t = threadIdx.x;  // 512
    if (t < BATCH) {
        const int b = t;
        float l[NEXP];
#pragma unroll
        for (int e = 0; e < NEXP; e++) l[e] = g_logits[b * NEXP + e];
        float b1v = -INFINITY, b2v = -INFINITY;
        int b1i = 0, b2i = 0;
#pragma unroll
        for (int e = 0; e < NEXP; e++) {
            float v = l[e];
            if (v > b1v) { b2v = b1v; b2i = b1i; b1v = v; b1i = e; }
            else if (v > b2v) { b2v = v; b2i = e; }
        }
        float e2 = expf(b2v - b1v);
        float denom = 1.f + e2;
        float gate1 = 1.f / denom;
        float gate2 = e2 / denom;
#pragma unroll
        for (int e = 0; e < NEXP; e++) g_gates[b * NEXP + e] = 0.f;
        g_gates[b * NEXP + b1i] = gate1;
        g_gates[b * NEXP + b2i] = gate2;
        g_pairE[2 * b] = b1i;     g_pairG[2 * b] = gate1;
        g_pairE[2 * b + 1] = b2i; g_pairG[2 * b + 1] = gate2;
    }
    if (t < NEXP) { scnt[t] = 0; scur[t] = 0; }
    __syncthreads();
    const int e = g_pairE[t];
    atomicAdd(&scnt[e], 1);
    __syncthreads();
    if (t == 0) {
        int o = 0;
        for (int i = 0; i < NEXP; i++) { soff[i] = o; o += scnt[i]; }
    }
    __syncthreads();
    const int slot = soff[e] + atomicAdd(&scur[e], 1);
    g_perm[slot] = t;
    g_inv[t] = slot;
    if (t < NEXP) { g_cnt[t] = scnt[t]; g_off[t] = soff[t]; }
}

// ------- per-token combine: softmax both expert rows, write y directly -----
__global__ void combine_kernel(float* __restrict__ y)
{
    const int token = blockIdx.x;   // 256
    const int t = threadIdx.x;      // 256
    __shared__ float red[256];
    float outv[4];
#pragma unroll
    for (int j = 0; j < 4; j++) outv[j] = 0.f;

    for (int q = 0; q < 2; q++) {
        const int pair = 2 * token + q;
        const int row = g_inv[pair];
        const float gate = g_pairG[pair];
        const float* r = g_o + (size_t)row * OUTD;

        float m = -INFINITY;
#pragma unroll
        for (int j = 0; j < 4; j++) m = fmaxf(m, r[t + j * 256]);
        red[t] = m;
        __syncthreads();
        for (int s = 128; s > 0; s >>= 1) {
            if (t < s) red[t] = fmaxf(red[t], red[t + s]);
            __syncthreads();
        }
        const float M = red[0];
        __syncthreads();

        float s = 0.f;
        float ev[4];
#pragma unroll
        for (int j = 0; j < 4; j++) {
            ev[j] = expf(r[t + j * 256] - M);
            s += ev[j];
        }
        red[t] = s;
        __syncthreads();
        for (int st = 128; st > 0; st >>= 1) {
            if (t < st) red[t] += red[t + st];
            __syncthreads();
        }
        const float scale = gate / red[0];
        __syncthreads();
#pragma unroll
        for (int j = 0; j < 4; j++) outv[j] += ev[j] * scale;
    }
#pragma unroll
    for (int j = 0; j < 4; j++)
        y[(size_t)token * OUTD + t + j * 256] = outv[j];
}

// ------------------------------- aux loss ----------------------------------
__global__ void aux_kernel(float* __restrict__ out, int out_size)
{
    __shared__ float imp[NEXP], loadv[NEXP];
    int t = threadIdx.x;
    if (t < NEXP) {
        float s = 0.f, L = 0.f;
        for (int b = 0; b < BATCH; b++) {
            float gv = g_gates[b * NEXP + t];
            s += gv;
            if (gv > 0.f) L += 1.f;
        }
        imp[t] = s;
        loadv[t] = L;
    }
    __syncthreads();
    if (t == 0 && out_size > BATCH * OUTD) {
        float mi = 0.f, ml = 0.f;
        for (int e = 0; e < NEXP; e++) { mi += imp[e]; ml += loadv[e]; }
        mi /= NEXP; ml /= NEXP;
        float vi = 0.f, vl = 0.f;
        for (int e = 0; e < NEXP; e++) {
            float di = imp[e] - mi, dl = loadv[e] - ml;
            vi += di * di; vl += dl * dl;
        }
        vi /= NEXP; vl /= NEXP;
        out[BATCH * OUTD] =
            0.01f * (vi / (mi * mi + 1e-10f) + vl / (ml * ml + 1e-10f));
    }
}

// ------------------------------- launcher ----------------------------------
extern "C" void kernel_launch(void* const* d_in, const int* in_sizes, int n_in,
                              void* d_out, int out_size)
{
    (void)in_sizes; (void)n_in;
    const float* x   = (const float*)d_in[0];
    const float* cw1 = (const float*)d_in[1];
    const float* cb1 = (const float*)d_in[2];
    const float* cw2 = (const float*)d_in[3];
    const float* cb2 = (const float*)d_in[4];
    const float* cw3 = (const float*)d_in[5];
    const float* cb3 = (const float*)d_in[6];
    const float* cw4 = (const float*)d_in[7];
    const float* cb4 = (const float*)d_in[8];
    const float* cw5 = (const float*)d_in[9];
    const float* cb5 = (const float*)d_in[10];
    const float* w1  = (const float*)d_in[11];
    const float* b1  = (const float*)d_in[12];
    const float* w2  = (const float*)d_in[13];
    const float* b2  = (const float*)d_in[14];
    const float* wg  = (const float*)d_in[15];
    float* y = (float*)d_out;

    float *pool_s, *o_s;
    u16 *hiA, *hiB, *whi, *feathi, *featlo, *hhi, *hlo;
    cudaGetSymbolAddress((void**)&pool_s, g_pool);
    cudaGetSymbolAddress((void**)&o_s, g_o);
    cudaGetSymbolAddress((void**)&hiA, g_hiA);
    cudaGetSymbolAddress((void**)&hiB, g_hiB);
    cudaGetSymbolAddress((void**)&whi, g_whi);
    cudaGetSymbolAddress((void**)&feathi, g_feathi);
    cudaGetSymbolAddress((void**)&featlo, g_featlo);
    cudaGetSymbolAddress((void**)&hhi, g_hhi);
    cudaGetSymbolAddress((void**)&hlo, g_hlo);

    cudaFuncSetAttribute(conv1_mma_kernel,
                         cudaFuncAttributeMaxDynamicSharedMemorySize, CONV1_DSM);
    cudaFuncSetAttribute(conv_mma_kernel<128, 32, 32, 256, false>,
                         cudaFuncAttributeMaxDynamicSharedMemorySize, CONV_DSM);
    cudaFuncSetAttribute(conv_mma_kernel<256, 16, 16, 256, false>,
                         cudaFuncAttributeMaxDynamicSharedMemorySize, CONV_DSM);
    cudaFuncSetAttribute(conv_mma_kernel<256, 8, 8, 512, false>,
                         cudaFuncAttributeMaxDynamicSharedMemorySize, CONV_DSM);
    cudaFuncSetAttribute(conv_mma_kernel<512, 4, 4, 512, true>,
                         cudaFuncAttributeMaxDynamicSharedMemorySize, CONV_DSM);
    cudaFuncSetAttribute(expert_mma_kernel<DFEAT, HID, true, true, true>,
                         cudaFuncAttributeMaxDynamicSharedMemorySize, EXP_DSM);
    cudaFuncSetAttribute(expert_mma_kernel<HID, OUTD, false, false, false>,
                         cudaFuncAttributeMaxDynamicSharedMemorySize, EXP_DSM);

    // weight offsets within g_whi (elements)
    const size_t OFF2 = 0, OFF3 = WP2, OFF4 = WP3, OFF5 = WP4;

    // ---- all conv weight packs in ONE launch ----
    wpack_all_kernel<<<(WPALL + 255) / 256, 256>>>(cw2, cw3, cw4, cw5, whi);

    // ---- conv stack (all tensor-core) ----
    conv1_mma_kernel<<<8192, 512, CONV1_DSM>>>(x, cw1, cb1, hiA);
    conv_mma_kernel<128, 32, 32, 256, false><<<dim3(2048, 2), 512, CONV_DSM>>>(
        hiA, whi + OFF2, cb2, hiB, nullptr, nullptr);
    conv_mma_kernel<256, 16, 16, 256, false><<<dim3(512, 2), 512, CONV_DSM>>>(
        hiB, whi + OFF3, cb3, hiA, nullptr, nullptr);
    conv_mma_kernel<256, 8, 8, 512, false><<<dim3(128, 4), 512, CONV_DSM>>>(
        hiA, whi + OFF4, cb4, hiB, nullptr, nullptr);
    conv_mma_kernel<512, 4, 4, 512, true><<<dim3(32, 4), 512, CONV_DSM>>>(
        hiB, whi + OFF5, cb5, feathi, featlo, pool_s);

    // ---- gating ----
    gate_logits_kernel<<<BATCH, 128>>>(pool_s, wg);
    topk_perm_kernel<<<1, 512>>>();

    // ---- sparse expert MLPs (fp16 2-term mma, M-tile 64) ----
    expert_mma_kernel<DFEAT, HID, true, true, true>
        <<<dim3(HID / 128, NEXP, 8), 256, EXP_DSM>>>(feathi, featlo, w1, b1,
                                                     hhi, hlo, nullptr);
    expert_mma_kernel<HID, OUTD, false, false, false>
        <<<dim3(OUTD / 128, NEXP, 8), 256, EXP_DSM>>>(hhi, hlo, w2, b2,
                                                      nullptr, nullptr, o_s);

    // ---- combine (atomic-free, per token) + aux ----
    combine_kernel<<<BATCH, 256>>>(y);
    aux_kernel<<<1, 256>>>(y, out_size);
}